// round 5
// baseline (speedup 1.0000x reference)
#include <cuda_runtime.h>
#include <cuda_bf16.h>
#include <cstdint>

#define DEV_INLINE __device__ __forceinline__
using bf16 = __nv_bfloat16;

constexpr int N  = 131072;
constexpr int C  = 128;
constexpr int S  = 6;
constexpr int E  = 131072;
constexpr int EL = 32768;
constexpr int NB = 4;
constexpr int CC = C * C;
constexpr int NSLOT = 66;
constexpr int NT = 1024;   // source row tiles (N/128)
constexpr int NL = 14;     // edge lists: 0-5 pre, 6-11 suc, 12 left, 13 right
constexpr int ESTORE = 12 * E + 2 * EL;

// Scratch (allocation-free rule: static __device__ arrays)
__device__ float g_feat[N * C];
__device__ float g_temp[N * C];
__device__ float g_Y[N * C];
__device__ bf16  g_Ah[N * C];
__device__ bf16  g_Al[N * C];
__device__ bf16  g_Wh[NSLOT * CC];   // [slot][c][k] (transposed)
__device__ bf16  g_Wl[NSLOT * CC];
// edge sort scratch
__device__ int g_cnt[NL * NT];
__device__ int g_off[NL * (NT + 1)];
__device__ int g_eu[ESTORE];
__device__ int g_ev[ESTORE];   // v & 127 (row within tile)

DEV_INLINE uint32_t smem_u32(const void* p) {
  uint32_t a;
  asm("{ .reg .u64 t; cvta.to.shared.u64 t, %1; cvt.u32.u64 %0, t; }"
      : "=r"(a) : "l"(p));
  return a;
}

// ---------------------------------------------------------------------------
// shared MMA building blocks
// smem tile layout: 128 rows x 256B, XOR-16B swizzle on (row&7)
// tile offsets (both kernels): Ah=0 Al=32768 Wh=65536 Wl=98304
// ---------------------------------------------------------------------------
constexpr int TILE_BYTES = 128 * 256;  // 32 KB

DEV_INLINE void ldsm4(uint32_t& r0, uint32_t& r1, uint32_t& r2, uint32_t& r3,
                      uint32_t addr) {
  asm volatile("ldmatrix.sync.aligned.m8n8.x4.shared.b16 {%0,%1,%2,%3}, [%4];"
               : "=r"(r0), "=r"(r1), "=r"(r2), "=r"(r3) : "r"(addr));
}
DEV_INLINE void mma_bf16(float* c, uint32_t a0, uint32_t a1, uint32_t a2,
                         uint32_t a3, uint32_t b0, uint32_t b1) {
  asm volatile(
      "mma.sync.aligned.m16n8k16.row.col.f32.bf16.bf16.f32 "
      "{%0,%1,%2,%3}, {%4,%5,%6,%7}, {%8,%9}, {%0,%1,%2,%3};"
      : "+f"(c[0]), "+f"(c[1]), "+f"(c[2]), "+f"(c[3])
      : "r"(a0), "r"(a1), "r"(a2), "r"(a3), "r"(b0), "r"(b1));
}

// stage one 128x128 bf16 tile (32 KB) with swizzle; 256 threads
DEV_INLINE void stage_tile(char* dst, const bf16* src, int tid) {
  const uint4* s = (const uint4*)src;
#pragma unroll
  for (int t = 0; t < 8; ++t) {
    int idx = tid + t * 256;
    int r = idx >> 4, c16 = idx & 15;
    uint32_t off = r * 256 + ((c16 * 16) ^ ((r & 7) << 4));
    *(uint4*)(dst + off) = s[idx];
  }
}

// 3-pass split-bf16 128x128x128 compute; warp tile 64x32
DEV_INLINE void mma_compute(uint32_t sbase, int lane, int wid,
                            float (&acc)[4][4][4]) {
#pragma unroll
  for (int mi = 0; mi < 4; ++mi)
#pragma unroll
    for (int ni = 0; ni < 4; ++ni)
#pragma unroll
      for (int j = 0; j < 4; ++j) acc[mi][ni][j] = 0.0f;

  const int rw = (wid & 1) * 64;
  const int cw = (wid >> 1) * 32;
  uint32_t aRow[4], aColK = (lane >> 4) * 16;
#pragma unroll
  for (int mi = 0; mi < 4; ++mi) aRow[mi] = rw + mi * 16 + (lane & 15);
  uint32_t bRow[2], bColK = ((lane >> 3) & 1) * 16;
#pragma unroll
  for (int bi = 0; bi < 2; ++bi)
    bRow[bi] = cw + bi * 16 + ((lane >> 4) * 8) + (lane & 7);

  const uint32_t aT[3] = {0, 0, (uint32_t)TILE_BYTES};
  const uint32_t bT[3] = {2 * TILE_BYTES, 3 * TILE_BYTES, 2 * TILE_BYTES};

#pragma unroll
  for (int p = 0; p < 3; ++p) {
    const uint32_t aBase = sbase + aT[p];
    const uint32_t bBase = sbase + bT[p];
#pragma unroll
    for (int kk = 0; kk < 8; ++kk) {
      const uint32_t kb = kk * 32;
      uint32_t a[4][4];
#pragma unroll
      for (int mi = 0; mi < 4; ++mi) {
        uint32_t r = aRow[mi];
        uint32_t addr = aBase + r * 256 + ((kb | aColK) ^ ((r & 7) << 4));
        ldsm4(a[mi][0], a[mi][1], a[mi][2], a[mi][3], addr);
      }
      uint32_t b[4][2];
#pragma unroll
      for (int bi = 0; bi < 2; ++bi) {
        uint32_t r = bRow[bi];
        uint32_t addr = bBase + r * 256 + ((kb | bColK) ^ ((r & 7) << 4));
        ldsm4(b[bi * 2][0], b[bi * 2][1], b[bi * 2 + 1][0], b[bi * 2 + 1][1],
              addr);
      }
#pragma unroll
      for (int mi = 0; mi < 4; ++mi)
#pragma unroll
        for (int ni = 0; ni < 4; ++ni)
          mma_bf16(acc[mi][ni], a[mi][0], a[mi][1], a[mi][2], a[mi][3],
                   b[ni][0], b[ni][1]);
    }
  }
}

DEV_INLINE void store_acc_global(float* Out, int rowBase, int lane, int wid,
                                 float (&acc)[4][4][4]) {
  const int rw = (wid & 1) * 64, cw = (wid >> 1) * 32;
  const int r0 = lane >> 2, c0 = (lane & 3) * 2;
#pragma unroll
  for (int mi = 0; mi < 4; ++mi)
#pragma unroll
    for (int ni = 0; ni < 4; ++ni) {
      int grow = rowBase + rw + mi * 16 + r0;
      int gcol = cw + ni * 8 + c0;
      *(float2*)(Out + (size_t)grow * C + gcol) =
          make_float2(acc[mi][ni][0], acc[mi][ni][1]);
      *(float2*)(Out + (size_t)(grow + 8) * C + gcol) =
          make_float2(acc[mi][ni][2], acc[mi][ni][3]);
    }
}

// ---------------------------------------------------------------------------
// standalone GEMM (input stage + ctr/ctr2): Out = (Ah+Al)@(Wh+Wl)^T
// ---------------------------------------------------------------------------
constexpr int SMEM_MMA_BYTES = 4 * TILE_BYTES;  // 128 KB

__global__ void __launch_bounds__(256, 1) gemm_mma(
    const bf16* __restrict__ Ah, const bf16* __restrict__ Al,
    const bf16* __restrict__ Bh, const bf16* __restrict__ Bl,
    float* __restrict__ Out) {
  extern __shared__ __align__(16) char smem[];
  const uint32_t sbase = smem_u32(smem);
  const int tid = threadIdx.x, lane = tid & 31, wid = tid >> 5;
  const int rowBase = blockIdx.x * 128;

  stage_tile(smem, Ah + (size_t)rowBase * C, tid);
  stage_tile(smem + TILE_BYTES, Al + (size_t)rowBase * C, tid);
  stage_tile(smem + 2 * TILE_BYTES, Bh, tid);
  stage_tile(smem + 3 * TILE_BYTES, Bl, tid);
  __syncthreads();

  float acc[4][4][4];
  mma_compute(sbase, lane, wid, acc);
  store_acc_global(Out, rowBase, lane, wid, acc);
}

// ---------------------------------------------------------------------------
// fused per-block kernel: 14 edge-GEMMs + direct smem scatter
// smem: A(64KB) + W(64KB) + Ybuf(128x136 f32 = 69632B) = 200704B
// ---------------------------------------------------------------------------
constexpr int YPITCH = 136;
constexpr int SMEM_FUSED = 2 * TILE_BYTES + 2 * TILE_BYTES + 128 * YPITCH * 4;

__global__ void __launch_bounds__(256, 1) fused_block_kernel(
    const bf16* __restrict__ Ah, const bf16* __restrict__ Al, int ib,
    float* __restrict__ TP) {
  extern __shared__ __align__(16) char smem[];
  const uint32_t sbase = smem_u32(smem);
  float* Ybuf = (float*)(smem + 4 * TILE_BYTES);
  const int tid = threadIdx.x, lane = tid & 31, wid = tid >> 5;
  const int rowBase = blockIdx.x * 128;

  stage_tile(smem, Ah + (size_t)rowBase * C, tid);
  stage_tile(smem + TILE_BYTES, Al + (size_t)rowBase * C, tid);

  const int rw = (wid & 1) * 64, cw = (wid >> 1) * 32;
  const int r0 = lane >> 2, c0 = (lane & 3) * 2;

#pragma unroll 1
  for (int l = 0; l < 14; ++l) {
    int slot = (l < 6)    ? 6 + ib * 6 + l
               : (l < 12) ? 30 + ib * 6 + (l - 6)
               : (l == 12) ? 54 + ib : 58 + ib;
    __syncthreads();  // Ybuf consumed, W free
    stage_tile(smem + 2 * TILE_BYTES, g_Wh + (size_t)slot * CC, tid);
    stage_tile(smem + 3 * TILE_BYTES, g_Wl + (size_t)slot * CC, tid);
    __syncthreads();

    float acc[4][4][4];
    mma_compute(sbase, lane, wid, acc);

    // stage Y tile to smem (pitch 136 floats: conflict-free stores)
#pragma unroll
    for (int mi = 0; mi < 4; ++mi)
#pragma unroll
      for (int ni = 0; ni < 4; ++ni) {
        int row = rw + mi * 16 + r0, col = cw + ni * 8 + c0;
        *(float2*)(Ybuf + row * YPITCH + col) =
            make_float2(acc[mi][ni][0], acc[mi][ni][1]);
        *(float2*)(Ybuf + (row + 8) * YPITCH + col) =
            make_float2(acc[mi][ni][2], acc[mi][ni][3]);
      }
    __syncthreads();

    // scatter: edges with v in this tile; warp per edge
    int ebase = (l < 12) ? l * E : 12 * E + (l - 12) * EL;
    int o0 = g_off[l * (NT + 1) + blockIdx.x];
    int o1 = g_off[l * (NT + 1) + blockIdx.x + 1];
    for (int j = o0 + wid; j < o1; j += 8) {
      int uu = g_eu[ebase + j];
      int vl = g_ev[ebase + j];
      float4 val = *(float4*)(Ybuf + vl * YPITCH + lane * 4);
      float* p = TP + (size_t)uu * C + lane * 4;
      asm volatile("red.global.add.v4.f32 [%0], {%1,%2,%3,%4};"
                   :: "l"(p), "f"(val.x), "f"(val.y), "f"(val.z), "f"(val.w)
                   : "memory");
    }
  }
}

// ---------------------------------------------------------------------------
// edge sort (counting sort by v>>7), once per launch
// ---------------------------------------------------------------------------
__global__ void zero_cnt_kernel() {
  int i = blockIdx.x * 256 + threadIdx.x;
  if (i < NL * NT) g_cnt[i] = 0;
}
__global__ void hist_kernel(const int* __restrict__ v, int nE, int l) {
  int e = blockIdx.x * 256 + threadIdx.x;
  if (e < nE) atomicAdd(&g_cnt[l * NT + (__ldg(&v[e]) >> 7)], 1);
}
__global__ void prefix_kernel() {  // one block per list, 1024 threads
  __shared__ int sh[NT];
  int l = blockIdx.x, t = threadIdx.x;
  sh[t] = g_cnt[l * NT + t];
  __syncthreads();
#pragma unroll
  for (int d = 1; d < NT; d <<= 1) {
    int x = (t >= d) ? sh[t - d] : 0;
    __syncthreads();
    sh[t] += x;
    __syncthreads();
  }
  g_off[l * (NT + 1) + t + 1] = sh[t];
  if (t == 0) g_off[l * (NT + 1)] = 0;
}
__global__ void fill_kernel(const int* __restrict__ u,
                            const int* __restrict__ v, int nE, int l,
                            int sbase) {
  int e = blockIdx.x * 256 + threadIdx.x;
  if (e >= nE) return;
  int vv = __ldg(&v[e]);
  int t = vv >> 7;
  int pos = sbase + g_off[l * (NT + 1) + t] + atomicAdd(&g_cnt[l * NT + t], 1);
  g_eu[pos] = __ldg(&u[e]);
  g_ev[pos] = vv & 127;
}

// ---------------------------------------------------------------------------
// split helpers / elementwise kernels
// ---------------------------------------------------------------------------
DEV_INLINE void split_store4(bf16* Hh, bf16* Hl, size_t idx4, float4 o) {
  __nv_bfloat162 h0 = __floats2bfloat162_rn(o.x, o.y);
  __nv_bfloat162 h1 = __floats2bfloat162_rn(o.z, o.w);
  float lx = o.x - __bfloat162float(h0.x);
  float ly = o.y - __bfloat162float(h0.y);
  float lz = o.z - __bfloat162float(h1.x);
  float lw = o.w - __bfloat162float(h1.y);
  __nv_bfloat162 l0 = __floats2bfloat162_rn(lx, ly);
  __nv_bfloat162 l1 = __floats2bfloat162_rn(lz, lw);
  *(uint2*)(Hh + idx4) = make_uint2(*(uint32_t*)&h0, *(uint32_t*)&h1);
  *(uint2*)(Hl + idx4) = make_uint2(*(uint32_t*)&l0, *(uint32_t*)&l1);
}

__global__ void wsplit_kernel(const float* __restrict__ src, int slotBase,
                              int nm) {
  int idx = blockIdx.x * 256 + threadIdx.x;
  int m = idx >> 14, r = idx & 16383;
  int c = r >> 7, k = r & 127;
  float w = src[(size_t)m * CC + k * 128 + c];
  bf16 hi = __float2bfloat16(w);
  bf16 lo = __float2bfloat16(w - __bfloat162float(hi));
  size_t o = (size_t)(slotBase + m) * CC + r;
  g_Wh[o] = hi;
  g_Wl[o] = lo;
}

__global__ void mlp0_split_kernel(const float* __restrict__ X2,
                                  const float* __restrict__ W0,
                                  const float* __restrict__ B0,
                                  bf16* __restrict__ Hh, bf16* __restrict__ Hl) {
  int idx = blockIdx.x * 256 + threadIdx.x;  // N*64
  int n = idx >> 6, c = (idx & 63) << 1;
  float x0 = X2[2 * n], x1 = X2[2 * n + 1];
  float ha = fmaxf(fmaf(x0, W0[c], fmaf(x1, W0[C + c], B0[c])), 0.0f);
  float hb = fmaxf(fmaf(x0, W0[c + 1], fmaf(x1, W0[C + c + 1], B0[c + 1])), 0.0f);
  __nv_bfloat162 h = __floats2bfloat162_rn(ha, hb);
  __nv_bfloat162 l = __floats2bfloat162_rn(ha - __bfloat162float(h.x),
                                           hb - __bfloat162float(h.y));
  *(__nv_bfloat162*)(Hh + (size_t)n * C + c) = h;
  *(__nv_bfloat162*)(Hl + (size_t)n * C + c) = l;
}

DEV_INLINE float wsum(float v) {
#pragma unroll
  for (int o = 16; o > 0; o >>= 1) v += __shfl_xor_sync(0xffffffffu, v, o);
  return v;
}

__global__ void gn_relu_split_kernel(const float* __restrict__ X,
                                     const float* __restrict__ G,
                                     const float* __restrict__ Bt,
                                     bf16* __restrict__ Hh,
                                     bf16* __restrict__ Hl) {
  int w = (blockIdx.x * blockDim.x + threadIdx.x) >> 5;
  int lane = threadIdx.x & 31;
  float4 x = ((const float4*)X)[(size_t)w * 32 + lane];
  float s = wsum(x.x + x.y + x.z + x.w);
  float q = wsum(x.x * x.x + x.y * x.y + x.z * x.z + x.w * x.w);
  float mu = s * (1.0f / 128.0f);
  float rs = rsqrtf(q * (1.0f / 128.0f) - mu * mu + 1e-5f);
  float4 g = ((const float4*)G)[lane];
  float4 b = ((const float4*)Bt)[lane];
  float4 o;
  o.x = fmaxf((x.x - mu) * rs * g.x + b.x, 0.0f);
  o.y = fmaxf((x.y - mu) * rs * g.y + b.y, 0.0f);
  o.z = fmaxf((x.z - mu) * rs * g.z + b.z, 0.0f);
  o.w = fmaxf((x.w - mu) * rs * g.w + b.w, 0.0f);
  split_store4(Hh, Hl, ((size_t)w * 32 + lane) * 4, o);
}

__global__ void gn_res_relu_kernel(const float* __restrict__ X,
                                   const float* __restrict__ G,
                                   const float* __restrict__ Bt,
                                   const float* __restrict__ Id,
                                   float* __restrict__ Of,
                                   bf16* __restrict__ Hh,
                                   bf16* __restrict__ Hl) {
  int w = (blockIdx.x * blockDim.x + threadIdx.x) >> 5;
  int lane = threadIdx.x & 31;
  float4 x = ((const float4*)X)[(size_t)w * 32 + lane];
  float s = wsum(x.x + x.y + x.z + x.w);
  float q = wsum(x.x * x.x + x.y * x.y + x.z * x.z + x.w * x.w);
  float mu = s * (1.0f / 128.0f);
  float rs = rsqrtf(q * (1.0f / 128.0f) - mu * mu + 1e-5f);
  float4 g = ((const float4*)G)[lane];
  float4 b = ((const float4*)Bt)[lane];
  float4 id = ((const float4*)Id)[(size_t)w * 32 + lane];
  float4 o;
  o.x = fmaxf((x.x - mu) * rs * g.x + b.x + id.x, 0.0f);
  o.y = fmaxf((x.y - mu) * rs * g.y + b.y + id.y, 0.0f);
  o.z = fmaxf((x.z - mu) * rs * g.z + b.z + id.z, 0.0f);
  o.w = fmaxf((x.w - mu) * rs * g.w + b.w + id.w, 0.0f);
  ((float4*)Of)[(size_t)w * 32 + lane] = o;
  if (Hh) split_store4(Hh, Hl, ((size_t)w * 32 + lane) * 4, o);
}

__global__ void combine_kernel(const float* __restrict__ Y1,
                               const float* __restrict__ Y2,
                               const float* __restrict__ G1,
                               const float* __restrict__ B1,
                               const float* __restrict__ G2,
                               const float* __restrict__ B2,
                               float* __restrict__ Of, bf16* __restrict__ Hh,
                               bf16* __restrict__ Hl) {
  int w = (blockIdx.x * blockDim.x + threadIdx.x) >> 5;
  int lane = threadIdx.x & 31;
  float4 x1 = ((const float4*)Y1)[(size_t)w * 32 + lane];
  float4 x2 = ((const float4*)Y2)[(size_t)w * 32 + lane];
  float s1 = wsum(x1.x + x1.y + x1.z + x1.w);
  float q1 = wsum(x1.x * x1.x + x1.y * x1.y + x1.z * x1.z + x1.w * x1.w);
  float s2 = wsum(x2.x + x2.y + x2.z + x2.w);
  float q2 = wsum(x2.x * x2.x + x2.y * x2.y + x2.z * x2.z + x2.w * x2.w);
  float mu1 = s1 * (1.0f / 128.0f);
  float rs1 = rsqrtf(q1 * (1.0f / 128.0f) - mu1 * mu1 + 1e-5f);
  float mu2 = s2 * (1.0f / 128.0f);
  float rs2 = rsqrtf(q2 * (1.0f / 128.0f) - mu2 * mu2 + 1e-5f);
  float4 g1 = ((const float4*)G1)[lane];
  float4 b1 = ((const float4*)B1)[lane];
  float4 g2 = ((const float4*)G2)[lane];
  float4 b2 = ((const float4*)B2)[lane];
  float4 o;
  o.x = fmaxf((x1.x - mu1) * rs1 * g1.x + b1.x + (x2.x - mu2) * rs2 * g2.x + b2.x, 0.0f);
  o.y = fmaxf((x1.y - mu1) * rs1 * g1.y + b1.y + (x2.y - mu2) * rs2 * g2.y + b2.y, 0.0f);
  o.z = fmaxf((x1.z - mu1) * rs1 * g1.z + b1.z + (x2.z - mu2) * rs2 * g2.z + b2.z, 0.0f);
  o.w = fmaxf((x1.w - mu1) * rs1 * g1.w + b1.w + (x2.w - mu2) * rs2 * g2.w + b2.w, 0.0f);
  ((float4*)Of)[(size_t)w * 32 + lane] = o;
  split_store4(Hh, Hl, ((size_t)w * 32 + lane) * 4, o);
}

// ---------------------------------------------------------------------------
extern "C" void kernel_launch(void* const* d_in, const int* in_sizes, int n_in,
                              void* d_out, int out_size) {
  const float* ctrs   = (const float*)d_in[0];
  const float* feats  = (const float*)d_in[1];
  const int*   pre_u  = (const int*)d_in[2];
  const int*   pre_v  = (const int*)d_in[3];
  const int*   suc_u  = (const int*)d_in[4];
  const int*   suc_v  = (const int*)d_in[5];
  const int*   left_u = (const int*)d_in[6];
  const int*   left_v = (const int*)d_in[7];
  const int*   right_u= (const int*)d_in[8];
  const int*   right_v= (const int*)d_in[9];
  const float* ic_w0  = (const float*)d_in[10];
  const float* ic_b0  = (const float*)d_in[11];
  const float* ic_w1  = (const float*)d_in[12];
  const float* ic_g   = (const float*)d_in[13];
  const float* ic_bt  = (const float*)d_in[14];
  const float* if_w0  = (const float*)d_in[15];
  const float* if_b0  = (const float*)d_in[16];
  const float* if_w1  = (const float*)d_in[17];
  const float* if_g   = (const float*)d_in[18];
  const float* if_bt  = (const float*)d_in[19];
  const float* ctr_w  = (const float*)d_in[20];
  const float* pre_w  = (const float*)d_in[21];
  const float* suc_w  = (const float*)d_in[22];
  const float* left_w = (const float*)d_in[23];
  const float* right_w= (const float*)d_in[24];
  const float* norm_g = (const float*)d_in[25];
  const float* norm_b = (const float*)d_in[26];
  const float* ctr2_w = (const float*)d_in[27];
  const float* ctr2_g = (const float*)d_in[28];
  const float* ctr2_b = (const float*)d_in[29];
  float* out = (float*)d_out;

  float *FT, *TP, *YB;
  bf16 *AH, *AL, *WH, *WL;
  cudaGetSymbolAddress((void**)&FT, g_feat);
  cudaGetSymbolAddress((void**)&TP, g_temp);
  cudaGetSymbolAddress((void**)&YB, g_Y);
  cudaGetSymbolAddress((void**)&AH, g_Ah);
  cudaGetSymbolAddress((void**)&AL, g_Al);
  cudaGetSymbolAddress((void**)&WH, g_Wh);
  cudaGetSymbolAddress((void**)&WL, g_Wl);

  cudaFuncSetAttribute(gemm_mma, cudaFuncAttributeMaxDynamicSharedMemorySize,
                       SMEM_MMA_BYTES);
  cudaFuncSetAttribute(fused_block_kernel,
                       cudaFuncAttributeMaxDynamicSharedMemorySize, SMEM_FUSED);

  const int GEMM_GRID = N / 128;
  const int ROW_GRID  = N / 8;
  const int MLP_GRID  = (N * 64) / 256;
  const int ZG = (NL * NT + 255) / 256;
  const int HG = (E + 255) / 256, HGS = (EL + 255) / 256;

  // ---- weight split + transpose ----
  wsplit_kernel<<<1 * 64, 256>>>(ic_w1, 0, 1);
  wsplit_kernel<<<1 * 64, 256>>>(if_w1, 1, 1);
  wsplit_kernel<<<4 * 64, 256>>>(ctr_w, 2, 4);
  wsplit_kernel<<<24 * 64, 256>>>(pre_w, 6, 24);
  wsplit_kernel<<<24 * 64, 256>>>(suc_w, 30, 24);
  wsplit_kernel<<<4 * 64, 256>>>(left_w, 54, 4);
  wsplit_kernel<<<4 * 64, 256>>>(right_w, 58, 4);
  wsplit_kernel<<<4 * 64, 256>>>(ctr2_w, 62, 4);

  // ---- edge sort by source tile (once; reused by all 4 blocks) ----
  zero_cnt_kernel<<<ZG, 256>>>();
  for (int s = 0; s < S; ++s) {
    hist_kernel<<<HG, 256>>>(pre_v + (size_t)s * E, E, s);
    hist_kernel<<<HG, 256>>>(suc_v + (size_t)s * E, E, 6 + s);
  }
  hist_kernel<<<HGS, 256>>>(left_v, EL, 12);
  hist_kernel<<<HGS, 256>>>(right_v, EL, 13);
  prefix_kernel<<<NL, NT>>>();
  zero_cnt_kernel<<<ZG, 256>>>();
  for (int s = 0; s < S; ++s) {
    fill_kernel<<<HG, 256>>>(pre_u + (size_t)s * E, pre_v + (size_t)s * E, E,
                             s, s * E);
    fill_kernel<<<HG, 256>>>(suc_u + (size_t)s * E, suc_v + (size_t)s * E, E,
                             6 + s, (6 + s) * E);
  }
  fill_kernel<<<HGS, 256>>>(left_u, left_v, EL, 12, 12 * E);
  fill_kernel<<<HGS, 256>>>(right_u, right_v, EL, 13, 12 * E + EL);

#define GEMM(slot, OutPtr)                                                     \
  gemm_mma<<<GEMM_GRID, 256, SMEM_MMA_BYTES>>>(AH, AL, WH + (size_t)(slot) * CC, \
                                               WL + (size_t)(slot) * CC, OutPtr)

  // ---- Input stage ----
  mlp0_split_kernel<<<MLP_GRID, 256>>>(ctrs, ic_w0, ic_b0, AH, AL);
  GEMM(0, FT);
  mlp0_split_kernel<<<MLP_GRID, 256>>>(feats, if_w0, if_b0, AH, AL);
  GEMM(1, YB);
  combine_kernel<<<ROW_GRID, 256>>>(FT, YB, ic_g, ic_bt, if_g, if_bt, FT, AH, AL);

  // ---- 4 fusion blocks ----
  for (int i = 0; i < NB; ++i) {
    GEMM(2 + i, TP);  // temp = feat @ ctr_w[i]  (direct row store, must precede atomics)
    fused_block_kernel<<<GEMM_GRID, 256, SMEM_FUSED>>>(AH, AL, i, TP);

    gn_relu_split_kernel<<<ROW_GRID, 256>>>(TP, norm_g + (size_t)i * C,
                                            norm_b + (size_t)i * C, AH, AL);
    GEMM(62 + i, TP);  // Y2 = feat_mid @ ctr2_w[i]

    if (i == NB - 1) {
      gn_res_relu_kernel<<<ROW_GRID, 256>>>(TP, ctr2_g + (size_t)i * C,
                                            ctr2_b + (size_t)i * C, FT, out,
                                            nullptr, nullptr);
    } else {
      gn_res_relu_kernel<<<ROW_GRID, 256>>>(TP, ctr2_g + (size_t)i * C,
                                            ctr2_b + (size_t)i * C, FT, FT,
                                            AH, AL);
    }
  }
#undef GEMM
}

// round 6
// speedup vs baseline: 1.2940x; 1.2940x over previous
#include <cuda_runtime.h>
#include <cuda_fp16.h>
#include <cstdint>

#define DEV_INLINE __device__ __forceinline__

constexpr int N  = 131072;
constexpr int C  = 128;
constexpr int S  = 6;
constexpr int E  = 131072;
constexpr int EL = 32768;
constexpr int NB = 4;
constexpr int CC = C * C;
constexpr int NSLOT = 66;
constexpr int NT = 1024;   // source row tiles (N/128)
constexpr int NL = 14;     // edge lists: 0-5 pre, 6-11 suc, 12 left, 13 right
constexpr int ESTORE = 12 * E + 2 * EL;

// Scratch (allocation-free rule: static __device__ arrays)
__device__ float  g_feat[N * C];
__device__ float  g_temp[N * C];
__device__ float  g_Y[N * C];
__device__ __half g_A[N * C];           // fp16 activations (single precision level)
__device__ __half g_Wh[NSLOT * CC];     // fp16 weight hi, [slot][c][k] (transposed)
__device__ __half g_Wl[NSLOT * CC];     // fp16 weight lo (residual)
// edge sort scratch
__device__ int g_cnt[NL * NT];
__device__ int g_off[NL * (NT + 1)];
__device__ int g_eu[ESTORE];
__device__ int g_ev[ESTORE];   // v & 127 (row within tile)

DEV_INLINE uint32_t smem_u32(const void* p) {
  uint32_t a;
  asm("{ .reg .u64 t; cvta.to.shared.u64 t, %1; cvt.u32.u64 %0, t; }"
      : "=r"(a) : "l"(p));
  return a;
}

// ---------------------------------------------------------------------------
// MMA building blocks. smem tile: 128 rows x 256B, XOR-16B swizzle on (row&7)
// ---------------------------------------------------------------------------
constexpr int TILE_BYTES = 128 * 256;  // 32 KB (128x128 fp16)

DEV_INLINE void ldsm4(uint32_t& r0, uint32_t& r1, uint32_t& r2, uint32_t& r3,
                      uint32_t addr) {
  asm volatile("ldmatrix.sync.aligned.m8n8.x4.shared.b16 {%0,%1,%2,%3}, [%4];"
               : "=r"(r0), "=r"(r1), "=r"(r2), "=r"(r3) : "r"(addr));
}
DEV_INLINE void mma_f16(float* c, uint32_t a0, uint32_t a1, uint32_t a2,
                        uint32_t a3, uint32_t b0, uint32_t b1) {
  asm volatile(
      "mma.sync.aligned.m16n8k16.row.col.f32.f16.f16.f32 "
      "{%0,%1,%2,%3}, {%4,%5,%6,%7}, {%8,%9}, {%0,%1,%2,%3};"
      : "+f"(c[0]), "+f"(c[1]), "+f"(c[2]), "+f"(c[3])
      : "r"(a0), "r"(a1), "r"(a2), "r"(a3), "r"(b0), "r"(b1));
}

DEV_INLINE void cp_async16(uint32_t dst, const void* src) {
  asm volatile("cp.async.cg.shared.global [%0], [%1], 16;" :: "r"(dst),
               "l"(src));
}
#define CP_COMMIT() asm volatile("cp.async.commit_group;" ::: "memory")
#define CP_WAIT(n)  asm volatile("cp.async.wait_group %0;" :: "n"(n) : "memory")

// stage one 128x128 fp16 tile (32 KB) with swizzle via cp.async; 256 threads
DEV_INLINE void stage_async(uint32_t dstBase, const __half* src, int tid) {
  const char* s = (const char*)src;
#pragma unroll
  for (int t = 0; t < 8; ++t) {
    int idx = tid + t * 256;
    int r = idx >> 4, c16 = idx & 15;
    uint32_t off = r * 256 + ((c16 * 16) ^ ((r & 7) << 4));
    cp_async16(dstBase + off, s + idx * 16);
  }
}

// 2-pass fp16 compute: acc += A@Wh + A@Wl. A frags loaded once per k-step.
DEV_INLINE void mma_compute2(uint32_t aBase, uint32_t bhBase, uint32_t blBase,
                             int lane, int wid, float (&acc)[4][4][4]) {
#pragma unroll
  for (int mi = 0; mi < 4; ++mi)
#pragma unroll
    for (int ni = 0; ni < 4; ++ni)
#pragma unroll
      for (int j = 0; j < 4; ++j) acc[mi][ni][j] = 0.0f;

  const int rw = (wid & 1) * 64;
  const int cw = (wid >> 1) * 32;
  uint32_t aRow[4], aColK = (lane >> 4) * 16;
#pragma unroll
  for (int mi = 0; mi < 4; ++mi) aRow[mi] = rw + mi * 16 + (lane & 15);
  uint32_t bRow[2], bColK = ((lane >> 3) & 1) * 16;
#pragma unroll
  for (int bi = 0; bi < 2; ++bi)
    bRow[bi] = cw + bi * 16 + ((lane >> 4) * 8) + (lane & 7);

#pragma unroll
  for (int kk = 0; kk < 8; ++kk) {
    const uint32_t kb = kk * 32;
    uint32_t a[4][4];
#pragma unroll
    for (int mi = 0; mi < 4; ++mi) {
      uint32_t r = aRow[mi];
      uint32_t addr = aBase + r * 256 + ((kb | aColK) ^ ((r & 7) << 4));
      ldsm4(a[mi][0], a[mi][1], a[mi][2], a[mi][3], addr);
    }
#pragma unroll
    for (int p = 0; p < 2; ++p) {
      const uint32_t bBase = p ? blBase : bhBase;
      uint32_t b[4][2];
#pragma unroll
      for (int bi = 0; bi < 2; ++bi) {
        uint32_t r = bRow[bi];
        uint32_t addr = bBase + r * 256 + ((kb | bColK) ^ ((r & 7) << 4));
        ldsm4(b[bi * 2][0], b[bi * 2][1], b[bi * 2 + 1][0], b[bi * 2 + 1][1],
              addr);
      }
#pragma unroll
      for (int mi = 0; mi < 4; ++mi)
#pragma unroll
        for (int ni = 0; ni < 4; ++ni)
          mma_f16(acc[mi][ni], a[mi][0], a[mi][1], a[mi][2], a[mi][3],
                  b[ni][0], b[ni][1]);
    }
  }
}

DEV_INLINE void store_acc_global(float* Out, int rowBase, int lane, int wid,
                                 float (&acc)[4][4][4]) {
  const int rw = (wid & 1) * 64, cw = (wid >> 1) * 32;
  const int r0 = lane >> 2, c0 = (lane & 3) * 2;
#pragma unroll
  for (int mi = 0; mi < 4; ++mi)
#pragma unroll
    for (int ni = 0; ni < 4; ++ni) {
      int grow = rowBase + rw + mi * 16 + r0;
      int gcol = cw + ni * 8 + c0;
      *(float2*)(Out + (size_t)grow * C + gcol) =
          make_float2(acc[mi][ni][0], acc[mi][ni][1]);
      *(float2*)(Out + (size_t)(grow + 8) * C + gcol) =
          make_float2(acc[mi][ni][2], acc[mi][ni][3]);
    }
}

// ---------------------------------------------------------------------------
// standalone GEMM: Out = A@(Wh+Wl)^T. smem 96 KB -> 2 CTAs/SM.
// ---------------------------------------------------------------------------
constexpr int SMEM_MMA_BYTES = 3 * TILE_BYTES;  // 96 KB

__global__ void __launch_bounds__(256, 2) gemm_mma(
    const __half* __restrict__ A, const __half* __restrict__ Bh,
    const __half* __restrict__ Bl, float* __restrict__ Out) {
  extern __shared__ __align__(16) char smem[];
  const uint32_t sbase = smem_u32(smem);
  const int tid = threadIdx.x, lane = tid & 31, wid = tid >> 5;
  const int rowBase = blockIdx.x * 128;

  stage_async(sbase, A + (size_t)rowBase * C, tid);
  stage_async(sbase + TILE_BYTES, Bh, tid);
  stage_async(sbase + 2 * TILE_BYTES, Bl, tid);
  CP_COMMIT();
  CP_WAIT(0);
  __syncthreads();

  float acc[4][4][4];
  mma_compute2(sbase, sbase + TILE_BYTES, sbase + 2 * TILE_BYTES, lane, wid,
               acc);
  store_acc_global(Out, rowBase, lane, wid, acc);
}

// ---------------------------------------------------------------------------
// fused per-block kernel: 14 edge-GEMMs + smem scatter, cp.async W pipeline
// smem: A(32K) + Wbuf x2 (each Wh+Wl = 64K -> 128K) + Ybuf(128x132 f32=66K)
// total 231424 B
// ---------------------------------------------------------------------------
constexpr int YPITCH = 132;
constexpr int W_OFF = TILE_BYTES;                    // 32768
constexpr int Y_OFF = TILE_BYTES + 4 * TILE_BYTES;   // 163840
constexpr int SMEM_FUSED = Y_OFF + 128 * YPITCH * 4; // 231424

__global__ void __launch_bounds__(256, 1) fused_block_kernel(
    const __half* __restrict__ A, int ib, float* __restrict__ TP) {
  extern __shared__ __align__(16) char smem[];
  const uint32_t sbase = smem_u32(smem);
  float* Ybuf = (float*)(smem + Y_OFF);
  const int tid = threadIdx.x, lane = tid & 31, wid = tid >> 5;
  const int rowBase = blockIdx.x * 128;

  const int rw = (wid & 1) * 64, cw = (wid >> 1) * 32;
  const int r0 = lane >> 2, c0 = (lane & 3) * 2;

  auto slot_of = [&](int l) {
    return (l < 6)    ? 6 + ib * 6 + l
           : (l < 12) ? 30 + ib * 6 + (l - 6)
           : (l == 12) ? 54 + ib : 58 + ib;
  };

  // group 0: A + W(list 0)
  stage_async(sbase, A + (size_t)rowBase * C, tid);
  stage_async(sbase + W_OFF, g_Wh + (size_t)slot_of(0) * CC, tid);
  stage_async(sbase + W_OFF + TILE_BYTES, g_Wl + (size_t)slot_of(0) * CC, tid);
  CP_COMMIT();

#pragma unroll 1
  for (int l = 0; l < 14; ++l) {
    if (l < 13) {
      uint32_t nb = W_OFF + ((l + 1) & 1) * (2 * TILE_BYTES);
      stage_async(sbase + nb, g_Wh + (size_t)slot_of(l + 1) * CC, tid);
      stage_async(sbase + nb + TILE_BYTES, g_Wl + (size_t)slot_of(l + 1) * CC,
                  tid);
      CP_COMMIT();
      CP_WAIT(1);  // W(l) (and A on l=0) complete
    } else {
      CP_WAIT(0);
    }
    __syncthreads();  // also guards Ybuf(l-1) fully scattered before rewrite

    const uint32_t wb = W_OFF + (l & 1) * (2 * TILE_BYTES);
    float acc[4][4][4];
    mma_compute2(sbase, sbase + wb, sbase + wb + TILE_BYTES, lane, wid, acc);

    // stage Y tile to smem
#pragma unroll
    for (int mi = 0; mi < 4; ++mi)
#pragma unroll
      for (int ni = 0; ni < 4; ++ni) {
        int row = rw + mi * 16 + r0, col = cw + ni * 8 + c0;
        *(float2*)(Ybuf + row * YPITCH + col) =
            make_float2(acc[mi][ni][0], acc[mi][ni][1]);
        *(float2*)(Ybuf + (row + 8) * YPITCH + col) =
            make_float2(acc[mi][ni][2], acc[mi][ni][3]);
      }
    __syncthreads();

    // scatter this tile's edges; warp per edge (W(l+1) cp.async in flight)
    int ebase = (l < 12) ? l * E : 12 * E + (l - 12) * EL;
    int o0 = g_off[l * (NT + 1) + blockIdx.x];
    int o1 = g_off[l * (NT + 1) + blockIdx.x + 1];
    for (int j = o0 + wid; j < o1; j += 8) {
      int uu = g_eu[ebase + j];
      int vl = g_ev[ebase + j];
      float4 val = *(float4*)(Ybuf + vl * YPITCH + lane * 4);
      float* p = TP + (size_t)uu * C + lane * 4;
      asm volatile("red.global.add.v4.f32 [%0], {%1,%2,%3,%4};"
                   :: "l"(p), "f"(val.x), "f"(val.y), "f"(val.z), "f"(val.w)
                   : "memory");
    }
  }
}

// ---------------------------------------------------------------------------
// edge sort (counting sort by v>>7), once per launch
// ---------------------------------------------------------------------------
__global__ void zero_cnt_kernel() {
  int i = blockIdx.x * 256 + threadIdx.x;
  if (i < NL * NT) g_cnt[i] = 0;
}
__global__ void hist_kernel(const int* __restrict__ v, int nE, int l) {
  int e = blockIdx.x * 256 + threadIdx.x;
  if (e < nE) atomicAdd(&g_cnt[l * NT + (__ldg(&v[e]) >> 7)], 1);
}
__global__ void prefix_kernel() {  // one block per list, 1024 threads
  __shared__ int sh[NT];
  int l = blockIdx.x, t = threadIdx.x;
  sh[t] = g_cnt[l * NT + t];
  __syncthreads();
#pragma unroll
  for (int d = 1; d < NT; d <<= 1) {
    int x = (t >= d) ? sh[t - d] : 0;
    __syncthreads();
    sh[t] += x;
    __syncthreads();
  }
  g_off[l * (NT + 1) + t + 1] = sh[t];
  if (t == 0) g_off[l * (NT + 1)] = 0;
}
__global__ void fill_kernel(const int* __restrict__ u,
                            const int* __restrict__ v, int nE, int l,
                            int sbase) {
  int e = blockIdx.x * 256 + threadIdx.x;
  if (e >= nE) return;
  int vv = __ldg(&v[e]);
  int t = vv >> 7;
  int pos = sbase + g_off[l * (NT + 1) + t] + atomicAdd(&g_cnt[l * NT + t], 1);
  g_eu[pos] = __ldg(&u[e]);
  g_ev[pos] = vv & 127;
}

// ---------------------------------------------------------------------------
// fp16 conversion helpers / elementwise kernels
// ---------------------------------------------------------------------------
DEV_INLINE void h4_store(__half* H, size_t idx4, float4 o) {
  __half2 a = __floats2half2_rn(o.x, o.y);
  __half2 b = __floats2half2_rn(o.z, o.w);
  *(uint2*)(H + idx4) = make_uint2(*(uint32_t*)&a, *(uint32_t*)&b);
}

// Weight split + transpose: out[slot][c][k] = fp16split(src[m][k][c])
__global__ void wsplit_kernel(const float* __restrict__ src, int slotBase,
                              int nm) {
  int idx = blockIdx.x * 256 + threadIdx.x;
  int m = idx >> 14, r = idx & 16383;
  int c = r >> 7, k = r & 127;
  float w = src[(size_t)m * CC + k * 128 + c];
  __half hi = __float2half_rn(w);
  __half lo = __float2half_rn(w - __half2float(hi));
  size_t o = (size_t)(slotBase + m) * CC + r;
  g_Wh[o] = hi;
  g_Wl[o] = lo;
}

__global__ void mlp0_kernel(const float* __restrict__ X2,
                            const float* __restrict__ W0,
                            const float* __restrict__ B0,
                            __half* __restrict__ H) {
  int idx = blockIdx.x * 256 + threadIdx.x;  // N*64
  int n = idx >> 6, c = (idx & 63) << 1;
  float x0 = X2[2 * n], x1 = X2[2 * n + 1];
  float ha = fmaxf(fmaf(x0, W0[c], fmaf(x1, W0[C + c], B0[c])), 0.0f);
  float hb = fmaxf(fmaf(x0, W0[c + 1], fmaf(x1, W0[C + c + 1], B0[c + 1])), 0.0f);
  *(__half2*)(H + (size_t)n * C + c) = __floats2half2_rn(ha, hb);
}

DEV_INLINE float wsum(float v) {
#pragma unroll
  for (int o = 16; o > 0; o >>= 1) v += __shfl_xor_sync(0xffffffffu, v, o);
  return v;
}

__global__ void gn_relu_h_kernel(const float* __restrict__ X,
                                 const float* __restrict__ G,
                                 const float* __restrict__ Bt,
                                 __half* __restrict__ H) {
  int w = (blockIdx.x * blockDim.x + threadIdx.x) >> 5;
  int lane = threadIdx.x & 31;
  float4 x = ((const float4*)X)[(size_t)w * 32 + lane];
  float s = wsum(x.x + x.y + x.z + x.w);
  float q = wsum(x.x * x.x + x.y * x.y + x.z * x.z + x.w * x.w);
  float mu = s * (1.0f / 128.0f);
  float rs = rsqrtf(q * (1.0f / 128.0f) - mu * mu + 1e-5f);
  float4 g = ((const float4*)G)[lane];
  float4 b = ((const float4*)Bt)[lane];
  float4 o;
  o.x = fmaxf((x.x - mu) * rs * g.x + b.x, 0.0f);
  o.y = fmaxf((x.y - mu) * rs * g.y + b.y, 0.0f);
  o.z = fmaxf((x.z - mu) * rs * g.z + b.z, 0.0f);
  o.w = fmaxf((x.w - mu) * rs * g.w + b.w, 0.0f);
  h4_store(H, ((size_t)w * 32 + lane) * 4, o);
}

__global__ void gn_res_relu_kernel(const float* __restrict__ X,
                                   const float* __restrict__ G,
                                   const float* __restrict__ Bt,
                                   const float* __restrict__ Id,
                                   float* __restrict__ Of,
                                   __half* __restrict__ H) {
  int w = (blockIdx.x * blockDim.x + threadIdx.x) >> 5;
  int lane = threadIdx.x & 31;
  float4 x = ((const float4*)X)[(size_t)w * 32 + lane];
  float s = wsum(x.x + x.y + x.z + x.w);
  float q = wsum(x.x * x.x + x.y * x.y + x.z * x.z + x.w * x.w);
  float mu = s * (1.0f / 128.0f);
  float rs = rsqrtf(q * (1.0f / 128.0f) - mu * mu + 1e-5f);
  float4 g = ((const float4*)G)[lane];
  float4 b = ((const float4*)Bt)[lane];
  float4 id = ((const float4*)Id)[(size_t)w * 32 + lane];
  float4 o;
  o.x = fmaxf((x.x - mu) * rs * g.x + b.x + id.x, 0.0f);
  o.y = fmaxf((x.y - mu) * rs * g.y + b.y + id.y, 0.0f);
  o.z = fmaxf((x.z - mu) * rs * g.z + b.z + id.z, 0.0f);
  o.w = fmaxf((x.w - mu) * rs * g.w + b.w + id.w, 0.0f);
  ((float4*)Of)[(size_t)w * 32 + lane] = o;
  if (H) h4_store(H, ((size_t)w * 32 + lane) * 4, o);
}

__global__ void combine_kernel(const float* __restrict__ Y1,
                               const float* __restrict__ Y2,
                               const float* __restrict__ G1,
                               const float* __restrict__ B1,
                               const float* __restrict__ G2,
                               const float* __restrict__ B2,
                               float* __restrict__ Of,
                               __half* __restrict__ H) {
  int w = (blockIdx.x * blockDim.x + threadIdx.x) >> 5;
  int lane = threadIdx.x & 31;
  float4 x1 = ((const float4*)Y1)[(size_t)w * 32 + lane];
  float4 x2 = ((const float4*)Y2)[(size_t)w * 32 + lane];
  float s1 = wsum(x1.x + x1.y + x1.z + x1.w);
  float q1 = wsum(x1.x * x1.x + x1.y * x1.y + x1.z * x1.z + x1.w * x1.w);
  float s2 = wsum(x2.x + x2.y + x2.z + x2.w);
  float q2 = wsum(x2.x * x2.x + x2.y * x2.y + x2.z * x2.z + x2.w * x2.w);
  float mu1 = s1 * (1.0f / 128.0f);
  float rs1 = rsqrtf(q1 * (1.0f / 128.0f) - mu1 * mu1 + 1e-5f);
  float mu2 = s2 * (1.0f / 128.0f);
  float rs2 = rsqrtf(q2 * (1.0f / 128.0f) - mu2 * mu2 + 1e-5f);
  float4 g1 = ((const float4*)G1)[lane];
  float4 b1 = ((const float4*)B1)[lane];
  float4 g2 = ((const float4*)G2)[lane];
  float4 b2 = ((const float4*)B2)[lane];
  float4 o;
  o.x = fmaxf((x1.x - mu1) * rs1 * g1.x + b1.x + (x2.x - mu2) * rs2 * g2.x + b2.x, 0.0f);
  o.y = fmaxf((x1.y - mu1) * rs1 * g1.y + b1.y + (x2.y - mu2) * rs2 * g2.y + b2.y, 0.0f);
  o.z = fmaxf((x1.z - mu1) * rs1 * g1.z + b1.z + (x2.z - mu2) * rs2 * g2.z + b2.z, 0.0f);
  o.w = fmaxf((x1.w - mu1) * rs1 * g1.w + b1.w + (x2.w - mu2) * rs2 * g2.w + b2.w, 0.0f);
  ((float4*)Of)[(size_t)w * 32 + lane] = o;
  h4_store(H, ((size_t)w * 32 + lane) * 4, o);
}

// ---------------------------------------------------------------------------
extern "C" void kernel_launch(void* const* d_in, const int* in_sizes, int n_in,
                              void* d_out, int out_size) {
  const float* ctrs   = (const float*)d_in[0];
  const float* feats  = (const float*)d_in[1];
  const int*   pre_u  = (const int*)d_in[2];
  const int*   pre_v  = (const int*)d_in[3];
  const int*   suc_u  = (const int*)d_in[4];
  const int*   suc_v  = (const int*)d_in[5];
  const int*   left_u = (const int*)d_in[6];
  const int*   left_v = (const int*)d_in[7];
  const int*   right_u= (const int*)d_in[8];
  const int*   right_v= (const int*)d_in[9];
  const float* ic_w0  = (const float*)d_in[10];
  const float* ic_b0  = (const float*)d_in[11];
  const float* ic_w1  = (const float*)d_in[12];
  const float* ic_g   = (const float*)d_in[13];
  const float* ic_bt  = (const float*)d_in[14];
  const float* if_w0  = (const float*)d_in[15];
  const float* if_b0  = (const float*)d_in[16];
  const float* if_w1  = (const float*)d_in[17];
  const float* if_g   = (const float*)d_in[18];
  const float* if_bt  = (const float*)d_in[19];
  const float* ctr_w  = (const float*)d_in[20];
  const float* pre_w  = (const float*)d_in[21];
  const float* suc_w  = (const float*)d_in[22];
  const float* left_w = (const float*)d_in[23];
  const float* right_w= (const float*)d_in[24];
  const float* norm_g = (const float*)d_in[25];
  const float* norm_b = (const float*)d_in[26];
  const float* ctr2_w = (const float*)d_in[27];
  const float* ctr2_g = (const float*)d_in[28];
  const float* ctr2_b = (const float*)d_in[29];
  float* out = (float*)d_out;

  float *FT, *TP, *YB;
  __half *AA, *WH, *WL;
  cudaGetSymbolAddress((void**)&FT, g_feat);
  cudaGetSymbolAddress((void**)&TP, g_temp);
  cudaGetSymbolAddress((void**)&YB, g_Y);
  cudaGetSymbolAddress((void**)&AA, g_A);
  cudaGetSymbolAddress((void**)&WH, g_Wh);
  cudaGetSymbolAddress((void**)&WL, g_Wl);

  cudaFuncSetAttribute(gemm_mma, cudaFuncAttributeMaxDynamicSharedMemorySize,
                       SMEM_MMA_BYTES);
  cudaFuncSetAttribute(fused_block_kernel,
                       cudaFuncAttributeMaxDynamicSharedMemorySize, SMEM_FUSED);

  const int GEMM_GRID = N / 128;
  const int ROW_GRID  = N / 8;
  const int MLP_GRID  = (N * 64) / 256;
  const int ZG = (NL * NT + 255) / 256;
  const int HG = (E + 255) / 256, HGS = (EL + 255) / 256;

  // ---- weight split + transpose ----
  wsplit_kernel<<<1 * 64, 256>>>(ic_w1, 0, 1);
  wsplit_kernel<<<1 * 64, 256>>>(if_w1, 1, 1);
  wsplit_kernel<<<4 * 64, 256>>>(ctr_w, 2, 4);
  wsplit_kernel<<<24 * 64, 256>>>(pre_w, 6, 24);
  wsplit_kernel<<<24 * 64, 256>>>(suc_w, 30, 24);
  wsplit_kernel<<<4 * 64, 256>>>(left_w, 54, 4);
  wsplit_kernel<<<4 * 64, 256>>>(right_w, 58, 4);
  wsplit_kernel<<<4 * 64, 256>>>(ctr2_w, 62, 4);

  // ---- edge sort by source tile (once; reused by all 4 blocks) ----
  zero_cnt_kernel<<<ZG, 256>>>();
  for (int s = 0; s < S; ++s) {
    hist_kernel<<<HG, 256>>>(pre_v + (size_t)s * E, E, s);
    hist_kernel<<<HG, 256>>>(suc_v + (size_t)s * E, E, 6 + s);
  }
  hist_kernel<<<HGS, 256>>>(left_v, EL, 12);
  hist_kernel<<<HGS, 256>>>(right_v, EL, 13);
  prefix_kernel<<<NL, NT>>>();
  zero_cnt_kernel<<<ZG, 256>>>();
  for (int s = 0; s < S; ++s) {
    fill_kernel<<<HG, 256>>>(pre_u + (size_t)s * E, pre_v + (size_t)s * E, E,
                             s, s * E);
    fill_kernel<<<HG, 256>>>(suc_u + (size_t)s * E, suc_v + (size_t)s * E, E,
                             6 + s, (6 + s) * E);
  }
  fill_kernel<<<HGS, 256>>>(left_u, left_v, EL, 12, 12 * E);
  fill_kernel<<<HGS, 256>>>(right_u, right_v, EL, 13, 12 * E + EL);

#define GEMM(slot, OutPtr)                                                   \
  gemm_mma<<<GEMM_GRID, 256, SMEM_MMA_BYTES>>>(                              \
      AA, WH + (size_t)(slot) * CC, WL + (size_t)(slot) * CC, OutPtr)

  // ---- Input stage ----
  mlp0_kernel<<<MLP_GRID, 256>>>(ctrs, ic_w0, ic_b0, AA);
  GEMM(0, FT);
  mlp0_kernel<<<MLP_GRID, 256>>>(feats, if_w0, if_b0, AA);
  GEMM(1, YB);
  combine_kernel<<<ROW_GRID, 256>>>(FT, YB, ic_g, ic_bt, if_g, if_bt, FT, AA);

  // ---- 4 fusion blocks ----
  for (int i = 0; i < NB; ++i) {
    GEMM(2 + i, TP);  // temp = feat @ ctr_w[i] (direct store precedes atomics)
    fused_block_kernel<<<GEMM_GRID, 256, SMEM_FUSED>>>(AA, i, TP);

    gn_relu_h_kernel<<<ROW_GRID, 256>>>(TP, norm_g + (size_t)i * C,
                                        norm_b + (size_t)i * C, AA);
    GEMM(62 + i, TP);  // Y2 = feat_mid @ ctr2_w[i]

    if (i == NB - 1) {
      gn_res_relu_kernel<<<ROW_GRID, 256>>>(TP, ctr2_g + (size_t)i * C,
                                            ctr2_b + (size_t)i * C, FT, out,
                                            nullptr);
    } else {
      gn_res_relu_kernel<<<ROW_GRID, 256>>>(TP, ctr2_g + (size_t)i * C,
                                            ctr2_b + (size_t)i * C, FT, FT,
                                            AA);
    }
  }
#undef GEMM
}

// round 7
// speedup vs baseline: 1.3364x; 1.0328x over previous
#include <cuda_runtime.h>
#include <cuda_fp16.h>
#include <cstdint>

#define DEV_INLINE __device__ __forceinline__

constexpr int N  = 131072;
constexpr int C  = 128;
constexpr int S  = 6;
constexpr int E  = 131072;
constexpr int EL = 32768;
constexpr int NB = 4;
constexpr int CC = C * C;
constexpr int NSLOT = 66;
constexpr int NT = 1024;   // source row tiles (N/128)
constexpr int NL = 14;     // edge lists: 0-5 pre, 6-11 suc, 12 left, 13 right
constexpr int ESTORE = 12 * E + 2 * EL;

// Scratch (allocation-free rule: static __device__ arrays)
__device__ float  g_feat[N * C];
__device__ float  g_temp[N * C];
__device__ float  g_Y[N * C];
__device__ __half g_A[N * C];           // fp16 activations
__device__ __half g_Wh[NSLOT * CC];     // fp16 weight hi, [slot][c][k] (transposed)
__device__ __half g_Wl[NSLOT * CC];     // fp16 weight lo (residual; main path only)
// edge sort scratch
__device__ int g_cnt[NL * NT];
__device__ int g_off[NL * (NT + 1)];
__device__ int g_eu[ESTORE];
__device__ int g_ev[ESTORE];   // v & 127 (row within tile)

DEV_INLINE uint32_t smem_u32(const void* p) {
  uint32_t a;
  asm("{ .reg .u64 t; cvta.to.shared.u64 t, %1; cvt.u32.u64 %0, t; }"
      : "=r"(a) : "l"(p));
  return a;
}

// ---------------------------------------------------------------------------
// MMA building blocks. smem tile: 128 rows x 256B, XOR-16B swizzle on (row&7)
// ---------------------------------------------------------------------------
constexpr int TILE_BYTES = 128 * 256;  // 32 KB (128x128 fp16)

DEV_INLINE void ldsm4(uint32_t& r0, uint32_t& r1, uint32_t& r2, uint32_t& r3,
                      uint32_t addr) {
  asm volatile("ldmatrix.sync.aligned.m8n8.x4.shared.b16 {%0,%1,%2,%3}, [%4];"
               : "=r"(r0), "=r"(r1), "=r"(r2), "=r"(r3) : "r"(addr));
}
DEV_INLINE void mma_f16(float* c, uint32_t a0, uint32_t a1, uint32_t a2,
                        uint32_t a3, uint32_t b0, uint32_t b1) {
  asm volatile(
      "mma.sync.aligned.m16n8k16.row.col.f32.f16.f16.f32 "
      "{%0,%1,%2,%3}, {%4,%5,%6,%7}, {%8,%9}, {%0,%1,%2,%3};"
      : "+f"(c[0]), "+f"(c[1]), "+f"(c[2]), "+f"(c[3])
      : "r"(a0), "r"(a1), "r"(a2), "r"(a3), "r"(b0), "r"(b1));
}

DEV_INLINE void cp_async16(uint32_t dst, const void* src) {
  asm volatile("cp.async.cg.shared.global [%0], [%1], 16;" :: "r"(dst),
               "l"(src));
}
#define CP_COMMIT() asm volatile("cp.async.commit_group;" ::: "memory")
#define CP_WAIT(n)  asm volatile("cp.async.wait_group %0;" :: "n"(n) : "memory")

// stage one 128x128 fp16 tile (32 KB) with swizzle via cp.async; 256 threads
DEV_INLINE void stage_async(uint32_t dstBase, const __half* src, int tid) {
  const char* s = (const char*)src;
#pragma unroll
  for (int t = 0; t < 8; ++t) {
    int idx = tid + t * 256;
    int r = idx >> 4, c16 = idx & 15;
    uint32_t off = r * 256 + ((c16 * 16) ^ ((r & 7) << 4));
    cp_async16(dstBase + off, s + idx * 16);
  }
}

// fragment address precompute
struct FragIdx {
  uint32_t aRow[4], aColK, bRow[2], bColK;
  int rw, cw;
};
DEV_INLINE FragIdx frag_idx(int lane, int wid) {
  FragIdx f;
  f.rw = (wid & 1) * 64;
  f.cw = (wid >> 1) * 32;
  f.aColK = (lane >> 4) * 16;
#pragma unroll
  for (int mi = 0; mi < 4; ++mi) f.aRow[mi] = f.rw + mi * 16 + (lane & 15);
  f.bColK = ((lane >> 3) & 1) * 16;
#pragma unroll
  for (int bi = 0; bi < 2; ++bi)
    f.bRow[bi] = f.cw + bi * 16 + ((lane >> 4) * 8) + (lane & 7);
  return f;
}

DEV_INLINE void zero_acc(float (&acc)[4][4][4]) {
#pragma unroll
  for (int mi = 0; mi < 4; ++mi)
#pragma unroll
    for (int ni = 0; ni < 4; ++ni)
#pragma unroll
      for (int j = 0; j < 4; ++j) acc[mi][ni][j] = 0.0f;
}

// one K-sweep (8 chunks) of A@B accumulated
DEV_INLINE void mma_pass(uint32_t aBase, uint32_t bBase, const FragIdx& f,
                         float (&acc)[4][4][4]) {
#pragma unroll
  for (int kk = 0; kk < 8; ++kk) {
    const uint32_t kb = kk * 32;
    uint32_t a[4][4];
#pragma unroll
    for (int mi = 0; mi < 4; ++mi) {
      uint32_t r = f.aRow[mi];
      uint32_t addr = aBase + r * 256 + ((kb | f.aColK) ^ ((r & 7) << 4));
      ldsm4(a[mi][0], a[mi][1], a[mi][2], a[mi][3], addr);
    }
    uint32_t b[4][2];
#pragma unroll
    for (int bi = 0; bi < 2; ++bi) {
      uint32_t r = f.bRow[bi];
      uint32_t addr = bBase + r * 256 + ((kb | f.bColK) ^ ((r & 7) << 4));
      ldsm4(b[bi * 2][0], b[bi * 2][1], b[bi * 2 + 1][0], b[bi * 2 + 1][1],
            addr);
    }
#pragma unroll
    for (int mi = 0; mi < 4; ++mi)
#pragma unroll
      for (int ni = 0; ni < 4; ++ni)
        mma_f16(acc[mi][ni], a[mi][0], a[mi][1], a[mi][2], a[mi][3],
                b[ni][0], b[ni][1]);
  }
}

DEV_INLINE void store_acc_global(float* Out, int rowBase, int lane, int wid,
                                 float (&acc)[4][4][4]) {
  const int rw = (wid & 1) * 64, cw = (wid >> 1) * 32;
  const int r0 = lane >> 2, c0 = (lane & 3) * 2;
#pragma unroll
  for (int mi = 0; mi < 4; ++mi)
#pragma unroll
    for (int ni = 0; ni < 4; ++ni) {
      int grow = rowBase + rw + mi * 16 + r0;
      int gcol = cw + ni * 8 + c0;
      *(float2*)(Out + (size_t)grow * C + gcol) =
          make_float2(acc[mi][ni][0], acc[mi][ni][1]);
      *(float2*)(Out + (size_t)(grow + 8) * C + gcol) =
          make_float2(acc[mi][ni][2], acc[mi][ni][3]);
    }
}

// ---------------------------------------------------------------------------
// standalone GEMM (main path, 2-pass): Out = A@(Wh+Wl)^T. 96 KB -> 2 CTA/SM.
// ---------------------------------------------------------------------------
constexpr int SMEM_MMA_BYTES = 3 * TILE_BYTES;  // 96 KB

__global__ void __launch_bounds__(256, 2) gemm_mma(
    const __half* __restrict__ A, const __half* __restrict__ Bh,
    const __half* __restrict__ Bl, float* __restrict__ Out) {
  extern __shared__ __align__(16) char smem[];
  const uint32_t sbase = smem_u32(smem);
  const int tid = threadIdx.x, lane = tid & 31, wid = tid >> 5;
  const int rowBase = blockIdx.x * 128;

  stage_async(sbase, A + (size_t)rowBase * C, tid);
  stage_async(sbase + TILE_BYTES, Bh, tid);
  stage_async(sbase + 2 * TILE_BYTES, Bl, tid);
  CP_COMMIT();
  CP_WAIT(0);
  __syncthreads();

  FragIdx f = frag_idx(lane, wid);
  float acc[4][4][4];
  zero_acc(acc);
  mma_pass(sbase, sbase + TILE_BYTES, f, acc);
  mma_pass(sbase, sbase + 2 * TILE_BYTES, f, acc);
  store_acc_global(Out, rowBase, lane, wid, acc);
}

// ---------------------------------------------------------------------------
// fused per-block kernel: 14 edge-GEMMs (single-pass fp16 W) + smem scatter
// smem: A(32K) + W x2 (32K each) + Ybuf(128x132 f32 = 66K) = 165888 B
// ---------------------------------------------------------------------------
constexpr int YPITCH = 132;
constexpr int W_OFF = TILE_BYTES;                    // 32768
constexpr int Y_OFF = 3 * TILE_BYTES;                // 98304
constexpr int SMEM_FUSED = Y_OFF + 128 * YPITCH * 4; // 165888

__global__ void __launch_bounds__(256, 1) fused_block_kernel(
    const __half* __restrict__ A, int ib, float* __restrict__ TP) {
  extern __shared__ __align__(16) char smem[];
  const uint32_t sbase = smem_u32(smem);
  float* Ybuf = (float*)(smem + Y_OFF);
  const int tid = threadIdx.x, lane = tid & 31, wid = tid >> 5;
  const int rowBase = blockIdx.x * 128;

  const int rw = (wid & 1) * 64, cw = (wid >> 1) * 32;
  const int r0 = lane >> 2, c0 = (lane & 3) * 2;

  auto slot_of = [&](int l) {
    return (l < 6)    ? 6 + ib * 6 + l
           : (l < 12) ? 30 + ib * 6 + (l - 6)
           : (l == 12) ? 54 + ib : 58 + ib;
  };

  // group 0: A + W(0)
  stage_async(sbase, A + (size_t)rowBase * C, tid);
  stage_async(sbase + W_OFF, g_Wh + (size_t)slot_of(0) * CC, tid);
  CP_COMMIT();

  FragIdx f = frag_idx(lane, wid);

#pragma unroll 1
  for (int l = 0; l < 14; ++l) {
    if (l < 13) {
      uint32_t nb = W_OFF + ((l + 1) & 1) * TILE_BYTES;
      stage_async(sbase + nb, g_Wh + (size_t)slot_of(l + 1) * CC, tid);
      CP_COMMIT();
      CP_WAIT(1);  // W(l) (and A on l=0) complete
    } else {
      CP_WAIT(0);
    }
    __syncthreads();  // also guards Ybuf(l-1) fully read before rewrite

    const uint32_t wb = W_OFF + (l & 1) * TILE_BYTES;
    float acc[4][4][4];
    zero_acc(acc);
    mma_pass(sbase, sbase + wb, f, acc);

    // stage Y tile to smem (pitch 132: conflict-free)
#pragma unroll
    for (int mi = 0; mi < 4; ++mi)
#pragma unroll
      for (int ni = 0; ni < 4; ++ni) {
        int row = rw + mi * 16 + r0, col = cw + ni * 8 + c0;
        *(float2*)(Ybuf + row * YPITCH + col) =
            make_float2(acc[mi][ni][0], acc[mi][ni][1]);
        *(float2*)(Ybuf + (row + 8) * YPITCH + col) =
            make_float2(acc[mi][ni][2], acc[mi][ni][3]);
      }
    __syncthreads();

    // scatter this tile's edges; warp per edge (W(l+1) cp.async in flight)
    int ebase = (l < 12) ? l * E : 12 * E + (l - 12) * EL;
    int o0 = g_off[l * (NT + 1) + blockIdx.x];
    int o1 = g_off[l * (NT + 1) + blockIdx.x + 1];
    for (int j = o0 + wid; j < o1; j += 8) {
      int uu = g_eu[ebase + j];
      int vl = g_ev[ebase + j];
      float4 val = *(float4*)(Ybuf + vl * YPITCH + lane * 4);
      float* p = TP + (size_t)uu * C + lane * 4;
      asm volatile("red.global.add.v4.f32 [%0], {%1,%2,%3,%4};"
                   :: "l"(p), "f"(val.x), "f"(val.y), "f"(val.z), "f"(val.w)
                   : "memory");
    }
  }
}

// ---------------------------------------------------------------------------
// edge sort (counting sort by v>>7), once per launch
// ---------------------------------------------------------------------------
__global__ void zero_cnt_kernel() {
  int i = blockIdx.x * 256 + threadIdx.x;
  if (i < NL * NT) g_cnt[i] = 0;
}
__global__ void hist_kernel(const int* __restrict__ v, int nE, int l) {
  int e = blockIdx.x * 256 + threadIdx.x;
  if (e < nE) atomicAdd(&g_cnt[l * NT + (__ldg(&v[e]) >> 7)], 1);
}
__global__ void prefix_kernel() {  // one block per list, 1024 threads
  __shared__ int sh[NT];
  int l = blockIdx.x, t = threadIdx.x;
  sh[t] = g_cnt[l * NT + t];
  __syncthreads();
#pragma unroll
  for (int d = 1; d < NT; d <<= 1) {
    int x = (t >= d) ? sh[t - d] : 0;
    __syncthreads();
    sh[t] += x;
    __syncthreads();
  }
  g_off[l * (NT + 1) + t + 1] = sh[t];
  if (t == 0) g_off[l * (NT + 1)] = 0;
}
__global__ void fill_kernel(const int* __restrict__ u,
                            const int* __restrict__ v, int nE, int l,
                            int sbase) {
  int e = blockIdx.x * 256 + threadIdx.x;
  if (e >= nE) return;
  int vv = __ldg(&v[e]);
  int t = vv >> 7;
  int pos = sbase + g_off[l * (NT + 1) + t] + atomicAdd(&g_cnt[l * NT + t], 1);
  g_eu[pos] = __ldg(&u[e]);
  g_ev[pos] = vv & 127;
}

// ---------------------------------------------------------------------------
// fp16 conversion helpers / elementwise kernels
// ---------------------------------------------------------------------------
DEV_INLINE void h4_store(__half* H, size_t idx4, float4 o) {
  __half2 a = __floats2half2_rn(o.x, o.y);
  __half2 b = __floats2half2_rn(o.z, o.w);
  *(uint2*)(H + idx4) = make_uint2(*(uint32_t*)&a, *(uint32_t*)&b);
}

// Weight split + transpose: out[slot][c][k] = fp16split(src[m][k][c])
__global__ void wsplit_kernel(const float* __restrict__ src, int slotBase,
                              int nm) {
  int idx = blockIdx.x * 256 + threadIdx.x;
  int m = idx >> 14, r = idx & 16383;
  int c = r >> 7, k = r & 127;
  float w = src[(size_t)m * CC + k * 128 + c];
  __half hi = __float2half_rn(w);
  __half lo = __float2half_rn(w - __half2float(hi));
  size_t o = (size_t)(slotBase + m) * CC + r;
  g_Wh[o] = hi;
  g_Wl[o] = lo;
}

__global__ void mlp0_kernel(const float* __restrict__ X2,
                            const float* __restrict__ W0,
                            const float* __restrict__ B0,
                            __half* __restrict__ H) {
  int idx = blockIdx.x * 256 + threadIdx.x;  // N*64
  int n = idx >> 6, c = (idx & 63) << 1;
  float x0 = X2[2 * n], x1 = X2[2 * n + 1];
  float ha = fmaxf(fmaf(x0, W0[c], fmaf(x1, W0[C + c], B0[c])), 0.0f);
  float hb = fmaxf(fmaf(x0, W0[c + 1], fmaf(x1, W0[C + c + 1], B0[c + 1])), 0.0f);
  *(__half2*)(H + (size_t)n * C + c) = __floats2half2_rn(ha, hb);
}

DEV_INLINE float wsum(float v) {
#pragma unroll
  for (int o = 16; o > 0; o >>= 1) v += __shfl_xor_sync(0xffffffffu, v, o);
  return v;
}

__global__ void gn_relu_h_kernel(const float* __restrict__ X,
                                 const float* __restrict__ G,
                                 const float* __restrict__ Bt,
                                 __half* __restrict__ H) {
  int w = (blockIdx.x * blockDim.x + threadIdx.x) >> 5;
  int lane = threadIdx.x & 31;
  float4 x = ((const float4*)X)[(size_t)w * 32 + lane];
  float s = wsum(x.x + x.y + x.z + x.w);
  float q = wsum(x.x * x.x + x.y * x.y + x.z * x.z + x.w * x.w);
  float mu = s * (1.0f / 128.0f);
  float rs = rsqrtf(q * (1.0f / 128.0f) - mu * mu + 1e-5f);
  float4 g = ((const float4*)G)[lane];
  float4 b = ((const float4*)Bt)[lane];
  float4 o;
  o.x = fmaxf((x.x - mu) * rs * g.x + b.x, 0.0f);
  o.y = fmaxf((x.y - mu) * rs * g.y + b.y, 0.0f);
  o.z = fmaxf((x.z - mu) * rs * g.z + b.z, 0.0f);
  o.w = fmaxf((x.w - mu) * rs * g.w + b.w, 0.0f);
  h4_store(H, ((size_t)w * 32 + lane) * 4, o);
}

__global__ void gn_res_relu_kernel(const float* __restrict__ X,
                                   const float* __restrict__ G,
                                   const float* __restrict__ Bt,
                                   const float* __restrict__ Id,
                                   float* __restrict__ Of,
                                   __half* __restrict__ H) {
  int w = (blockIdx.x * blockDim.x + threadIdx.x) >> 5;
  int lane = threadIdx.x & 31;
  float4 x = ((const float4*)X)[(size_t)w * 32 + lane];
  float s = wsum(x.x + x.y + x.z + x.w);
  float q = wsum(x.x * x.x + x.y * x.y + x.z * x.z + x.w * x.w);
  float mu = s * (1.0f / 128.0f);
  float rs = rsqrtf(q * (1.0f / 128.0f) - mu * mu + 1e-5f);
  float4 g = ((const float4*)G)[lane];
  float4 b = ((const float4*)Bt)[lane];
  float4 id = ((const float4*)Id)[(size_t)w * 32 + lane];
  float4 o;
  o.x = fmaxf((x.x - mu) * rs * g.x + b.x + id.x, 0.0f);
  o.y = fmaxf((x.y - mu) * rs * g.y + b.y + id.y, 0.0f);
  o.z = fmaxf((x.z - mu) * rs * g.z + b.z + id.z, 0.0f);
  o.w = fmaxf((x.w - mu) * rs * g.w + b.w + id.w, 0.0f);
  ((float4*)Of)[(size_t)w * 32 + lane] = o;
  if (H) h4_store(H, ((size_t)w * 32 + lane) * 4, o);
}

__global__ void combine_kernel(const float* __restrict__ Y1,
                               const float* __restrict__ Y2,
                               const float* __restrict__ G1,
                               const float* __restrict__ B1,
                               const float* __restrict__ G2,
                               const float* __restrict__ B2,
                               float* __restrict__ Of,
                               __half* __restrict__ H) {
  int w = (blockIdx.x * blockDim.x + threadIdx.x) >> 5;
  int lane = threadIdx.x & 31;
  float4 x1 = ((const float4*)Y1)[(size_t)w * 32 + lane];
  float4 x2 = ((const float4*)Y2)[(size_t)w * 32 + lane];
  float s1 = wsum(x1.x + x1.y + x1.z + x1.w);
  float q1 = wsum(x1.x * x1.x + x1.y * x1.y + x1.z * x1.z + x1.w * x1.w);
  float s2 = wsum(x2.x + x2.y + x2.z + x2.w);
  float q2 = wsum(x2.x * x2.x + x2.y * x2.y + x2.z * x2.z + x2.w * x2.w);
  float mu1 = s1 * (1.0f / 128.0f);
  float rs1 = rsqrtf(q1 * (1.0f / 128.0f) - mu1 * mu1 + 1e-5f);
  float mu2 = s2 * (1.0f / 128.0f);
  float rs2 = rsqrtf(q2 * (1.0f / 128.0f) - mu2 * mu2 + 1e-5f);
  float4 g1 = ((const float4*)G1)[lane];
  float4 b1 = ((const float4*)B1)[lane];
  float4 g2 = ((const float4*)G2)[lane];
  float4 b2 = ((const float4*)B2)[lane];
  float4 o;
  o.x = fmaxf((x1.x - mu1) * rs1 * g1.x + b1.x + (x2.x - mu2) * rs2 * g2.x + b2.x, 0.0f);
  o.y = fmaxf((x1.y - mu1) * rs1 * g1.y + b1.y + (x2.y - mu2) * rs2 * g2.y + b2.y, 0.0f);
  o.z = fmaxf((x1.z - mu1) * rs1 * g1.z + b1.z + (x2.z - mu2) * rs2 * g2.z + b2.z, 0.0f);
  o.w = fmaxf((x1.w - mu1) * rs1 * g1.w + b1.w + (x2.w - mu2) * rs2 * g2.w + b2.w, 0.0f);
  ((float4*)Of)[(size_t)w * 32 + lane] = o;
  h4_store(H, ((size_t)w * 32 + lane) * 4, o);
}

// ---------------------------------------------------------------------------
extern "C" void kernel_launch(void* const* d_in, const int* in_sizes, int n_in,
                              void* d_out, int out_size) {
  const float* ctrs   = (const float*)d_in[0];
  const float* feats  = (const float*)d_in[1];
  const int*   pre_u  = (const int*)d_in[2];
  const int*   pre_v  = (const int*)d_in[3];
  const int*   suc_u  = (const int*)d_in[4];
  const int*   suc_v  = (const int*)d_in[5];
  const int*   left_u = (const int*)d_in[6];
  const int*   left_v = (const int*)d_in[7];
  const int*   right_u= (const int*)d_in[8];
  const int*   right_v= (const int*)d_in[9];
  const float* ic_w0  = (const float*)d_in[10];
  const float* ic_b0  = (const float*)d_in[11];
  const float* ic_w1  = (const float*)d_in[12];
  const float* ic_g   = (const float*)d_in[13];
  const float* ic_bt  = (const float*)d_in[14];
  const float* if_w0  = (const float*)d_in[15];
  const float* if_b0  = (const float*)d_in[16];
  const float* if_w1  = (const float*)d_in[17];
  const float* if_g   = (const float*)d_in[18];
  const float* if_bt  = (const float*)d_in[19];
  const float* ctr_w  = (const float*)d_in[20];
  const float* pre_w  = (const float*)d_in[21];
  const float* suc_w  = (const float*)d_in[22];
  const float* left_w = (const float*)d_in[23];
  const float* right_w= (const float*)d_in[24];
  const float* norm_g = (const float*)d_in[25];
  const float* norm_b = (const float*)d_in[26];
  const float* ctr2_w = (const float*)d_in[27];
  const float* ctr2_g = (const float*)d_in[28];
  const float* ctr2_b = (const float*)d_in[29];
  float* out = (float*)d_out;

  float *FT, *TP, *YB;
  __half *AA, *WH, *WL;
  cudaGetSymbolAddress((void**)&FT, g_feat);
  cudaGetSymbolAddress((void**)&TP, g_temp);
  cudaGetSymbolAddress((void**)&YB, g_Y);
  cudaGetSymbolAddress((void**)&AA, g_A);
  cudaGetSymbolAddress((void**)&WH, g_Wh);
  cudaGetSymbolAddress((void**)&WL, g_Wl);

  cudaFuncSetAttribute(gemm_mma, cudaFuncAttributeMaxDynamicSharedMemorySize,
                       SMEM_MMA_BYTES);
  cudaFuncSetAttribute(fused_block_kernel,
                       cudaFuncAttributeMaxDynamicSharedMemorySize, SMEM_FUSED);

  const int GEMM_GRID = N / 128;
  const int ROW_GRID  = N / 8;
  const int MLP_GRID  = (N * 64) / 256;
  const int ZG = (NL * NT + 255) / 256;
  const int HG = (E + 255) / 256, HGS = (EL + 255) / 256;

  // ---- weight split + transpose ----
  wsplit_kernel<<<1 * 64, 256>>>(ic_w1, 0, 1);
  wsplit_kernel<<<1 * 64, 256>>>(if_w1, 1, 1);
  wsplit_kernel<<<4 * 64, 256>>>(ctr_w, 2, 4);
  wsplit_kernel<<<24 * 64, 256>>>(pre_w, 6, 24);
  wsplit_kernel<<<24 * 64, 256>>>(suc_w, 30, 24);
  wsplit_kernel<<<4 * 64, 256>>>(left_w, 54, 4);
  wsplit_kernel<<<4 * 64, 256>>>(right_w, 58, 4);
  wsplit_kernel<<<4 * 64, 256>>>(ctr2_w, 62, 4);

  // ---- edge sort by source tile (once; reused by all 4 blocks) ----
  zero_cnt_kernel<<<ZG, 256>>>();
  for (int s = 0; s < S; ++s) {
    hist_kernel<<<HG, 256>>>(pre_v + (size_t)s * E, E, s);
    hist_kernel<<<HG, 256>>>(suc_v + (size_t)s * E, E, 6 + s);
  }
  hist_kernel<<<HGS, 256>>>(left_v, EL, 12);
  hist_kernel<<<HGS, 256>>>(right_v, EL, 13);
  prefix_kernel<<<NL, NT>>>();
  zero_cnt_kernel<<<ZG, 256>>>();
  for (int s = 0; s < S; ++s) {
    fill_kernel<<<HG, 256>>>(pre_u + (size_t)s * E, pre_v + (size_t)s * E, E,
                             s, s * E);
    fill_kernel<<<HG, 256>>>(suc_u + (size_t)s * E, suc_v + (size_t)s * E, E,
                             6 + s, (6 + s) * E);
  }
  fill_kernel<<<HGS, 256>>>(left_u, left_v, EL, 12, 12 * E);
  fill_kernel<<<HGS, 256>>>(right_u, right_v, EL, 13, 12 * E + EL);

#define GEMM(slot, OutPtr)                                                   \
  gemm_mma<<<GEMM_GRID, 256, SMEM_MMA_BYTES>>>(                              \
      AA, WH + (size_t)(slot) * CC, WL + (size_t)(slot) * CC, OutPtr)

  // ---- Input stage ----
  mlp0_kernel<<<MLP_GRID, 256>>>(ctrs, ic_w0, ic_b0, AA);
  GEMM(0, FT);
  mlp0_kernel<<<MLP_GRID, 256>>>(feats, if_w0, if_b0, AA);
  GEMM(1, YB);
  combine_kernel<<<ROW_GRID, 256>>>(FT, YB, ic_g, ic_bt, if_g, if_bt, FT, AA);

  // ---- 4 fusion blocks ----
  for (int i = 0; i < NB; ++i) {
    GEMM(2 + i, TP);  // temp = feat @ ctr_w[i] (direct store precedes atomics)
    fused_block_kernel<<<GEMM_GRID, 256, SMEM_FUSED>>>(AA, i, TP);

    gn_relu_h_kernel<<<ROW_GRID, 256>>>(TP, norm_g + (size_t)i * C,
                                        norm_b + (size_t)i * C, AA);
    GEMM(62 + i, TP);  // Y2 = feat_mid @ ctr2_w[i]

    if (i == NB - 1) {
      gn_res_relu_kernel<<<ROW_GRID, 256>>>(TP, ctr2_g + (size_t)i * C,
                                            ctr2_b + (size_t)i * C, FT, out,
                                            nullptr);
    } else {
      gn_res_relu_kernel<<<ROW_GRID, 256>>>(TP, ctr2_g + (size_t)i * C,
                                            ctr2_b + (size_t)i * C, FT, FT,
                                            AA);
    }
  }
#undef GEMM
}

// round 9
// speedup vs baseline: 1.9420x; 1.4531x over previous
#include <cuda_runtime.h>
#include <cuda_fp16.h>
#include <cstdint>

#define DEV_INLINE __device__ __forceinline__

constexpr int N  = 131072;
constexpr int C  = 128;
constexpr int S  = 6;
constexpr int E  = 131072;
constexpr int EL = 32768;
constexpr int NB = 4;
constexpr int CC = C * C;
constexpr int NSLOT = 66;
constexpr int NT = 1024;   // source row tiles (N/128)
constexpr int NL = 14;     // edge lists: 0-5 pre, 6-11 suc, 12 left, 13 right
constexpr int ESTORE = 12 * E + 2 * EL;

// Scratch (allocation-free rule: static __device__ arrays)
__device__ float  g_feat[N * C];
__device__ float  g_temp[N * C];
__device__ float  g_Y[N * C];
__device__ __half g_A[N * C];           // fp16 activations
__device__ __half g_Wh[NSLOT * CC];     // fp16 weight hi, [slot][c][k] (transposed)
__device__ __half g_Wl[NSLOT * CC];     // fp16 weight lo (residual; main path only)
// edge sort scratch
__device__ int g_cnt[NL * NT];
__device__ int g_off[NL * (NT + 1)];
__device__ int g_epk[ESTORE];  // packed edge: (u << 7) | (v & 127)

DEV_INLINE uint32_t smem_u32(const void* p) {
  uint32_t a;
  asm("{ .reg .u64 t; cvta.to.shared.u64 t, %1; cvt.u32.u64 %0, t; }"
      : "=r"(a) : "l"(p));
  return a;
}

// ---------------------------------------------------------------------------
// MMA building blocks. smem tile: 128 rows x 256B, XOR-16B swizzle on (row&7)
// ---------------------------------------------------------------------------
constexpr int TILE_BYTES = 128 * 256;  // 32 KB (128x128 fp16)

DEV_INLINE void ldsm4(uint32_t& r0, uint32_t& r1, uint32_t& r2, uint32_t& r3,
                      uint32_t addr) {
  asm volatile("ldmatrix.sync.aligned.m8n8.x4.shared.b16 {%0,%1,%2,%3}, [%4];"
               : "=r"(r0), "=r"(r1), "=r"(r2), "=r"(r3) : "r"(addr));
}
DEV_INLINE void mma_f16(float* c, uint32_t a0, uint32_t a1, uint32_t a2,
                        uint32_t a3, uint32_t b0, uint32_t b1) {
  asm volatile(
      "mma.sync.aligned.m16n8k16.row.col.f32.f16.f16.f32 "
      "{%0,%1,%2,%3}, {%4,%5,%6,%7}, {%8,%9}, {%0,%1,%2,%3};"
      : "+f"(c[0]), "+f"(c[1]), "+f"(c[2]), "+f"(c[3])
      : "r"(a0), "r"(a1), "r"(a2), "r"(a3), "r"(b0), "r"(b1));
}

DEV_INLINE void cp_async16(uint32_t dst, const void* src) {
  asm volatile("cp.async.cg.shared.global [%0], [%1], 16;" :: "r"(dst),
               "l"(src));
}
#define CP_COMMIT() asm volatile("cp.async.commit_group;" ::: "memory")
#define CP_WAIT(n)  asm volatile("cp.async.wait_group %0;" :: "n"(n) : "memory")

// stage one 128x128 fp16 tile (32 KB) with swizzle via cp.async; 256 threads
DEV_INLINE void stage_async(uint32_t dstBase, const __half* src, int tid) {
  const char* s = (const char*)src;
#pragma unroll
  for (int t = 0; t < 8; ++t) {
    int idx = tid + t * 256;
    int r = idx >> 4, c16 = idx & 15;
    uint32_t off = r * 256 + ((c16 * 16) ^ ((r & 7) << 4));
    cp_async16(dstBase + off, s + idx * 16);
  }
}

// fragment address precompute
struct FragIdx {
  uint32_t aRow[4], aColK, bRow[2], bColK;
  int rw, cw;
};
DEV_INLINE FragIdx frag_idx(int lane, int wid) {
  FragIdx f;
  f.rw = (wid & 1) * 64;
  f.cw = (wid >> 1) * 32;
  f.aColK = (lane >> 4) * 16;
#pragma unroll
  for (int mi = 0; mi < 4; ++mi) f.aRow[mi] = f.rw + mi * 16 + (lane & 15);
  f.bColK = ((lane >> 3) & 1) * 16;
#pragma unroll
  for (int bi = 0; bi < 2; ++bi)
    f.bRow[bi] = f.cw + bi * 16 + ((lane >> 4) * 8) + (lane & 7);
  return f;
}

DEV_INLINE void zero_acc(float (&acc)[4][4][4]) {
#pragma unroll
  for (int mi = 0; mi < 4; ++mi)
#pragma unroll
    for (int ni = 0; ni < 4; ++ni)
#pragma unroll
      for (int j = 0; j < 4; ++j) acc[mi][ni][j] = 0.0f;
}

// one K-sweep (8 chunks) of A@B accumulated
DEV_INLINE void mma_pass(uint32_t aBase, uint32_t bBase, const FragIdx& f,
                         float (&acc)[4][4][4]) {
#pragma unroll
  for (int kk = 0; kk < 8; ++kk) {
    const uint32_t kb = kk * 32;
    uint32_t a[4][4];
#pragma unroll
    for (int mi = 0; mi < 4; ++mi) {
      uint32_t r = f.aRow[mi];
      uint32_t addr = aBase + r * 256 + ((kb | f.aColK) ^ ((r & 7) << 4));
      ldsm4(a[mi][0], a[mi][1], a[mi][2], a[mi][3], addr);
    }
    uint32_t b[4][2];
#pragma unroll
    for (int bi = 0; bi < 2; ++bi) {
      uint32_t r = f.bRow[bi];
      uint32_t addr = bBase + r * 256 + ((kb | f.bColK) ^ ((r & 7) << 4));
      ldsm4(b[bi * 2][0], b[bi * 2][1], b[bi * 2 + 1][0], b[bi * 2 + 1][1],
            addr);
    }
#pragma unroll
    for (int mi = 0; mi < 4; ++mi)
#pragma unroll
      for (int ni = 0; ni < 4; ++ni)
        mma_f16(acc[mi][ni], a[mi][0], a[mi][1], a[mi][2], a[mi][3],
                b[ni][0], b[ni][1]);
  }
}

DEV_INLINE void store_acc_global(float* Out, int rowBase, int lane, int wid,
                                 float (&acc)[4][4][4]) {
  const int rw = (wid & 1) * 64, cw = (wid >> 1) * 32;
  const int r0 = lane >> 2, c0 = (lane & 3) * 2;
#pragma unroll
  for (int mi = 0; mi < 4; ++mi)
#pragma unroll
    for (int ni = 0; ni < 4; ++ni) {
      int grow = rowBase + rw + mi * 16 + r0;
      int gcol = cw + ni * 8 + c0;
      *(float2*)(Out + (size_t)grow * C + gcol) =
          make_float2(acc[mi][ni][0], acc[mi][ni][1]);
      *(float2*)(Out + (size_t)(grow + 8) * C + gcol) =
          make_float2(acc[mi][ni][2], acc[mi][ni][3]);
    }
}

// ---------------------------------------------------------------------------
// standalone GEMM (main path, 2-pass): Out = A@(Wh+Wl)^T. 96 KB -> 2 CTA/SM.
// ---------------------------------------------------------------------------
constexpr int SMEM_MMA_BYTES = 3 * TILE_BYTES;  // 96 KB

__global__ void __launch_bounds__(256, 2) gemm_mma(
    const __half* __restrict__ A, const __half* __restrict__ Bh,
    const __half* __restrict__ Bl, float* __restrict__ Out) {
  extern __shared__ __align__(16) char smem[];
  const uint32_t sbase = smem_u32(smem);
  const int tid = threadIdx.x, lane = tid & 31, wid = tid >> 5;
  const int rowBase = blockIdx.x * 128;

  stage_async(sbase, A + (size_t)rowBase * C, tid);
  stage_async(sbase + TILE_BYTES, Bh, tid);
  stage_async(sbase + 2 * TILE_BYTES, Bl, tid);
  CP_COMMIT();
  CP_WAIT(0);
  __syncthreads();

  FragIdx f = frag_idx(lane, wid);
  float acc[4][4][4];
  zero_acc(acc);
  mma_pass(sbase, sbase + TILE_BYTES, f, acc);
  mma_pass(sbase, sbase + 2 * TILE_BYTES, f, acc);
  store_acc_global(Out, rowBase, lane, wid, acc);
}

// single-pass variant (ctr slots; same error status as edge messages)
__global__ void __launch_bounds__(256, 2) gemm_mma1(
    const __half* __restrict__ A, const __half* __restrict__ Bh,
    float* __restrict__ Out) {
  extern __shared__ __align__(16) char smem[];
  const uint32_t sbase = smem_u32(smem);
  const int tid = threadIdx.x, lane = tid & 31, wid = tid >> 5;
  const int rowBase = blockIdx.x * 128;

  stage_async(sbase, A + (size_t)rowBase * C, tid);
  stage_async(sbase + TILE_BYTES, Bh, tid);
  CP_COMMIT();
  CP_WAIT(0);
  __syncthreads();

  FragIdx f = frag_idx(lane, wid);
  float acc[4][4][4];
  zero_acc(acc);
  mma_pass(sbase, sbase + TILE_BYTES, f, acc);
  store_acc_global(Out, rowBase, lane, wid, acc);
}

// ---------------------------------------------------------------------------
// fused per-block kernel: 14 edge-GEMMs (single-pass fp16 W) + smem scatter
// smem: A(32K) + W(32K) + Ybuf fp16 (128 x 136 halves = 34816B) = 100352 B
// -> 2 CTAs/SM: one CTA's scatter overlaps the other's MMA.
// W(l+1) prefetched via cp.async during scatter(l).
// ---------------------------------------------------------------------------
constexpr int YPITCH_H = 136;  // halves; 272B rows -> 4-bank stagger, conflict-free
constexpr int W_OFF = TILE_BYTES;       // 32768
constexpr int Y_OFF = 2 * TILE_BYTES;   // 65536
constexpr int SMEM_FUSED = Y_OFF + 128 * YPITCH_H * 2;  // 100352

__global__ void __launch_bounds__(256, 2) fused_block_kernel(
    const __half* __restrict__ A, int ib, float* __restrict__ TP) {
  extern __shared__ __align__(16) char smem[];
  const uint32_t sbase = smem_u32(smem);
  __half* Ybuf = (__half*)(smem + Y_OFF);
  const int tid = threadIdx.x, lane = tid & 31, wid = tid >> 5;
  const int rowBase = blockIdx.x * 128;

  const int rw = (wid & 1) * 64, cw = (wid >> 1) * 32;
  const int r0 = lane >> 2, c0 = (lane & 3) * 2;

  auto slot_of = [&](int l) {
    return (l < 6)    ? 6 + ib * 6 + l
           : (l < 12) ? 30 + ib * 6 + (l - 6)
           : (l == 12) ? 54 + ib : 58 + ib;
  };

  stage_async(sbase, A + (size_t)rowBase * C, tid);
  stage_async(sbase + W_OFF, g_Wh + (size_t)slot_of(0) * CC, tid);
  CP_COMMIT();
  CP_WAIT(0);
  __syncthreads();

  FragIdx f = frag_idx(lane, wid);

#pragma unroll 1
  for (int l = 0; l < 14; ++l) {
    float acc[4][4][4];
    zero_acc(acc);
    mma_pass(sbase, sbase + W_OFF, f, acc);

    // stage Y tile to smem as fp16
#pragma unroll
    for (int mi = 0; mi < 4; ++mi)
#pragma unroll
      for (int ni = 0; ni < 4; ++ni) {
        int row = rw + mi * 16 + r0, col = cw + ni * 8 + c0;
        __half2 h0 = __floats2half2_rn(acc[mi][ni][0], acc[mi][ni][1]);
        __half2 h1 = __floats2half2_rn(acc[mi][ni][2], acc[mi][ni][3]);
        *(__half2*)(Ybuf + row * YPITCH_H + col) = h0;
        *(__half2*)(Ybuf + (row + 8) * YPITCH_H + col) = h1;
      }
    __syncthreads();  // Ybuf ready; W(l) fully consumed by all warps

    // prefetch W(l+1) into the (single) W buffer; lands during scatter
    if (l < 13) {
      stage_async(sbase + W_OFF, g_Wh + (size_t)slot_of(l + 1) * CC, tid);
      CP_COMMIT();
    }

    // scatter this tile's edges; warp per edge
    int ebase = (l < 12) ? l * E : 12 * E + (l - 12) * EL;
    int o0 = g_off[l * (NT + 1) + blockIdx.x];
    int o1 = g_off[l * (NT + 1) + blockIdx.x + 1];
#pragma unroll 2
    for (int j = o0 + wid; j < o1; j += 8) {
      int pk = g_epk[ebase + j];
      int vl = pk & 127;
      int uu = pk >> 7;
      uint2 hv = *(uint2*)(Ybuf + vl * YPITCH_H + lane * 4);
      float2 f0 = __half22float2(*(__half2*)&hv.x);
      float2 f1 = __half22float2(*(__half2*)&hv.y);
      float* p = TP + (size_t)uu * C + lane * 4;
      asm volatile("red.global.add.v4.f32 [%0], {%1,%2,%3,%4};"
                   :: "l"(p), "f"(f0.x), "f"(f0.y), "f"(f1.x), "f"(f1.y)
                   : "memory");
    }

    if (l < 13) CP_WAIT(0);
    __syncthreads();  // W(l+1) in smem; Ybuf free for rewrite
  }
}

// ---------------------------------------------------------------------------
// edge sort (counting sort by v>>7), once per launch
// ---------------------------------------------------------------------------
__global__ void zero_cnt_kernel() {
  int i = blockIdx.x * 256 + threadIdx.x;
  if (i < NL * NT) g_cnt[i] = 0;
}
__global__ void hist_kernel(const int* __restrict__ v, int nE, int l) {
  int e = blockIdx.x * 256 + threadIdx.x;
  if (e < nE) atomicAdd(&g_cnt[l * NT + (__ldg(&v[e]) >> 7)], 1);
}
__global__ void prefix_kernel() {  // one block per list, 1024 threads
  __shared__ int sh[NT];
  int l = blockIdx.x, t = threadIdx.x;
  sh[t] = g_cnt[l * NT + t];
  __syncthreads();
#pragma unroll
  for (int d = 1; d < NT; d <<= 1) {
    int x = (t >= d) ? sh[t - d] : 0;
    __syncthreads();
    sh[t] += x;
    __syncthreads();
  }
  g_off[l * (NT + 1) + t + 1] = sh[t];
  if (t == 0) g_off[l * (NT + 1)] = 0;
}
__global__ void fill_kernel(const int* __restrict__ u,
                            const int* __restrict__ v, int nE, int l,
                            int sbase) {
  int e = blockIdx.x * 256 + threadIdx.x;
  if (e >= nE) return;
  int vv = __ldg(&v[e]);
  int t = vv >> 7;
  int pos = sbase + g_off[l * (NT + 1) + t] + atomicAdd(&g_cnt[l * NT + t], 1);
  g_epk[pos] = (__ldg(&u[e]) << 7) | (vv & 127);
}

// ---------------------------------------------------------------------------
// fp16 conversion helpers / elementwise kernels
// ---------------------------------------------------------------------------
DEV_INLINE void h4_store(__half* H, size_t idx4, float4 o) {
  __half2 a = __floats2half2_rn(o.x, o.y);
  __half2 b = __floats2half2_rn(o.z, o.w);
  *(uint2*)(H + idx4) = make_uint2(*(uint32_t*)&a, *(uint32_t*)&b);
}

// Weight split + transpose: out[slot][c][k] = fp16split(src[m][k][c])
__global__ void wsplit_kernel(const float* __restrict__ src, int slotBase,
                              int nm) {
  int idx = blockIdx.x * 256 + threadIdx.x;
  int m = idx >> 14, r = idx & 16383;
  int c = r >> 7, k = r & 127;
  float w = src[(size_t)m * CC + k * 128 + c];
  __half hi = __float2half_rn(w);
  __half lo = __float2half_rn(w - __half2float(hi));
  size_t o = (size_t)(slotBase + m) * CC + r;
  g_Wh[o] = hi;
  g_Wl[o] = lo;
}

__global__ void mlp0_kernel(const float* __restrict__ X2,
                            const float* __restrict__ W0,
                            const float* __restrict__ B0,
                            __half* __restrict__ H) {
  int idx = blockIdx.x * 256 + threadIdx.x;  // N*64
  int n = idx >> 6, c = (idx & 63) << 1;
  float x0 = X2[2 * n], x1 = X2[2 * n + 1];
  float ha = fmaxf(fmaf(x0, W0[c], fmaf(x1, W0[C + c], B0[c])), 0.0f);
  float hb = fmaxf(fmaf(x0, W0[c + 1], fmaf(x1, W0[C + c + 1], B0[c + 1])), 0.0f);
  *(__half2*)(H + (size_t)n * C + c) = __floats2half2_rn(ha, hb);
}

DEV_INLINE float wsum(float v) {
#pragma unroll
  for (int o = 16; o > 0; o >>= 1) v += __shfl_xor_sync(0xffffffffu, v, o);
  return v;
}

__global__ void gn_relu_h_kernel(const float* __restrict__ X,
                                 const float* __restrict__ G,
                                 const float* __restrict__ Bt,
                                 __half* __restrict__ H) {
  int w = (blockIdx.x * blockDim.x + threadIdx.x) >> 5;
  int lane = threadIdx.x & 31;
  float4 x = ((const float4*)X)[(size_t)w * 32 + lane];
  float s = wsum(x.x + x.y + x.z + x.w);
  float q = wsum(x.x * x.x + x.y * x.y + x.z * x.z + x.w * x.w);
  float mu = s * (1.0f / 128.0f);
  float rs = rsqrtf(q * (1.0f / 128.0f) - mu * mu + 1e-5f);
  float4 g = ((const float4*)G)[lane];
  float4 b = ((const float4*)Bt)[lane];
  float4 o;
  o.x = fmaxf((x.x - mu) * rs * g.x + b.x, 0.0f);
  o.y = fmaxf((x.y - mu) * rs * g.y + b.y, 0.0f);
  o.z = fmaxf((x.z - mu) * rs * g.z + b.z, 0.0f);
  o.w = fmaxf((x.w - mu) * rs * g.w + b.w, 0.0f);
  h4_store(H, ((size_t)w * 32 + lane) * 4, o);
}

__global__ void gn_res_relu_kernel(const float* __restrict__ X,
                                   const float* __restrict__ G,
                                   const float* __restrict__ Bt,
                                   const float* __restrict__ Id,
                                   float* __restrict__ Of,
                                   __half* __restrict__ H) {
  int w = (blockIdx.x * blockDim.x + threadIdx.x) >> 5;
  int lane = threadIdx.x & 31;
  float4 x = ((const float4*)X)[(size_t)w * 32 + lane];
  float s = wsum(x.x + x.y + x.z + x.w);
  float q = wsum(x.x * x.x + x.y * x.y + x.z * x.z + x.w * x.w);
  float mu = s * (1.0f / 128.0f);
  float rs = rsqrtf(q * (1.0f / 128.0f) - mu * mu + 1e-5f);
  float4 g = ((const float4*)G)[lane];
  float4 b = ((const float4*)Bt)[lane];
  float4 id = ((const float4*)Id)[(size_t)w * 32 + lane];
  float4 o;
  o.x = fmaxf((x.x - mu) * rs * g.x + b.x + id.x, 0.0f);
  o.y = fmaxf((x.y - mu) * rs * g.y + b.y + id.y, 0.0f);
  o.z = fmaxf((x.z - mu) * rs * g.z + b.z + id.z, 0.0f);
  o.w = fmaxf((x.w - mu) * rs * g.w + b.w + id.w, 0.0f);
  ((float4*)Of)[(size_t)w * 32 + lane] = o;
  if (H) h4_store(H, ((size_t)w * 32 + lane) * 4, o);
}

__global__ void combine_kernel(const float* __restrict__ Y1,
                               const float* __restrict__ Y2,
                               const float* __restrict__ G1,
                               const float* __restrict__ B1,
                               const float* __restrict__ G2,
                               const float* __restrict__ B2,
                               float* __restrict__ Of,
                               __half* __restrict__ H) {
  int w = (blockIdx.x * blockDim.x + threadIdx.x) >> 5;
  int lane = threadIdx.x & 31;
  float4 x1 = ((const float4*)Y1)[(size_t)w * 32 + lane];
  float4 x2 = ((const float4*)Y2)[(size_t)w * 32 + lane];
  float s1 = wsum(x1.x + x1.y + x1.z + x1.w);
  float q1 = wsum(x1.x * x1.x + x1.y * x1.y + x1.z * x1.z + x1.w * x1.w);
  float s2 = wsum(x2.x + x2.y + x2.z + x2.w);
  float q2 = wsum(x2.x * x2.x + x2.y * x2.y + x2.z * x2.z + x2.w * x2.w);
  float mu1 = s1 * (1.0f / 128.0f);
  float rs1 = rsqrtf(q1 * (1.0f / 128.0f) - mu1 * mu1 + 1e-5f);
  float mu2 = s2 * (1.0f / 128.0f);
  float rs2 = rsqrtf(q2 * (1.0f / 128.0f) - mu2 * mu2 + 1e-5f);
  float4 g1 = ((const float4*)G1)[lane];
  float4 b1 = ((const float4*)B1)[lane];
  float4 g2 = ((const float4*)G2)[lane];
  float4 b2 = ((const float4*)B2)[lane];
  float4 o;
  o.x = fmaxf((x1.x - mu1) * rs1 * g1.x + b1.x + (x2.x - mu2) * rs2 * g2.x + b2.x, 0.0f);
  o.y = fmaxf((x1.y - mu1) * rs1 * g1.y + b1.y + (x2.y - mu2) * rs2 * g2.y + b2.y, 0.0f);
  o.z = fmaxf((x1.z - mu1) * rs1 * g1.z + b1.z + (x2.z - mu2) * rs2 * g2.z + b2.z, 0.0f);
  o.w = fmaxf((x1.w - mu1) * rs1 * g1.w + b1.w + (x2.w - mu2) * rs2 * g2.w + b2.w, 0.0f);
  ((float4*)Of)[(size_t)w * 32 + lane] = o;
  h4_store(H, ((size_t)w * 32 + lane) * 4, o);
}

// ---------------------------------------------------------------------------
extern "C" void kernel_launch(void* const* d_in, const int* in_sizes, int n_in,
                              void* d_out, int out_size) {
  const float* ctrs   = (const float*)d_in[0];
  const float* feats  = (const float*)d_in[1];
  const int*   pre_u  = (const int*)d_in[2];
  const int*   pre_v  = (const int*)d_in[3];
  const int*   suc_u  = (const int*)d_in[4];
  const int*   suc_v  = (const int*)d_in[5];
  const int*   left_u = (const int*)d_in[6];
  const int*   left_v = (const int*)d_in[7];
  const int*   right_u= (const int*)d_in[8];
  const int*   right_v= (const int*)d_in[9];
  const float* ic_w0  = (const float*)d_in[10];
  const float* ic_b0  = (const float*)d_in[11];
  const float* ic_w1  = (const float*)d_in[12];
  const float* ic_g   = (const float*)d_in[13];
  const float* ic_bt  = (const float*)d_in[14];
  const float* if_w0  = (const float*)d_in[15];
  const float* if_b0  = (const float*)d_in[16];
  const float* if_w1  = (const float*)d_in[17];
  const float* if_g   = (const float*)d_in[18];
  const float* if_bt  = (const float*)d_in[19];
  const float* ctr_w  = (const float*)d_in[20];
  const float* pre_w  = (const float*)d_in[21];
  const float* suc_w  = (const float*)d_in[22];
  const float* left_w = (const float*)d_in[23];
  const float* right_w= (const float*)d_in[24];
  const float* norm_g = (const float*)d_in[25];
  const float* norm_b = (const float*)d_in[26];
  const float* ctr2_w = (const float*)d_in[27];
  const float* ctr2_g = (const float*)d_in[28];
  const float* ctr2_b = (const float*)d_in[29];
  float* out = (float*)d_out;

  float *FT, *TP, *YB;
  __half *AA, *WH, *WL;
  cudaGetSymbolAddress((void**)&FT, g_feat);
  cudaGetSymbolAddress((void**)&TP, g_temp);
  cudaGetSymbolAddress((void**)&YB, g_Y);
  cudaGetSymbolAddress((void**)&AA, g_A);
  cudaGetSymbolAddress((void**)&WH, g_Wh);
  cudaGetSymbolAddress((void**)&WL, g_Wl);

  cudaFuncSetAttribute(gemm_mma, cudaFuncAttributeMaxDynamicSharedMemorySize,
                       SMEM_MMA_BYTES);
  cudaFuncSetAttribute(gemm_mma1, cudaFuncAttributeMaxDynamicSharedMemorySize,
                       2 * TILE_BYTES);
  cudaFuncSetAttribute(fused_block_kernel,
                       cudaFuncAttributeMaxDynamicSharedMemorySize, SMEM_FUSED);

  const int GEMM_GRID = N / 128;
  const int ROW_GRID  = N / 8;
  const int MLP_GRID  = (N * 64) / 256;
  const int ZG = (NL * NT + 255) / 256;
  const int HG = (E + 255) / 256, HGS = (EL + 255) / 256;

  // ---- weight split + transpose ----
  wsplit_kernel<<<1 * 64, 256>>>(ic_w1, 0, 1);
  wsplit_kernel<<<1 * 64, 256>>>(if_w1, 1, 1);
  wsplit_kernel<<<4 * 64, 256>>>(ctr_w, 2, 4);
  wsplit_kernel<<<24 * 64, 256>>>(pre_w, 6, 24);
  wsplit_kernel<<<24 * 64, 256>>>(suc_w, 30, 24);
  wsplit_kernel<<<4 * 64, 256>>>(left_w, 54, 4);
  wsplit_kernel<<<4 * 64, 256>>>(right_w, 58, 4);
  wsplit_kernel<<<4 * 64, 256>>>(ctr2_w, 62, 4);

  // ---- edge sort by source tile (once; reused by all 4 blocks) ----
  zero_cnt_kernel<<<ZG, 256>>>();
  for (int s = 0; s < S; ++s) {
    hist_kernel<<<HG, 256>>>(pre_v + (size_t)s * E, E, s);
    hist_kernel<<<HG, 256>>>(suc_v + (size_t)s * E, E, 6 + s);
  }
  hist_kernel<<<HGS, 256>>>(left_v, EL, 12);
  hist_kernel<<<HGS, 256>>>(right_v, EL, 13);
  prefix_kernel<<<NL, NT>>>();
  zero_cnt_kernel<<<ZG, 256>>>();
  for (int s = 0; s < S; ++s) {
    fill_kernel<<<HG, 256>>>(pre_u + (size_t)s * E, pre_v + (size_t)s * E, E,
                             s, s * E);
    fill_kernel<<<HG, 256>>>(suc_u + (size_t)s * E, suc_v + (size_t)s * E, E,
                             6 + s, (6 + s) * E);
  }
  fill_kernel<<<HGS, 256>>>(left_u, left_v, EL, 12, 12 * E);
  fill_kernel<<<HGS, 256>>>(right_u, right_v, EL, 13, 12 * E + EL);

#define GEMM2(slot, OutPtr)                                                  \
  gemm_mma<<<GEMM_GRID, 256, SMEM_MMA_BYTES>>>(                              \
      AA, WH + (size_t)(slot) * CC, WL + (size_t)(slot) * CC, OutPtr)
#define GEMM1(slot, OutPtr)                                                  \
  gemm_mma1<<<GEMM_GRID, 256, 2 * TILE_BYTES>>>(                             \
      AA, WH + (size_t)(slot) * CC, OutPtr)

  // ---- Input stage ----
  mlp0_kernel<<<MLP_GRID, 256>>>(ctrs, ic_w0, ic_b0, AA);
  GEMM2(0, FT);
  mlp0_kernel<<<MLP_GRID, 256>>>(feats, if_w0, if_b0, AA);
  GEMM2(1, YB);
  combine_kernel<<<ROW_GRID, 256>>>(FT, YB, ic_g, ic_bt, if_g, if_bt, FT, AA);

  // ---- 4 fusion blocks ----
  for (int i = 0; i < NB; ++i) {
    GEMM1(2 + i, TP);  // temp = feat @ ctr_w[i] (direct store precedes atomics)
    fused_block_kernel<<<GEMM_GRID, 256, SMEM_FUSED>>>(AA, i, TP);

    gn_relu_h_kernel<<<ROW_GRID, 256>>>(TP, norm_g + (size_t)i * C,
                                        norm_b + (size_t)i * C, AA);
    GEMM2(62 + i, TP);  // Y2 = feat_mid @ ctr2_w[i]

    if (i == NB - 1) {
      gn_res_relu_kernel<<<ROW_GRID, 256>>>(TP, ctr2_g + (size_t)i * C,
                                            ctr2_b + (size_t)i * C, FT, out,
                                            nullptr);
    } else {
      gn_res_relu_kernel<<<ROW_GRID, 256>>>(TP, ctr2_g + (size_t)i * C,
                                            ctr2_b + (size_t)i * C, FT, FT,
                                            AA);
    }
  }
#undef GEMM2
#undef GEMM1
}

// round 10
// speedup vs baseline: 2.5566x; 1.3165x over previous
#include <cuda_runtime.h>
#include <cuda_fp16.h>
#include <cstdint>

#define DEV_INLINE __device__ __forceinline__

constexpr int N  = 131072;
constexpr int C  = 128;
constexpr int S  = 6;
constexpr int E  = 131072;
constexpr int EL = 32768;
constexpr int NB = 4;
constexpr int CC = C * C;
constexpr int NSLOT = 66;
constexpr int NT = 1024;   // source row tiles (N/128)
constexpr int NL = 14;     // edge lists: 0-5 pre, 6-11 suc, 12 left, 13 right
constexpr int ESTORE = 12 * E + 2 * EL;
constexpr int IDX_CAP = 512;   // smem-resident edges per (tile, list); gmem fallback beyond

// Scratch (allocation-free rule: static __device__ arrays)
__device__ float  g_feat[N * C];
__device__ float  g_temp[N * C];
__device__ float  g_Y[N * C];
__device__ __half g_A[N * C];           // fp16 activations
__device__ __half g_Wh[NSLOT * CC];     // fp16 weight hi, [slot][c][k] (transposed)
__device__ __half g_Wl[NSLOT * CC];     // fp16 weight lo (residual; main path only)
// edge sort scratch
__device__ int g_cnt[NL * NT];
__device__ int g_off[NL * (NT + 1)];
__device__ int g_epk[ESTORE];  // packed edge: (u << 7) | (v & 127)

DEV_INLINE uint32_t smem_u32(const void* p) {
  uint32_t a;
  asm("{ .reg .u64 t; cvta.to.shared.u64 t, %1; cvt.u32.u64 %0, t; }"
      : "=r"(a) : "l"(p));
  return a;
}

// ---------------------------------------------------------------------------
// MMA building blocks. smem tile: 128 rows x 256B, XOR-16B swizzle on (row&7)
// ---------------------------------------------------------------------------
constexpr int TILE_BYTES = 128 * 256;  // 32 KB (128x128 fp16)

DEV_INLINE void ldsm4(uint32_t& r0, uint32_t& r1, uint32_t& r2, uint32_t& r3,
                      uint32_t addr) {
  asm volatile("ldmatrix.sync.aligned.m8n8.x4.shared.b16 {%0,%1,%2,%3}, [%4];"
               : "=r"(r0), "=r"(r1), "=r"(r2), "=r"(r3) : "r"(addr));
}
DEV_INLINE void mma_f16(float* c, uint32_t a0, uint32_t a1, uint32_t a2,
                        uint32_t a3, uint32_t b0, uint32_t b1) {
  asm volatile(
      "mma.sync.aligned.m16n8k16.row.col.f32.f16.f16.f32 "
      "{%0,%1,%2,%3}, {%4,%5,%6,%7}, {%8,%9}, {%0,%1,%2,%3};"
      : "+f"(c[0]), "+f"(c[1]), "+f"(c[2]), "+f"(c[3])
      : "r"(a0), "r"(a1), "r"(a2), "r"(a3), "r"(b0), "r"(b1));
}

DEV_INLINE void cp_async16(uint32_t dst, const void* src) {
  asm volatile("cp.async.cg.shared.global [%0], [%1], 16;" :: "r"(dst),
               "l"(src));
}
DEV_INLINE void cp_async4(uint32_t dst, const void* src) {
  asm volatile("cp.async.ca.shared.global [%0], [%1], 4;" :: "r"(dst),
               "l"(src));
}
#define CP_COMMIT() asm volatile("cp.async.commit_group;" ::: "memory")
#define CP_WAIT(n)  asm volatile("cp.async.wait_group %0;" :: "n"(n) : "memory")

// stage one 128x128 fp16 tile (32 KB) with swizzle via cp.async; 256 threads
DEV_INLINE void stage_async(uint32_t dstBase, const __half* src, int tid) {
  const char* s = (const char*)src;
#pragma unroll
  for (int t = 0; t < 8; ++t) {
    int idx = tid + t * 256;
    int r = idx >> 4, c16 = idx & 15;
    uint32_t off = r * 256 + ((c16 * 16) ^ ((r & 7) << 4));
    cp_async16(dstBase + off, s + idx * 16);
  }
}

// fragment address precompute
struct FragIdx {
  uint32_t aRow[4], aColK, bRow[2], bColK;
  int rw, cw;
};
DEV_INLINE FragIdx frag_idx(int lane, int wid) {
  FragIdx f;
  f.rw = (wid & 1) * 64;
  f.cw = (wid >> 1) * 32;
  f.aColK = (lane >> 4) * 16;
#pragma unroll
  for (int mi = 0; mi < 4; ++mi) f.aRow[mi] = f.rw + mi * 16 + (lane & 15);
  f.bColK = ((lane >> 3) & 1) * 16;
#pragma unroll
  for (int bi = 0; bi < 2; ++bi)
    f.bRow[bi] = f.cw + bi * 16 + ((lane >> 4) * 8) + (lane & 7);
  return f;
}

DEV_INLINE void zero_acc(float (&acc)[4][4][4]) {
#pragma unroll
  for (int mi = 0; mi < 4; ++mi)
#pragma unroll
    for (int ni = 0; ni < 4; ++ni)
#pragma unroll
      for (int j = 0; j < 4; ++j) acc[mi][ni][j] = 0.0f;
}

// one K-sweep (8 chunks) of A@B accumulated
DEV_INLINE void mma_pass(uint32_t aBase, uint32_t bBase, const FragIdx& f,
                         float (&acc)[4][4][4]) {
#pragma unroll
  for (int kk = 0; kk < 8; ++kk) {
    const uint32_t kb = kk * 32;
    uint32_t a[4][4];
#pragma unroll
    for (int mi = 0; mi < 4; ++mi) {
      uint32_t r = f.aRow[mi];
      uint32_t addr = aBase + r * 256 + ((kb | f.aColK) ^ ((r & 7) << 4));
      ldsm4(a[mi][0], a[mi][1], a[mi][2], a[mi][3], addr);
    }
    uint32_t b[4][2];
#pragma unroll
    for (int bi = 0; bi < 2; ++bi) {
      uint32_t r = f.bRow[bi];
      uint32_t addr = bBase + r * 256 + ((kb | f.bColK) ^ ((r & 7) << 4));
      ldsm4(b[bi * 2][0], b[bi * 2][1], b[bi * 2 + 1][0], b[bi * 2 + 1][1],
            addr);
    }
#pragma unroll
    for (int mi = 0; mi < 4; ++mi)
#pragma unroll
      for (int ni = 0; ni < 4; ++ni)
        mma_f16(acc[mi][ni], a[mi][0], a[mi][1], a[mi][2], a[mi][3],
                b[ni][0], b[ni][1]);
  }
}

DEV_INLINE void store_acc_global(float* Out, int rowBase, int lane, int wid,
                                 float (&acc)[4][4][4]) {
  const int rw = (wid & 1) * 64, cw = (wid >> 1) * 32;
  const int r0 = lane >> 2, c0 = (lane & 3) * 2;
#pragma unroll
  for (int mi = 0; mi < 4; ++mi)
#pragma unroll
    for (int ni = 0; ni < 4; ++ni) {
      int grow = rowBase + rw + mi * 16 + r0;
      int gcol = cw + ni * 8 + c0;
      *(float2*)(Out + (size_t)grow * C + gcol) =
          make_float2(acc[mi][ni][0], acc[mi][ni][1]);
      *(float2*)(Out + (size_t)(grow + 8) * C + gcol) =
          make_float2(acc[mi][ni][2], acc[mi][ni][3]);
    }
}

// ---------------------------------------------------------------------------
// standalone GEMM (main path, 2-pass): Out = A@(Wh+Wl)^T. 96 KB -> 2 CTA/SM.
// ---------------------------------------------------------------------------
constexpr int SMEM_MMA_BYTES = 3 * TILE_BYTES;  // 96 KB

__global__ void __launch_bounds__(256, 2) gemm_mma(
    const __half* __restrict__ A, const __half* __restrict__ Bh,
    const __half* __restrict__ Bl, float* __restrict__ Out) {
  extern __shared__ __align__(16) char smem[];
  const uint32_t sbase = smem_u32(smem);
  const int tid = threadIdx.x, lane = tid & 31, wid = tid >> 5;
  const int rowBase = blockIdx.x * 128;

  stage_async(sbase, A + (size_t)rowBase * C, tid);
  stage_async(sbase + TILE_BYTES, Bh, tid);
  stage_async(sbase + 2 * TILE_BYTES, Bl, tid);
  CP_COMMIT();
  CP_WAIT(0);
  __syncthreads();

  FragIdx f = frag_idx(lane, wid);
  float acc[4][4][4];
  zero_acc(acc);
  mma_pass(sbase, sbase + TILE_BYTES, f, acc);
  mma_pass(sbase, sbase + 2 * TILE_BYTES, f, acc);
  store_acc_global(Out, rowBase, lane, wid, acc);
}

// ---------------------------------------------------------------------------
// fused per-block kernel: ctr GEMM (it=0, own-row red.add into zeroed TP)
// + 14 edge-GEMMs (single-pass fp16 W) + smem scatter with smem-resident
// edge indices (cp.async prefetched, double-buffered).
// smem: A(32K) + W(32K) + Ybuf fp16(34816) + idx 2x2KB = 104448 -> 2 CTA/SM
// ---------------------------------------------------------------------------
constexpr int YPITCH_H = 136;
constexpr int W_OFF   = TILE_BYTES;       // 32768
constexpr int Y_OFF   = 2 * TILE_BYTES;   // 65536
constexpr int IDX_OFF = Y_OFF + 128 * YPITCH_H * 2;      // 100352
constexpr int SMEM_FUSED = IDX_OFF + 2 * IDX_CAP * 4;    // 104448

__global__ void __launch_bounds__(256, 2) fused_block_kernel(
    const __half* __restrict__ A, int ib, float* __restrict__ TP) {
  extern __shared__ __align__(16) char smem[];
  const uint32_t sbase = smem_u32(smem);
  __half* Ybuf = (__half*)(smem + Y_OFF);
  const int tid = threadIdx.x, lane = tid & 31, wid = tid >> 5;
  const int rowBase = blockIdx.x * 128;

  const int rw = (wid & 1) * 64, cw = (wid >> 1) * 32;
  const int r0 = lane >> 2, c0 = (lane & 3) * 2;

  // it=0: ctr. it 1..6: pre scales. it 7..12: suc scales. 13: left. 14: right.
  auto slot_of = [&](int it) {
    return (it == 0)   ? 2 + ib
           : (it < 7)  ? 6 + ib * 6 + (it - 1)
           : (it < 13) ? 30 + ib * 6 + (it - 7)
           : (it == 13) ? 54 + ib : 58 + ib;
  };
  // edge-list base in g_epk for iteration it>=1 (list l = it-1)
  auto ebase_of = [&](int it) {
    int l = it - 1;
    return (l < 12) ? l * E : 12 * E + (l - 12) * EL;
  };

  // stage indices for iteration it (list it-1) into idx buffer (it&1)
  auto stage_idx = [&](int it) {
    int l = it - 1;
    int o0 = g_off[l * (NT + 1) + blockIdx.x];
    int o1 = g_off[l * (NT + 1) + blockIdx.x + 1];
    int cnt = min(o1 - o0, IDX_CAP);
    const int* src = g_epk + ebase_of(it) + o0;
    uint32_t dst = sbase + IDX_OFF + (it & 1) * (IDX_CAP * 4);
    for (int j = tid; j < cnt; j += 256) cp_async4(dst + j * 4, src + j);
  };

  stage_async(sbase, A + (size_t)rowBase * C, tid);
  stage_async(sbase + W_OFF, g_Wh + (size_t)slot_of(0) * CC, tid);
  stage_idx(1);
  CP_COMMIT();
  CP_WAIT(0);
  __syncthreads();

  FragIdx f = frag_idx(lane, wid);

#pragma unroll 1
  for (int it = 0; it < 15; ++it) {
    float acc[4][4][4];
    zero_acc(acc);
    mma_pass(sbase, sbase + W_OFF, f, acc);

    // stage Y tile to smem as fp16
#pragma unroll
    for (int mi = 0; mi < 4; ++mi)
#pragma unroll
      for (int ni = 0; ni < 4; ++ni) {
        int row = rw + mi * 16 + r0, col = cw + ni * 8 + c0;
        __half2 h0 = __floats2half2_rn(acc[mi][ni][0], acc[mi][ni][1]);
        __half2 h1 = __floats2half2_rn(acc[mi][ni][2], acc[mi][ni][3]);
        *(__half2*)(Ybuf + row * YPITCH_H + col) = h0;
        *(__half2*)(Ybuf + (row + 8) * YPITCH_H + col) = h1;
      }
    __syncthreads();  // Ybuf ready; W(it) fully consumed

    // prefetch W(it+1) and idx(it+1); lands during the scatter below
    if (it < 14) {
      stage_async(sbase + W_OFF, g_Wh + (size_t)slot_of(it + 1) * CC, tid);
      if (it + 1 >= 1 && it + 1 <= 14) stage_idx(it + 1);
      CP_COMMIT();
    }

    if (it == 0) {
      // ctr: add own 128 rows into (pre-zeroed) TP
      for (int r = wid; r < 128; r += 8) {
        uint2 hv = *(uint2*)(Ybuf + r * YPITCH_H + lane * 4);
        float2 f0 = __half22float2(*(__half2*)&hv.x);
        float2 f1 = __half22float2(*(__half2*)&hv.y);
        float* p = TP + (size_t)(rowBase + r) * C + lane * 4;
        asm volatile("red.global.add.v4.f32 [%0], {%1,%2,%3,%4};"
                     :: "l"(p), "f"(f0.x), "f"(f0.y), "f"(f1.x), "f"(f1.y)
                     : "memory");
      }
    } else {
      int l = it - 1;
      int o0 = g_off[l * (NT + 1) + blockIdx.x];
      int o1 = g_off[l * (NT + 1) + blockIdx.x + 1];
      int cnt = o1 - o0;
      const int* sidx = (const int*)(smem + IDX_OFF + (it & 1) * (IDX_CAP * 4));
      const int* gidx = g_epk + ebase_of(it) + o0;
#pragma unroll 2
      for (int j = wid; j < cnt; j += 8) {
        int pk = (j < IDX_CAP) ? sidx[j] : __ldg(&gidx[j]);
        int vl = pk & 127;
        int uu = pk >> 7;
        uint2 hv = *(uint2*)(Ybuf + vl * YPITCH_H + lane * 4);
        float2 f0 = __half22float2(*(__half2*)&hv.x);
        float2 f1 = __half22float2(*(__half2*)&hv.y);
        float* p = TP + (size_t)uu * C + lane * 4;
        asm volatile("red.global.add.v4.f32 [%0], {%1,%2,%3,%4};"
                     :: "l"(p), "f"(f0.x), "f"(f0.y), "f"(f1.x), "f"(f1.y)
                     : "memory");
      }
    }

    if (it < 14) CP_WAIT(0);
    __syncthreads();  // W(it+1)+idx in smem; Ybuf free for rewrite
  }
}

// ---------------------------------------------------------------------------
// edge sort (counting sort by v>>7), once per launch
// ---------------------------------------------------------------------------
__global__ void zero_cnt_kernel() {
  int i = blockIdx.x * 256 + threadIdx.x;
  if (i < NL * NT) g_cnt[i] = 0;
}
__global__ void hist_kernel(const int* __restrict__ v, int nE, int l) {
  int e = blockIdx.x * 256 + threadIdx.x;
  if (e < nE) atomicAdd(&g_cnt[l * NT + (__ldg(&v[e]) >> 7)], 1);
}
__global__ void prefix_kernel() {  // one block per list, 1024 threads
  __shared__ int sh[NT];
  int l = blockIdx.x, t = threadIdx.x;
  sh[t] = g_cnt[l * NT + t];
  __syncthreads();
#pragma unroll
  for (int d = 1; d < NT; d <<= 1) {
    int x = (t >= d) ? sh[t - d] : 0;
    __syncthreads();
    sh[t] += x;
    __syncthreads();
  }
  g_off[l * (NT + 1) + t + 1] = sh[t];
  if (t == 0) g_off[l * (NT + 1)] = 0;
}
__global__ void fill_kernel(const int* __restrict__ u,
                            const int* __restrict__ v, int nE, int l,
                            int sbase) {
  int e = blockIdx.x * 256 + threadIdx.x;
  if (e >= nE) return;
  int vv = __ldg(&v[e]);
  int t = vv >> 7;
  int pos = sbase + g_off[l * (NT + 1) + t] + atomicAdd(&g_cnt[l * NT + t], 1);
  g_epk[pos] = (__ldg(&u[e]) << 7) | (vv & 127);
}

// ---------------------------------------------------------------------------
// fp16 conversion helpers / elementwise kernels
// ---------------------------------------------------------------------------
DEV_INLINE void h4_store(__half* H, size_t idx4, float4 o) {
  __half2 a = __floats2half2_rn(o.x, o.y);
  __half2 b = __floats2half2_rn(o.z, o.w);
  *(uint2*)(H + idx4) = make_uint2(*(uint32_t*)&a, *(uint32_t*)&b);
}

// Weight split + transpose: out[slot][c][k] = fp16split(src[m][k][c])
__global__ void wsplit_kernel(const float* __restrict__ src, int slotBase,
                              int nm) {
  int idx = blockIdx.x * 256 + threadIdx.x;
  int m = idx >> 14, r = idx & 16383;
  int c = r >> 7, k = r & 127;
  float w = src[(size_t)m * CC + k * 128 + c];
  __half hi = __float2half_rn(w);
  __half lo = __float2half_rn(w - __half2float(hi));
  size_t o = (size_t)(slotBase + m) * CC + r;
  g_Wh[o] = hi;
  g_Wl[o] = lo;
}

__global__ void mlp0_kernel(const float* __restrict__ X2,
                            const float* __restrict__ W0,
                            const float* __restrict__ B0,
                            __half* __restrict__ H) {
  int idx = blockIdx.x * 256 + threadIdx.x;  // N*64
  int n = idx >> 6, c = (idx & 63) << 1;
  float x0 = X2[2 * n], x1 = X2[2 * n + 1];
  float ha = fmaxf(fmaf(x0, W0[c], fmaf(x1, W0[C + c], B0[c])), 0.0f);
  float hb = fmaxf(fmaf(x0, W0[c + 1], fmaf(x1, W0[C + c + 1], B0[c + 1])), 0.0f);
  *(__half2*)(H + (size_t)n * C + c) = __floats2half2_rn(ha, hb);
}

DEV_INLINE float wsum(float v) {
#pragma unroll
  for (int o = 16; o > 0; o >>= 1) v += __shfl_xor_sync(0xffffffffu, v, o);
  return v;
}

__global__ void gn_relu_h_kernel(const float* __restrict__ X,
                                 const float* __restrict__ G,
                                 const float* __restrict__ Bt,
                                 __half* __restrict__ H) {
  int w = (blockIdx.x * blockDim.x + threadIdx.x) >> 5;
  int lane = threadIdx.x & 31;
  float4 x = ((const float4*)X)[(size_t)w * 32 + lane];
  float s = wsum(x.x + x.y + x.z + x.w);
  float q = wsum(x.x * x.x + x.y * x.y + x.z * x.z + x.w * x.w);
  float mu = s * (1.0f / 128.0f);
  float rs = rsqrtf(q * (1.0f / 128.0f) - mu * mu + 1e-5f);
  float4 g = ((const float4*)G)[lane];
  float4 b = ((const float4*)Bt)[lane];
  float4 o;
  o.x = fmaxf((x.x - mu) * rs * g.x + b.x, 0.0f);
  o.y = fmaxf((x.y - mu) * rs * g.y + b.y, 0.0f);
  o.z = fmaxf((x.z - mu) * rs * g.z + b.z, 0.0f);
  o.w = fmaxf((x.w - mu) * rs * g.w + b.w, 0.0f);
  h4_store(H, ((size_t)w * 32 + lane) * 4, o);
}

// feat = relu(GN(X)+Id); also zeroes TPz (next block's accumulator) if given
__global__ void gn_res_relu_kernel(const float* __restrict__ X,
                                   const float* __restrict__ G,
                                   const float* __restrict__ Bt,
                                   const float* __restrict__ Id,
                                   float* __restrict__ Of,
                                   __half* __restrict__ H,
                                   float* __restrict__ TPz) {
  int w = (blockIdx.x * blockDim.x + threadIdx.x) >> 5;
  int lane = threadIdx.x & 31;
  size_t idx = (size_t)w * 32 + lane;
  float4 x = ((const float4*)X)[idx];
  float s = wsum(x.x + x.y + x.z + x.w);
  float q = wsum(x.x * x.x + x.y * x.y + x.z * x.z + x.w * x.w);
  float mu = s * (1.0f / 128.0f);
  float rs = rsqrtf(q * (1.0f / 128.0f) - mu * mu + 1e-5f);
  float4 g = ((const float4*)G)[lane];
  float4 b = ((const float4*)Bt)[lane];
  float4 id = ((const float4*)Id)[idx];
  float4 o;
  o.x = fmaxf((x.x - mu) * rs * g.x + b.x + id.x, 0.0f);
  o.y = fmaxf((x.y - mu) * rs * g.y + b.y + id.y, 0.0f);
  o.z = fmaxf((x.z - mu) * rs * g.z + b.z + id.z, 0.0f);
  o.w = fmaxf((x.w - mu) * rs * g.w + b.w + id.w, 0.0f);
  ((float4*)Of)[idx] = o;
  if (H) h4_store(H, idx * 4, o);
  if (TPz) ((float4*)TPz)[idx] = make_float4(0.f, 0.f, 0.f, 0.f);
}

// feat = relu(GN(Y1)+GN(Y2)); also zeroes TPz (block 0 accumulator)
__global__ void combine_kernel(const float* __restrict__ Y1,
                               const float* __restrict__ Y2,
                               const float* __restrict__ G1,
                               const float* __restrict__ B1,
                               const float* __restrict__ G2,
                               const float* __restrict__ B2,
                               float* __restrict__ Of,
                               __half* __restrict__ H,
                               float* __restrict__ TPz) {
  int w = (blockIdx.x * blockDim.x + threadIdx.x) >> 5;
  int lane = threadIdx.x & 31;
  size_t idx = (size_t)w * 32 + lane;
  float4 x1 = ((const float4*)Y1)[idx];
  float4 x2 = ((const float4*)Y2)[idx];
  float s1 = wsum(x1.x + x1.y + x1.z + x1.w);
  float q1 = wsum(x1.x * x1.x + x1.y * x1.y + x1.z * x1.z + x1.w * x1.w);
  float s2 = wsum(x2.x + x2.y + x2.z + x2.w);
  float q2 = wsum(x2.x * x2.x + x2.y * x2.y + x2.z * x2.z + x2.w * x2.w);
  float mu1 = s1 * (1.0f / 128.0f);
  float rs1 = rsqrtf(q1 * (1.0f / 128.0f) - mu1 * mu1 + 1e-5f);
  float mu2 = s2 * (1.0f / 128.0f);
  float rs2 = rsqrtf(q2 * (1.0f / 128.0f) - mu2 * mu2 + 1e-5f);
  float4 g1 = ((const float4*)G1)[lane];
  float4 b1 = ((const float4*)B1)[lane];
  float4 g2 = ((const float4*)G2)[lane];
  float4 b2 = ((const float4*)B2)[lane];
  float4 o;
  o.x = fmaxf((x1.x - mu1) * rs1 * g1.x + b1.x + (x2.x - mu2) * rs2 * g2.x + b2.x, 0.0f);
  o.y = fmaxf((x1.y - mu1) * rs1 * g1.y + b1.y + (x2.y - mu2) * rs2 * g2.y + b2.y, 0.0f);
  o.z = fmaxf((x1.z - mu1) * rs1 * g1.z + b1.z + (x2.z - mu2) * rs2 * g2.z + b2.z, 0.0f);
  o.w = fmaxf((x1.w - mu1) * rs1 * g1.w + b1.w + (x2.w - mu2) * rs2 * g2.w + b2.w, 0.0f);
  ((float4*)Of)[idx] = o;
  h4_store(H, idx * 4, o);
  ((float4*)TPz)[idx] = make_float4(0.f, 0.f, 0.f, 0.f);
}

// ---------------------------------------------------------------------------
extern "C" void kernel_launch(void* const* d_in, const int* in_sizes, int n_in,
                              void* d_out, int out_size) {
  const float* ctrs   = (const float*)d_in[0];
  const float* feats  = (const float*)d_in[1];
  const int*   pre_u  = (const int*)d_in[2];
  const int*   pre_v  = (const int*)d_in[3];
  const int*   suc_u  = (const int*)d_in[4];
  const int*   suc_v  = (const int*)d_in[5];
  const int*   left_u = (const int*)d_in[6];
  const int*   left_v = (const int*)d_in[7];
  const int*   right_u= (const int*)d_in[8];
  const int*   right_v= (const int*)d_in[9];
  const float* ic_w0  = (const float*)d_in[10];
  const float* ic_b0  = (const float*)d_in[11];
  const float* ic_w1  = (const float*)d_in[12];
  const float* ic_g   = (const float*)d_in[13];
  const float* ic_bt  = (const float*)d_in[14];
  const float* if_w0  = (const float*)d_in[15];
  const float* if_b0  = (const float*)d_in[16];
  const float* if_w1  = (const float*)d_in[17];
  const float* if_g   = (const float*)d_in[18];
  const float* if_bt  = (const float*)d_in[19];
  const float* ctr_w  = (const float*)d_in[20];
  const float* pre_w  = (const float*)d_in[21];
  const float* suc_w  = (const float*)d_in[22];
  const float* left_w = (const float*)d_in[23];
  const float* right_w= (const float*)d_in[24];
  const float* norm_g = (const float*)d_in[25];
  const float* norm_b = (const float*)d_in[26];
  const float* ctr2_w = (const float*)d_in[27];
  const float* ctr2_g = (const float*)d_in[28];
  const float* ctr2_b = (const float*)d_in[29];
  float* out = (float*)d_out;

  float *FT, *TP, *YB;
  __half *AA, *WH, *WL;
  cudaGetSymbolAddress((void**)&FT, g_feat);
  cudaGetSymbolAddress((void**)&TP, g_temp);
  cudaGetSymbolAddress((void**)&YB, g_Y);
  cudaGetSymbolAddress((void**)&AA, g_A);
  cudaGetSymbolAddress((void**)&WH, g_Wh);
  cudaGetSymbolAddress((void**)&WL, g_Wl);

  cudaFuncSetAttribute(gemm_mma, cudaFuncAttributeMaxDynamicSharedMemorySize,
                       SMEM_MMA_BYTES);
  cudaFuncSetAttribute(fused_block_kernel,
                       cudaFuncAttributeMaxDynamicSharedMemorySize, SMEM_FUSED);

  const int GEMM_GRID = N / 128;
  const int ROW_GRID  = N / 8;
  const int MLP_GRID  = (N * 64) / 256;
  const int ZG = (NL * NT + 255) / 256;
  const int HG = (E + 255) / 256, HGS = (EL + 255) / 256;

  // ---- weight split + transpose ----
  wsplit_kernel<<<1 * 64, 256>>>(ic_w1, 0, 1);
  wsplit_kernel<<<1 * 64, 256>>>(if_w1, 1, 1);
  wsplit_kernel<<<4 * 64, 256>>>(ctr_w, 2, 4);
  wsplit_kernel<<<24 * 64, 256>>>(pre_w, 6, 24);
  wsplit_kernel<<<24 * 64, 256>>>(suc_w, 30, 24);
  wsplit_kernel<<<4 * 64, 256>>>(left_w, 54, 4);
  wsplit_kernel<<<4 * 64, 256>>>(right_w, 58, 4);
  wsplit_kernel<<<4 * 64, 256>>>(ctr2_w, 62, 4);

  // ---- edge sort by source tile (once; reused by all 4 blocks) ----
  zero_cnt_kernel<<<ZG, 256>>>();
  for (int s = 0; s < S; ++s) {
    hist_kernel<<<HG, 256>>>(pre_v + (size_t)s * E, E, s);
    hist_kernel<<<HG, 256>>>(suc_v + (size_t)s * E, E, 6 + s);
  }
  hist_kernel<<<HGS, 256>>>(left_v, EL, 12);
  hist_kernel<<<HGS, 256>>>(right_v, EL, 13);
  prefix_kernel<<<NL, NT>>>();
  zero_cnt_kernel<<<ZG, 256>>>();
  for (int s = 0; s < S; ++s) {
    fill_kernel<<<HG, 256>>>(pre_u + (size_t)s * E, pre_v + (size_t)s * E, E,
                             s, s * E);
    fill_kernel<<<HG, 256>>>(suc_u + (size_t)s * E, suc_v + (size_t)s * E, E,
                             6 + s, (6 + s) * E);
  }
  fill_kernel<<<HGS, 256>>>(left_u, left_v, EL, 12, 12 * E);
  fill_kernel<<<HGS, 256>>>(right_u, right_v, EL, 13, 12 * E + EL);

#define GEMM2(slot, OutPtr)                                                  \
  gemm_mma<<<GEMM_GRID, 256, SMEM_MMA_BYTES>>>(                              \
      AA, WH + (size_t)(slot) * CC, WL + (size_t)(slot) * CC, OutPtr)

  // ---- Input stage ----
  mlp0_kernel<<<MLP_GRID, 256>>>(ctrs, ic_w0, ic_b0, AA);
  GEMM2(0, FT);
  mlp0_kernel<<<MLP_GRID, 256>>>(feats, if_w0, if_b0, AA);
  GEMM2(1, YB);
  // feat + split + zero TP for block 0
  combine_kernel<<<ROW_GRID, 256>>>(FT, YB, ic_g, ic_bt, if_g, if_bt, FT, AA,
                                    TP);

  // ---- 4 fusion blocks ----
  for (int i = 0; i < NB; ++i) {
    // ctr + 14 edge lists, all fused (TP pre-zeroed)
    fused_block_kernel<<<GEMM_GRID, 256, SMEM_FUSED>>>(AA, i, TP);

    gn_relu_h_kernel<<<ROW_GRID, 256>>>(TP, norm_g + (size_t)i * C,
                                        norm_b + (size_t)i * C, AA);
    GEMM2(62 + i, TP);  // Y2 = feat_mid @ ctr2_w[i]

    if (i == NB - 1) {
      gn_res_relu_kernel<<<ROW_GRID, 256>>>(TP, ctr2_g + (size_t)i * C,
                                            ctr2_b + (size_t)i * C, FT, out,
                                            nullptr, nullptr);
    } else {
      // writes feat (+split) and zeroes TP for the next block
      gn_res_relu_kernel<<<ROW_GRID, 256>>>(TP, ctr2_g + (size_t)i * C,
                                            ctr2_b + (size_t)i * C, FT, FT,
                                            AA, TP);
    }
  }
#undef GEMM2
}

// round 12
// speedup vs baseline: 3.0270x; 1.1840x over previous
#include <cuda_runtime.h>
#include <cuda_fp16.h>
#include <cstdint>

#define DEV_INLINE __device__ __forceinline__

constexpr int N  = 131072;
constexpr int C  = 128;
constexpr int S  = 6;
constexpr int E  = 131072;
constexpr int EL = 32768;
constexpr int NB = 4;
constexpr int CC = C * C;
constexpr int NSLOT = 66;
constexpr int NT = 1024;   // source row tiles (N/128)
constexpr int NL = 14;     // edge lists: 0-5 pre, 6-11 suc, 12 left, 13 right
constexpr int ESTORE = 12 * E + 2 * EL;
constexpr int IDX_CAP = 512;   // smem-resident edges per (tile, list)

// Scratch (allocation-free rule: static __device__ arrays)
__device__ float  g_feat[N * C];
__device__ float  g_temp[N * C];
__device__ float  g_Y[N * C];
__device__ __half g_A[N * C];           // fp16 activations
__device__ __half g_Wh[NSLOT * CC];     // fp16 weight hi, [slot][c][k] (transposed)
__device__ __half g_Wl[NSLOT * CC];     // fp16 weight lo (residual; main path only)
// edge sort scratch
__device__ int g_cnt[NL * NT];
__device__ int g_off[NL * (NT + 1)];
__device__ int g_epk[ESTORE];  // packed edge: (u << 7) | (v & 127)

DEV_INLINE uint32_t smem_u32(const void* p) {
  uint32_t a;
  asm("{ .reg .u64 t; cvta.to.shared.u64 t, %1; cvt.u32.u64 %0, t; }"
      : "=r"(a) : "l"(p));
  return a;
}

// ---------------------------------------------------------------------------
// MMA building blocks. smem tile: 128 rows x 256B, XOR-16B swizzle on (row&7)
// ---------------------------------------------------------------------------
constexpr int TILE_BYTES = 128 * 256;  // 32 KB (128x128 fp16)

DEV_INLINE void ldsm4(uint32_t& r0, uint32_t& r1, uint32_t& r2, uint32_t& r3,
                      uint32_t addr) {
  asm volatile("ldmatrix.sync.aligned.m8n8.x4.shared.b16 {%0,%1,%2,%3}, [%4];"
               : "=r"(r0), "=r"(r1), "=r"(r2), "=r"(r3) : "r"(addr));
}
DEV_INLINE void mma_f16(float* c, uint32_t a0, uint32_t a1, uint32_t a2,
                        uint32_t a3, uint32_t b0, uint32_t b1) {
  asm volatile(
      "mma.sync.aligned.m16n8k16.row.col.f32.f16.f16.f32 "
      "{%0,%1,%2,%3}, {%4,%5,%6,%7}, {%8,%9}, {%0,%1,%2,%3};"
      : "+f"(c[0]), "+f"(c[1]), "+f"(c[2]), "+f"(c[3])
      : "r"(a0), "r"(a1), "r"(a2), "r"(a3), "r"(b0), "r"(b1));
}

DEV_INLINE void cp_async16(uint32_t dst, const void* src) {
  asm volatile("cp.async.cg.shared.global [%0], [%1], 16;" :: "r"(dst),
               "l"(src));
}
DEV_INLINE void cp_async4(uint32_t dst, const void* src) {
  asm volatile("cp.async.ca.shared.global [%0], [%1], 4;" :: "r"(dst),
               "l"(src));
}
#define CP_COMMIT() asm volatile("cp.async.commit_group;" ::: "memory")
#define CP_WAIT(n)  asm volatile("cp.async.wait_group %0;" :: "n"(n) : "memory")

// stage one 128x128 fp16 tile (32 KB) with swizzle via cp.async; 256 threads
DEV_INLINE void stage_async(uint32_t dstBase, const __half* src, int tid) {
  const char* s = (const char*)src;
#pragma unroll
  for (int t = 0; t < 8; ++t) {
    int idx = tid + t * 256;
    int r = idx >> 4, c16 = idx & 15;
    uint32_t off = r * 256 + ((c16 * 16) ^ ((r & 7) << 4));
    cp_async16(dstBase + off, s + idx * 16);
  }
}

// fragment address precompute
struct FragIdx {
  uint32_t aRow[4], aColK, bRow[2], bColK;
  int rw, cw;
};
DEV_INLINE FragIdx frag_idx(int lane, int wid) {
  FragIdx f;
  f.rw = (wid & 1) * 64;
  f.cw = (wid >> 1) * 32;
  f.aColK = (lane >> 4) * 16;
#pragma unroll
  for (int mi = 0; mi < 4; ++mi) f.aRow[mi] = f.rw + mi * 16 + (lane & 15);
  f.bColK = ((lane >> 3) & 1) * 16;
#pragma unroll
  for (int bi = 0; bi < 2; ++bi)
    f.bRow[bi] = f.cw + bi * 16 + ((lane >> 4) * 8) + (lane & 7);
  return f;
}

DEV_INLINE void zero_acc(float (&acc)[4][4][4]) {
#pragma unroll
  for (int mi = 0; mi < 4; ++mi)
#pragma unroll
    for (int ni = 0; ni < 4; ++ni)
#pragma unroll
      for (int j = 0; j < 4; ++j) acc[mi][ni][j] = 0.0f;
}

// one K-sweep (8 chunks) of A@B accumulated
DEV_INLINE void mma_pass(uint32_t aBase, uint32_t bBase, const FragIdx& f,
                         float (&acc)[4][4][4]) {
#pragma unroll
  for (int kk = 0; kk < 8; ++kk) {
    const uint32_t kb = kk * 32;
    uint32_t a[4][4];
#pragma unroll
    for (int mi = 0; mi < 4; ++mi) {
      uint32_t r = f.aRow[mi];
      uint32_t addr = aBase + r * 256 + ((kb | f.aColK) ^ ((r & 7) << 4));
      ldsm4(a[mi][0], a[mi][1], a[mi][2], a[mi][3], addr);
    }
    uint32_t b[4][2];
#pragma unroll
    for (int bi = 0; bi < 2; ++bi) {
      uint32_t r = f.bRow[bi];
      uint32_t addr = bBase + r * 256 + ((kb | f.bColK) ^ ((r & 7) << 4));
      ldsm4(b[bi * 2][0], b[bi * 2][1], b[bi * 2 + 1][0], b[bi * 2 + 1][1],
            addr);
    }
#pragma unroll
    for (int mi = 0; mi < 4; ++mi)
#pragma unroll
      for (int ni = 0; ni < 4; ++ni)
        mma_f16(acc[mi][ni], a[mi][0], a[mi][1], a[mi][2], a[mi][3],
                b[ni][0], b[ni][1]);
  }
}

DEV_INLINE void store_acc_global(float* Out, int rowBase, int lane, int wid,
                                 float (&acc)[4][4][4]) {
  const int rw = (wid & 1) * 64, cw = (wid >> 1) * 32;
  const int r0 = lane >> 2, c0 = (lane & 3) * 2;
#pragma unroll
  for (int mi = 0; mi < 4; ++mi)
#pragma unroll
    for (int ni = 0; ni < 4; ++ni) {
      int grow = rowBase + rw + mi * 16 + r0;
      int gcol = cw + ni * 8 + c0;
      *(float2*)(Out + (size_t)grow * C + gcol) =
          make_float2(acc[mi][ni][0], acc[mi][ni][1]);
      *(float2*)(Out + (size_t)(grow + 8) * C + gcol) =
          make_float2(acc[mi][ni][2], acc[mi][ni][3]);
    }
}

DEV_INLINE float wsum(float v) {
#pragma unroll
  for (int o = 16; o > 0; o >>= 1) v += __shfl_xor_sync(0xffffffffu, v, o);
  return v;
}

// ---------------------------------------------------------------------------
// standalone GEMM (input stage, 2-pass): Out = A@(Wh+Wl)^T. 96 KB -> 2 CTA/SM.
// ---------------------------------------------------------------------------
constexpr int SMEM_MMA_BYTES = 3 * TILE_BYTES;  // 96 KB

__global__ void __launch_bounds__(256, 2) gemm_mma(
    const __half* __restrict__ A, const __half* __restrict__ Bh,
    const __half* __restrict__ Bl, float* __restrict__ Out) {
  extern __shared__ __align__(16) char smem[];
  const uint32_t sbase = smem_u32(smem);
  const int tid = threadIdx.x, lane = tid & 31, wid = tid >> 5;
  const int rowBase = blockIdx.x * 128;

  stage_async(sbase, A + (size_t)rowBase * C, tid);
  stage_async(sbase + TILE_BYTES, Bh, tid);
  stage_async(sbase + 2 * TILE_BYTES, Bl, tid);
  CP_COMMIT();
  CP_WAIT(0);
  __syncthreads();

  FragIdx f = frag_idx(lane, wid);
  float acc[4][4][4];
  zero_acc(acc);
  mma_pass(sbase, sbase + TILE_BYTES, f, acc);
  mma_pass(sbase, sbase + 2 * TILE_BYTES, f, acc);
  store_acc_global(Out, rowBase, lane, wid, acc);
}

// ---------------------------------------------------------------------------
// fused block tail: prologue GN(temp)+relu -> fp16 A tile (smem only),
// 2-pass ctr2 MMA, epilogue rowwise GN + identity + relu -> feat fp32,
// fp16 split, zero temp. Ybuf (fp32, 512B rows, XOR swizzle) reuses W smem.
// ---------------------------------------------------------------------------
__global__ void __launch_bounds__(256, 2) gn_gemm_gn_kernel(
    const float* __restrict__ Xin,                        // temp (post-atomics)
    const float* __restrict__ G1v, const float* __restrict__ B1v,
    const __half* __restrict__ Bh, const __half* __restrict__ Bl,
    const float* __restrict__ G2v, const float* __restrict__ B2v,
    const float* __restrict__ Id, float* __restrict__ OutF,
    __half* __restrict__ Aout, float* __restrict__ TPz) {
  extern __shared__ __align__(16) char smem[];
  const uint32_t sbase = smem_u32(smem);
  const int tid = threadIdx.x, lane = tid & 31, wid = tid >> 5;
  const int rowBase = blockIdx.x * 128;

  // W staged while prologue computes
  stage_async(sbase + TILE_BYTES, Bh, tid);
  stage_async(sbase + 2 * TILE_BYTES, Bl, tid);
  CP_COMMIT();

  // prologue: rowwise GN+relu of Xin -> swizzled fp16 A tile
  {
    float4 g1 = ((const float4*)G1v)[lane];
    float4 b1 = ((const float4*)B1v)[lane];
#pragma unroll 4
    for (int i = 0; i < 16; ++i) {
      int r = wid * 16 + i;
      float4 x = *(const float4*)(Xin + (size_t)(rowBase + r) * C + lane * 4);
      float s = wsum(x.x + x.y + x.z + x.w);
      float q = wsum(x.x * x.x + x.y * x.y + x.z * x.z + x.w * x.w);
      float mu = s * (1.0f / 128.0f);
      float rs = rsqrtf(q * (1.0f / 128.0f) - mu * mu + 1e-5f);
      float ox = fmaxf((x.x - mu) * rs * g1.x + b1.x, 0.0f);
      float oy = fmaxf((x.y - mu) * rs * g1.y + b1.y, 0.0f);
      float oz = fmaxf((x.z - mu) * rs * g1.z + b1.z, 0.0f);
      float ow = fmaxf((x.w - mu) * rs * g1.w + b1.w, 0.0f);
      __half2 h0 = __floats2half2_rn(ox, oy);
      __half2 h1 = __floats2half2_rn(oz, ow);
      uint32_t off = r * 256 + ((lane * 8) ^ ((r & 7) << 4));
      *(uint2*)(smem + off) = make_uint2(*(uint32_t*)&h0, *(uint32_t*)&h1);
    }
  }
  CP_WAIT(0);
  __syncthreads();

  FragIdx f = frag_idx(lane, wid);
  float acc[4][4][4];
  zero_acc(acc);
  mma_pass(sbase, sbase + TILE_BYTES, f, acc);
  mma_pass(sbase, sbase + 2 * TILE_BYTES, f, acc);
  __syncthreads();  // all warps done with W smem

  // stage Y2 fp32 into the (now free) W region: 128 rows x 512B, XOR swizzle
  {
    const int rw = (wid & 1) * 64, cw = (wid >> 1) * 32;
    const int r0 = lane >> 2, c0 = (lane & 3) * 2;
#pragma unroll
    for (int mi = 0; mi < 4; ++mi)
#pragma unroll
      for (int ni = 0; ni < 4; ++ni) {
        int row = rw + mi * 16 + r0, col = cw + ni * 8 + c0;
        uint32_t o1 = row * 512 + ((col * 4) ^ ((row & 7) << 4));
        *(float2*)(smem + TILE_BYTES + o1) =
            make_float2(acc[mi][ni][0], acc[mi][ni][1]);
        uint32_t o2 = (row + 8) * 512 + ((col * 4) ^ (((row + 8) & 7) << 4));
        *(float2*)(smem + TILE_BYTES + o2) =
            make_float2(acc[mi][ni][2], acc[mi][ni][3]);
      }
  }
  __syncthreads();

  // epilogue: rowwise GN + identity + relu; write feat / split / zero temp
  // Read at PHYSICAL offset lane*16 (conflict-free full-row coverage); the
  // logical column of that value is ((lane*16) ^ ((r&7)<<4)) / 4.
#pragma unroll 2
  for (int i = 0; i < 16; ++i) {
    int r = wid * 16 + i;
    float4 y = *(float4*)(smem + TILE_BYTES + r * 512 + lane * 16);
    float s = wsum(y.x + y.y + y.z + y.w);
    float q = wsum(y.x * y.x + y.y * y.y + y.z * y.z + y.w * y.w);
    float mu = s * (1.0f / 128.0f);
    float rs = rsqrtf(q * (1.0f / 128.0f) - mu * mu + 1e-5f);
    int colb = ((lane * 16) ^ ((r & 7) << 4)) >> 2;  // logical column
    float4 g2 = *(const float4*)(G2v + colb);
    float4 b2 = *(const float4*)(B2v + colb);
    size_t goff = (size_t)(rowBase + r) * C + colb;
    float4 id = *(const float4*)(Id + goff);
    float4 o;
    o.x = fmaxf((y.x - mu) * rs * g2.x + b2.x + id.x, 0.0f);
    o.y = fmaxf((y.y - mu) * rs * g2.y + b2.y + id.y, 0.0f);
    o.z = fmaxf((y.z - mu) * rs * g2.z + b2.z + id.z, 0.0f);
    o.w = fmaxf((y.w - mu) * rs * g2.w + b2.w + id.w, 0.0f);
    *(float4*)(OutF + goff) = o;
    if (Aout) {
      __half2 h0 = __floats2half2_rn(o.x, o.y);
      __half2 h1 = __floats2half2_rn(o.z, o.w);
      *(uint2*)(Aout + goff) = make_uint2(*(uint32_t*)&h0, *(uint32_t*)&h1);
    }
    if (TPz) *(float4*)(TPz + goff) = make_float4(0.f, 0.f, 0.f, 0.f);
  }
}

// ---------------------------------------------------------------------------
// fused per-block kernel: ctr GEMM (it=0, own-row red.add into zeroed TP)
// + 14 edge-GEMMs (single-pass fp16 W) + smem scatter with smem-resident
// edge indices (cp.async prefetched, double-buffered). 2 CTA/SM.
// ---------------------------------------------------------------------------
constexpr int YPITCH_H = 136;
constexpr int W_OFF   = TILE_BYTES;       // 32768
constexpr int Y_OFF   = 2 * TILE_BYTES;   // 65536
constexpr int IDX_OFF = Y_OFF + 128 * YPITCH_H * 2;      // 100352
constexpr int SMEM_FUSED = IDX_OFF + 2 * IDX_CAP * 4;    // 104448

__global__ void __launch_bounds__(256, 2) fused_block_kernel(
    const __half* __restrict__ A, int ib, float* __restrict__ TP) {
  extern __shared__ __align__(16) char smem[];
  const uint32_t sbase = smem_u32(smem);
  __half* Ybuf = (__half*)(smem + Y_OFF);
  const int tid = threadIdx.x, lane = tid & 31, wid = tid >> 5;
  const int rowBase = blockIdx.x * 128;

  const int rw = (wid & 1) * 64, cw = (wid >> 1) * 32;
  const int r0 = lane >> 2, c0 = (lane & 3) * 2;

  auto slot_of = [&](int it) {
    return (it == 0)   ? 2 + ib
           : (it < 7)  ? 6 + ib * 6 + (it - 1)
           : (it < 13) ? 30 + ib * 6 + (it - 7)
           : (it == 13) ? 54 + ib : 58 + ib;
  };
  auto ebase_of = [&](int it) {
    int l = it - 1;
    return (l < 12) ? l * E : 12 * E + (l - 12) * EL;
  };
  auto stage_idx = [&](int it) {
    int l = it - 1;
    int o0 = g_off[l * (NT + 1) + blockIdx.x];
    int o1 = g_off[l * (NT + 1) + blockIdx.x + 1];
    int cnt = min(o1 - o0, IDX_CAP);
    const int* src = g_epk + ebase_of(it) + o0;
    uint32_t dst = sbase + IDX_OFF + (it & 1) * (IDX_CAP * 4);
    for (int j = tid; j < cnt; j += 256) cp_async4(dst + j * 4, src + j);
  };

  stage_async(sbase, A + (size_t)rowBase * C, tid);
  stage_async(sbase + W_OFF, g_Wh + (size_t)slot_of(0) * CC, tid);
  stage_idx(1);
  CP_COMMIT();
  CP_WAIT(0);
  __syncthreads();

  FragIdx f = frag_idx(lane, wid);

#pragma unroll 1
  for (int it = 0; it < 15; ++it) {
    float acc[4][4][4];
    zero_acc(acc);
    mma_pass(sbase, sbase + W_OFF, f, acc);

#pragma unroll
    for (int mi = 0; mi < 4; ++mi)
#pragma unroll
      for (int ni = 0; ni < 4; ++ni) {
        int row = rw + mi * 16 + r0, col = cw + ni * 8 + c0;
        __half2 h0 = __floats2half2_rn(acc[mi][ni][0], acc[mi][ni][1]);
        __half2 h1 = __floats2half2_rn(acc[mi][ni][2], acc[mi][ni][3]);
        *(__half2*)(Ybuf + row * YPITCH_H + col) = h0;
        *(__half2*)(Ybuf + (row + 8) * YPITCH_H + col) = h1;
      }
    __syncthreads();  // Ybuf ready; W(it) fully consumed

    if (it < 14) {
      stage_async(sbase + W_OFF, g_Wh + (size_t)slot_of(it + 1) * CC, tid);
      stage_idx(it + 1);
      CP_COMMIT();
    }

    if (it == 0) {
      for (int r = wid; r < 128; r += 8) {
        uint2 hv = *(uint2*)(Ybuf + r * YPITCH_H + lane * 4);
        float2 f0 = __half22float2(*(__half2*)&hv.x);
        float2 f1 = __half22float2(*(__half2*)&hv.y);
        float* p = TP + (size_t)(rowBase + r) * C + lane * 4;
        asm volatile("red.global.add.v4.f32 [%0], {%1,%2,%3,%4};"
                     :: "l"(p), "f"(f0.x), "f"(f0.y), "f"(f1.x), "f"(f1.y)
                     : "memory");
      }
    } else {
      int l = it - 1;
      int o0 = g_off[l * (NT + 1) + blockIdx.x];
      int o1 = g_off[l * (NT + 1) + blockIdx.x + 1];
      int cnt = o1 - o0;
      const int* sidx = (const int*)(smem + IDX_OFF + (it & 1) * (IDX_CAP * 4));
      const int* gidx = g_epk + ebase_of(it) + o0;
#pragma unroll 2
      for (int j = wid; j < cnt; j += 8) {
        int pk = (j < IDX_CAP) ? sidx[j] : __ldg(&gidx[j]);
        int vl = pk & 127;
        int uu = pk >> 7;
        uint2 hv = *(uint2*)(Ybuf + vl * YPITCH_H + lane * 4);
        float2 f0 = __half22float2(*(__half2*)&hv.x);
        float2 f1 = __half22float2(*(__half2*)&hv.y);
        float* p = TP + (size_t)uu * C + lane * 4;
        asm volatile("red.global.add.v4.f32 [%0], {%1,%2,%3,%4};"
                     :: "l"(p), "f"(f0.x), "f"(f0.y), "f"(f1.x), "f"(f1.y)
                     : "memory");
      }
    }

    if (it < 14) CP_WAIT(0);
    __syncthreads();
  }
}

// ---------------------------------------------------------------------------
// edge sort (counting sort by v>>7), once per launch — consolidated kernels
// ---------------------------------------------------------------------------
__global__ void zero_cnt_kernel() {
  int i = blockIdx.x * 256 + threadIdx.x;
  if (i < NL * NT) g_cnt[i] = 0;
}

DEV_INLINE void edge_locate(int e, const int*& vp, int& l, int& off,
                            const int* pre_v, const int* suc_v,
                            const int* left_v, const int* right_v) {
  if (e < 6 * E) { l = e / E; vp = pre_v; off = e; }
  else if (e < 12 * E) { l = 6 + (e - 6 * E) / E; vp = suc_v; off = e - 6 * E; }
  else if (e < 12 * E + EL) { l = 12; vp = left_v; off = e - 12 * E; }
  else { l = 13; vp = right_v; off = e - 12 * E - EL; }
}

__global__ void hist_all_kernel(const int* __restrict__ pre_v,
                                const int* __restrict__ suc_v,
                                const int* __restrict__ left_v,
                                const int* __restrict__ right_v) {
  int e = blockIdx.x * 256 + threadIdx.x;
  if (e >= ESTORE) return;
  const int* vp; int l, off;
  edge_locate(e, vp, l, off, pre_v, suc_v, left_v, right_v);
  atomicAdd(&g_cnt[l * NT + (__ldg(&vp[off]) >> 7)], 1);
}

__global__ void prefix_kernel() {  // one block per list, 1024 threads
  __shared__ int sh[NT];
  int l = blockIdx.x, t = threadIdx.x;
  sh[t] = g_cnt[l * NT + t];
  __syncthreads();
#pragma unroll
  for (int d = 1; d < NT; d <<= 1) {
    int x = (t >= d) ? sh[t - d] : 0;
    __syncthreads();
    sh[t] += x;
    __syncthreads();
  }
  g_off[l * (NT + 1) + t + 1] = sh[t];
  if (t == 0) g_off[l * (NT + 1)] = 0;
}

__global__ void fill_all_kernel(const int* __restrict__ pre_u,
                                const int* __restrict__ pre_v,
                                const int* __restrict__ suc_u,
                                const int* __restrict__ suc_v,
                                const int* __restrict__ left_u,
                                const int* __restrict__ left_v,
                                const int* __restrict__ right_u,
                                const int* __restrict__ right_v) {
  int e = blockIdx.x * 256 + threadIdx.x;
  if (e >= ESTORE) return;
  const int* vp; int l, off;
  edge_locate(e, vp, l, off, pre_v, suc_v, left_v, right_v);
  const int* up = (l < 6) ? pre_u : (l < 12) ? suc_u : (l == 12) ? left_u
                                                                 : right_u;
  int vv = __ldg(&vp[off]);
  int t = vv >> 7;
  int lbase = (l < 12) ? l * E : 12 * E + (l - 12) * EL;
  int pos = lbase + g_off[l * (NT + 1) + t] + atomicAdd(&g_cnt[l * NT + t], 1);
  g_epk[pos] = (__ldg(&up[off]) << 7) | (vv & 127);
}

// ---------------------------------------------------------------------------
// setup: weight split + transpose, all 66 slots in one kernel
// ---------------------------------------------------------------------------
__global__ void wsplit_all_kernel(const float* __restrict__ ic_w1,
                                  const float* __restrict__ if_w1,
                                  const float* __restrict__ ctr_w,
                                  const float* __restrict__ pre_w,
                                  const float* __restrict__ suc_w,
                                  const float* __restrict__ left_w,
                                  const float* __restrict__ right_w,
                                  const float* __restrict__ ctr2_w) {
  int idx = blockIdx.x * 256 + threadIdx.x;  // NSLOT * 16384
  int slot = idx >> 14, r = idx & 16383;
  int c = r >> 7, k = r & 127;
  const float* src; int m;
  if (slot < 1)       { src = ic_w1;  m = 0; }
  else if (slot < 2)  { src = if_w1;  m = 0; }
  else if (slot < 6)  { src = ctr_w;  m = slot - 2; }
  else if (slot < 30) { src = pre_w;  m = slot - 6; }
  else if (slot < 54) { src = suc_w;  m = slot - 30; }
  else if (slot < 58) { src = left_w; m = slot - 54; }
  else if (slot < 62) { src = right_w; m = slot - 58; }
  else                { src = ctr2_w; m = slot - 62; }
  float w = src[(size_t)m * CC + k * 128 + c];
  __half hi = __float2half_rn(w);
  __half lo = __float2half_rn(w - __half2float(hi));
  size_t o = (size_t)slot * CC + r;
  g_Wh[o] = hi;
  g_Wl[o] = lo;
}

// ---------------------------------------------------------------------------
// elementwise kernels (input stage)
// ---------------------------------------------------------------------------
DEV_INLINE void h4_store(__half* H, size_t idx4, float4 o) {
  __half2 a = __floats2half2_rn(o.x, o.y);
  __half2 b = __floats2half2_rn(o.z, o.w);
  *(uint2*)(H + idx4) = make_uint2(*(uint32_t*)&a, *(uint32_t*)&b);
}

__global__ void mlp0_kernel(const float* __restrict__ X2,
                            const float* __restrict__ W0,
                            const float* __restrict__ B0,
                            __half* __restrict__ H) {
  int idx = blockIdx.x * 256 + threadIdx.x;  // N*64
  int n = idx >> 6, c = (idx & 63) << 1;
  float x0 = X2[2 * n], x1 = X2[2 * n + 1];
  float ha = fmaxf(fmaf(x0, W0[c], fmaf(x1, W0[C + c], B0[c])), 0.0f);
  float hb = fmaxf(fmaf(x0, W0[c + 1], fmaf(x1, W0[C + c + 1], B0[c + 1])), 0.0f);
  *(__half2*)(H + (size_t)n * C + c) = __floats2half2_rn(ha, hb);
}

// feat = relu(GN(Y1)+GN(Y2)); writes fp32 FT + fp16 split + zeroes TP
__global__ void combine_kernel(const float* __restrict__ Y1,
                               const float* __restrict__ Y2,
                               const float* __restrict__ G1,
                               const float* __restrict__ B1,
                               const float* __restrict__ G2,
                               const float* __restrict__ B2,
                               float* __restrict__ Of,
                               __half* __restrict__ H,
                               float* __restrict__ TPz) {
  int w = (blockIdx.x * blockDim.x + threadIdx.x) >> 5;
  int lane = threadIdx.x & 31;
  size_t idx = (size_t)w * 32 + lane;
  float4 x1 = ((const float4*)Y1)[idx];
  float4 x2 = ((const float4*)Y2)[idx];
  float s1 = wsum(x1.x + x1.y + x1.z + x1.w);
  float q1 = wsum(x1.x * x1.x + x1.y * x1.y + x1.z * x1.z + x1.w * x1.w);
  float s2 = wsum(x2.x + x2.y + x2.z + x2.w);
  float q2 = wsum(x2.x * x2.x + x2.y * x2.y + x2.z * x2.z + x2.w * x2.w);
  float mu1 = s1 * (1.0f / 128.0f);
  float rs1 = rsqrtf(q1 * (1.0f / 128.0f) - mu1 * mu1 + 1e-5f);
  float mu2 = s2 * (1.0f / 128.0f);
  float rs2 = rsqrtf(q2 * (1.0f / 128.0f) - mu2 * mu2 + 1e-5f);
  float4 g1 = ((const float4*)G1)[lane];
  float4 b1 = ((const float4*)B1)[lane];
  float4 g2 = ((const float4*)G2)[lane];
  float4 b2 = ((const float4*)B2)[lane];
  float4 o;
  o.x = fmaxf((x1.x - mu1) * rs1 * g1.x + b1.x + (x2.x - mu2) * rs2 * g2.x + b2.x, 0.0f);
  o.y = fmaxf((x1.y - mu1) * rs1 * g1.y + b1.y + (x2.y - mu2) * rs2 * g2.y + b2.y, 0.0f);
  o.z = fmaxf((x1.z - mu1) * rs1 * g1.z + b1.z + (x2.z - mu2) * rs2 * g2.z + b2.z, 0.0f);
  o.w = fmaxf((x1.w - mu1) * rs1 * g1.w + b1.w + (x2.w - mu2) * rs2 * g2.w + b2.w, 0.0f);
  ((float4*)Of)[idx] = o;
  h4_store(H, idx * 4, o);
  ((float4*)TPz)[idx] = make_float4(0.f, 0.f, 0.f, 0.f);
}

// ---------------------------------------------------------------------------
extern "C" void kernel_launch(void* const* d_in, const int* in_sizes, int n_in,
                              void* d_out, int out_size) {
  const float* ctrs   = (const float*)d_in[0];
  const float* feats  = (const float*)d_in[1];
  const int*   pre_u  = (const int*)d_in[2];
  const int*   pre_v  = (const int*)d_in[3];
  const int*   suc_u  = (const int*)d_in[4];
  const int*   suc_v  = (const int*)d_in[5];
  const int*   left_u = (const int*)d_in[6];
  const int*   left_v = (const int*)d_in[7];
  const int*   right_u= (const int*)d_in[8];
  const int*   right_v= (const int*)d_in[9];
  const float* ic_w0  = (const float*)d_in[10];
  const float* ic_b0  = (const float*)d_in[11];
  const float* ic_w1  = (const float*)d_in[12];
  const float* ic_g   = (const float*)d_in[13];
  const float* ic_bt  = (const float*)d_in[14];
  const float* if_w0  = (const float*)d_in[15];
  const float* if_b0  = (const float*)d_in[16];
  const float* if_w1  = (const float*)d_in[17];
  const float* if_g   = (const float*)d_in[18];
  const float* if_bt  = (const float*)d_in[19];
  const float* ctr_w  = (const float*)d_in[20];
  const float* pre_w  = (const float*)d_in[21];
  const float* suc_w  = (const float*)d_in[22];
  const float* left_w = (const float*)d_in[23];
  const float* right_w= (const float*)d_in[24];
  const float* norm_g = (const float*)d_in[25];
  const float* norm_b = (const float*)d_in[26];
  const float* ctr2_w = (const float*)d_in[27];
  const float* ctr2_g = (const float*)d_in[28];
  const float* ctr2_b = (const float*)d_in[29];
  float* out = (float*)d_out;

  float *FT, *TP, *YB;
  __half *AA, *WH, *WL;
  cudaGetSymbolAddress((void**)&FT, g_feat);
  cudaGetSymbolAddress((void**)&TP, g_temp);
  cudaGetSymbolAddress((void**)&YB, g_Y);
  cudaGetSymbolAddress((void**)&AA, g_A);
  cudaGetSymbolAddress((void**)&WH, g_Wh);
  cudaGetSymbolAddress((void**)&WL, g_Wl);

  cudaFuncSetAttribute(gemm_mma, cudaFuncAttributeMaxDynamicSharedMemorySize,
                       SMEM_MMA_BYTES);
  cudaFuncSetAttribute(gn_gemm_gn_kernel,
                       cudaFuncAttributeMaxDynamicSharedMemorySize,
                       SMEM_MMA_BYTES);
  cudaFuncSetAttribute(fused_block_kernel,
                       cudaFuncAttributeMaxDynamicSharedMemorySize, SMEM_FUSED);

  const int GEMM_GRID = N / 128;
  const int ROW_GRID  = N / 8;
  const int MLP_GRID  = (N * 64) / 256;
  const int ZG = (NL * NT + 255) / 256;
  const int EG = (ESTORE + 255) / 256;

  // ---- setup: weight split (1 launch) + edge sort (4 launches) ----
  wsplit_all_kernel<<<NSLOT * 64, 256>>>(ic_w1, if_w1, ctr_w, pre_w, suc_w,
                                         left_w, right_w, ctr2_w);
  zero_cnt_kernel<<<ZG, 256>>>();
  hist_all_kernel<<<EG, 256>>>(pre_v, suc_v, left_v, right_v);
  prefix_kernel<<<NL, NT>>>();
  zero_cnt_kernel<<<ZG, 256>>>();
  fill_all_kernel<<<EG, 256>>>(pre_u, pre_v, suc_u, suc_v, left_u, left_v,
                               right_u, right_v);

#define GEMM2(slot, OutPtr)                                                  \
  gemm_mma<<<GEMM_GRID, 256, SMEM_MMA_BYTES>>>(                              \
      AA, WH + (size_t)(slot) * CC, WL + (size_t)(slot) * CC, OutPtr)

  // ---- Input stage ----
  mlp0_kernel<<<MLP_GRID, 256>>>(ctrs, ic_w0, ic_b0, AA);
  GEMM2(0, FT);
  mlp0_kernel<<<MLP_GRID, 256>>>(feats, if_w0, if_b0, AA);
  GEMM2(1, YB);
  combine_kernel<<<ROW_GRID, 256>>>(FT, YB, ic_g, ic_bt, if_g, if_bt, FT, AA,
                                    TP);

  // ---- 4 fusion blocks: 2 kernels each ----
  for (int i = 0; i < NB; ++i) {
    fused_block_kernel<<<GEMM_GRID, 256, SMEM_FUSED>>>(AA, i, TP);

    if (i == NB - 1) {
      gn_gemm_gn_kernel<<<GEMM_GRID, 256, SMEM_MMA_BYTES>>>(
          TP, norm_g + (size_t)i * C, norm_b + (size_t)i * C,
          WH + (size_t)(62 + i) * CC, WL + (size_t)(62 + i) * CC,
          ctr2_g + (size_t)i * C, ctr2_b + (size_t)i * C, FT, out, nullptr,
          nullptr);
    } else {
      gn_gemm_gn_kernel<<<GEMM_GRID, 256, SMEM_MMA_BYTES>>>(
          TP, norm_g + (size_t)i * C, norm_b + (size_t)i * C,
          WH + (size_t)(62 + i) * CC, WL + (size_t)(62 + i) * CC,
          ctr2_g + (size_t)i * C, ctr2_b + (size_t)i * C, FT, FT, AA, TP);
    }
  }
#undef GEMM2
}

// round 13
// speedup vs baseline: 3.3126x; 1.0943x over previous
#include <cuda_runtime.h>
#include <cuda_fp16.h>
#include <cstdint>

#define DEV_INLINE __device__ __forceinline__

constexpr int N  = 131072;
constexpr int C  = 128;
constexpr int S  = 6;
constexpr int E  = 131072;
constexpr int EL = 32768;
constexpr int NB = 4;
constexpr int CC = C * C;
constexpr int NSLOT = 66;
constexpr int NT = 1024;   // source row tiles (N/128)
constexpr int NLS = 12;    // sorted edge lists: 0-5 pre, 6-11 suc
constexpr int ESTORE = 12 * E;
constexpr int IDX_CAP = 512;   // smem-resident edges per (tile, list)
constexpr int NCHUNK = EL / 128;  // 256 compact chunks for left/right

// Scratch (allocation-free rule: static __device__ arrays)
__device__ float  g_feat[N * C];
__device__ float  g_temp[N * C];
__device__ float  g_Y[N * C];
__device__ __half g_A[N * C];           // fp16 activations
__device__ __half g_Wh[NSLOT * CC];     // fp16 weight hi, [slot][c][k] (transposed)
__device__ __half g_Wl[NSLOT * CC];     // fp16 weight lo (residual; main path only)
// edge sort scratch
__device__ int g_cnt[NLS * NT];
__device__ int g_off[NLS * (NT + 1)];
__device__ int g_epk[ESTORE];  // packed edge: (u << 7) | (v & 127)

DEV_INLINE uint32_t smem_u32(const void* p) {
  uint32_t a;
  asm("{ .reg .u64 t; cvta.to.shared.u64 t, %1; cvt.u32.u64 %0, t; }"
      : "=r"(a) : "l"(p));
  return a;
}

// ---------------------------------------------------------------------------
// MMA building blocks. smem tile: 128 rows x 256B, XOR-16B swizzle on (row&7)
// ---------------------------------------------------------------------------
constexpr int TILE_BYTES = 128 * 256;  // 32 KB (128x128 fp16)

DEV_INLINE void ldsm4(uint32_t& r0, uint32_t& r1, uint32_t& r2, uint32_t& r3,
                      uint32_t addr) {
  asm volatile("ldmatrix.sync.aligned.m8n8.x4.shared.b16 {%0,%1,%2,%3}, [%4];"
               : "=r"(r0), "=r"(r1), "=r"(r2), "=r"(r3) : "r"(addr));
}
DEV_INLINE void mma_f16(float* c, uint32_t a0, uint32_t a1, uint32_t a2,
                        uint32_t a3, uint32_t b0, uint32_t b1) {
  asm volatile(
      "mma.sync.aligned.m16n8k16.row.col.f32.f16.f16.f32 "
      "{%0,%1,%2,%3}, {%4,%5,%6,%7}, {%8,%9}, {%0,%1,%2,%3};"
      : "+f"(c[0]), "+f"(c[1]), "+f"(c[2]), "+f"(c[3])
      : "r"(a0), "r"(a1), "r"(a2), "r"(a3), "r"(b0), "r"(b1));
}

DEV_INLINE void cp_async16(uint32_t dst, const void* src) {
  asm volatile("cp.async.cg.shared.global [%0], [%1], 16;" :: "r"(dst),
               "l"(src));
}
DEV_INLINE void cp_async4(uint32_t dst, const void* src) {
  asm volatile("cp.async.ca.shared.global [%0], [%1], 4;" :: "r"(dst),
               "l"(src));
}
#define CP_COMMIT() asm volatile("cp.async.commit_group;" ::: "memory")
#define CP_WAIT(n)  asm volatile("cp.async.wait_group %0;" :: "n"(n) : "memory")

// stage one 128x128 fp16 tile (32 KB) with swizzle via cp.async; 256 threads
DEV_INLINE void stage_async(uint32_t dstBase, const __half* src, int tid) {
  const char* s = (const char*)src;
#pragma unroll
  for (int t = 0; t < 8; ++t) {
    int idx = tid + t * 256;
    int r = idx >> 4, c16 = idx & 15;
    uint32_t off = r * 256 + ((c16 * 16) ^ ((r & 7) << 4));
    cp_async16(dstBase + off, s + idx * 16);
  }
}

// fragment address precompute
struct FragIdx {
  uint32_t aRow[4], aColK, bRow[2], bColK;
  int rw, cw;
};
DEV_INLINE FragIdx frag_idx(int lane, int wid) {
  FragIdx f;
  f.rw = (wid & 1) * 64;
  f.cw = (wid >> 1) * 32;
  f.aColK = (lane >> 4) * 16;
#pragma unroll
  for (int mi = 0; mi < 4; ++mi) f.aRow[mi] = f.rw + mi * 16 + (lane & 15);
  f.bColK = ((lane >> 3) & 1) * 16;
#pragma unroll
  for (int bi = 0; bi < 2; ++bi)
    f.bRow[bi] = f.cw + bi * 16 + ((lane >> 4) * 8) + (lane & 7);
  return f;
}

DEV_INLINE void zero_acc(float (&acc)[4][4][4]) {
#pragma unroll
  for (int mi = 0; mi < 4; ++mi)
#pragma unroll
    for (int ni = 0; ni < 4; ++ni)
#pragma unroll
      for (int j = 0; j < 4; ++j) acc[mi][ni][j] = 0.0f;
}

// one K-sweep (8 chunks) of A@B accumulated
DEV_INLINE void mma_pass(uint32_t aBase, uint32_t bBase, const FragIdx& f,
                         float (&acc)[4][4][4]) {
#pragma unroll
  for (int kk = 0; kk < 8; ++kk) {
    const uint32_t kb = kk * 32;
    uint32_t a[4][4];
#pragma unroll
    for (int mi = 0; mi < 4; ++mi) {
      uint32_t r = f.aRow[mi];
      uint32_t addr = aBase + r * 256 + ((kb | f.aColK) ^ ((r & 7) << 4));
      ldsm4(a[mi][0], a[mi][1], a[mi][2], a[mi][3], addr);
    }
    uint32_t b[4][2];
#pragma unroll
    for (int bi = 0; bi < 2; ++bi) {
      uint32_t r = f.bRow[bi];
      uint32_t addr = bBase + r * 256 + ((kb | f.bColK) ^ ((r & 7) << 4));
      ldsm4(b[bi * 2][0], b[bi * 2][1], b[bi * 2 + 1][0], b[bi * 2 + 1][1],
            addr);
    }
#pragma unroll
    for (int mi = 0; mi < 4; ++mi)
#pragma unroll
      for (int ni = 0; ni < 4; ++ni)
        mma_f16(acc[mi][ni], a[mi][0], a[mi][1], a[mi][2], a[mi][3],
                b[ni][0], b[ni][1]);
  }
}

DEV_INLINE void store_acc_global(float* Out, int rowBase, int lane, int wid,
                                 float (&acc)[4][4][4]) {
  const int rw = (wid & 1) * 64, cw = (wid >> 1) * 32;
  const int r0 = lane >> 2, c0 = (lane & 3) * 2;
#pragma unroll
  for (int mi = 0; mi < 4; ++mi)
#pragma unroll
    for (int ni = 0; ni < 4; ++ni) {
      int grow = rowBase + rw + mi * 16 + r0;
      int gcol = cw + ni * 8 + c0;
      *(float2*)(Out + (size_t)grow * C + gcol) =
          make_float2(acc[mi][ni][0], acc[mi][ni][1]);
      *(float2*)(Out + (size_t)(grow + 8) * C + gcol) =
          make_float2(acc[mi][ni][2], acc[mi][ni][3]);
    }
}

DEV_INLINE float wsum(float v) {
#pragma unroll
  for (int o = 16; o > 0; o >>= 1) v += __shfl_xor_sync(0xffffffffu, v, o);
  return v;
}

// ---------------------------------------------------------------------------
// standalone GEMM (input stage, 2-pass): Out = A@(Wh+Wl)^T. 96 KB -> 2 CTA/SM.
// ---------------------------------------------------------------------------
constexpr int SMEM_MMA_BYTES = 3 * TILE_BYTES;  // 96 KB

__global__ void __launch_bounds__(256, 2) gemm_mma(
    const __half* __restrict__ A, const __half* __restrict__ Bh,
    const __half* __restrict__ Bl, float* __restrict__ Out) {
  extern __shared__ __align__(16) char smem[];
  const uint32_t sbase = smem_u32(smem);
  const int tid = threadIdx.x, lane = tid & 31, wid = tid >> 5;
  const int rowBase = blockIdx.x * 128;

  stage_async(sbase, A + (size_t)rowBase * C, tid);
  stage_async(sbase + TILE_BYTES, Bh, tid);
  stage_async(sbase + 2 * TILE_BYTES, Bl, tid);
  CP_COMMIT();
  CP_WAIT(0);
  __syncthreads();

  FragIdx f = frag_idx(lane, wid);
  float acc[4][4][4];
  zero_acc(acc);
  mma_pass(sbase, sbase + TILE_BYTES, f, acc);
  mma_pass(sbase, sbase + 2 * TILE_BYTES, f, acc);
  store_acc_global(Out, rowBase, lane, wid, acc);
}

// ---------------------------------------------------------------------------
// fused block tail: prologue GN(temp)+relu -> fp16 A tile (smem only),
// single-pass ctr2 MMA (Wh only), epilogue rowwise GN + identity + relu,
// fp16 split, zero temp. Y2 fp32 staged into tiles 1-2 (W region dead).
// ---------------------------------------------------------------------------
__global__ void __launch_bounds__(256, 2) gn_gemm_gn_kernel(
    const float* __restrict__ Xin,                        // temp (post-atomics)
    const float* __restrict__ G1v, const float* __restrict__ B1v,
    const __half* __restrict__ Bh,
    const float* __restrict__ G2v, const float* __restrict__ B2v,
    const float* __restrict__ Id, float* __restrict__ OutF,
    __half* __restrict__ Aout, float* __restrict__ TPz) {
  extern __shared__ __align__(16) char smem[];
  const uint32_t sbase = smem_u32(smem);
  const int tid = threadIdx.x, lane = tid & 31, wid = tid >> 5;
  const int rowBase = blockIdx.x * 128;

  // W staged while prologue computes
  stage_async(sbase + TILE_BYTES, Bh, tid);
  CP_COMMIT();

  // prologue: rowwise GN+relu of Xin -> swizzled fp16 A tile
  {
    float4 g1 = ((const float4*)G1v)[lane];
    float4 b1 = ((const float4*)B1v)[lane];
#pragma unroll 4
    for (int i = 0; i < 16; ++i) {
      int r = wid * 16 + i;
      float4 x = *(const float4*)(Xin + (size_t)(rowBase + r) * C + lane * 4);
      float s = wsum(x.x + x.y + x.z + x.w);
      float q = wsum(x.x * x.x + x.y * x.y + x.z * x.z + x.w * x.w);
      float mu = s * (1.0f / 128.0f);
      float rs = rsqrtf(q * (1.0f / 128.0f) - mu * mu + 1e-5f);
      float ox = fmaxf((x.x - mu) * rs * g1.x + b1.x, 0.0f);
      float oy = fmaxf((x.y - mu) * rs * g1.y + b1.y, 0.0f);
      float oz = fmaxf((x.z - mu) * rs * g1.z + b1.z, 0.0f);
      float ow = fmaxf((x.w - mu) * rs * g1.w + b1.w, 0.0f);
      __half2 h0 = __floats2half2_rn(ox, oy);
      __half2 h1 = __floats2half2_rn(oz, ow);
      uint32_t off = r * 256 + ((lane * 8) ^ ((r & 7) << 4));
      *(uint2*)(smem + off) = make_uint2(*(uint32_t*)&h0, *(uint32_t*)&h1);
    }
  }
  CP_WAIT(0);
  __syncthreads();

  FragIdx f = frag_idx(lane, wid);
  float acc[4][4][4];
  zero_acc(acc);
  mma_pass(sbase, sbase + TILE_BYTES, f, acc);
  __syncthreads();  // all warps done with W smem

  // stage Y2 fp32 into tiles 1-2 (64 KB): 128 rows x 512B, XOR swizzle
  {
    const int rw = (wid & 1) * 64, cw = (wid >> 1) * 32;
    const int r0 = lane >> 2, c0 = (lane & 3) * 2;
#pragma unroll
    for (int mi = 0; mi < 4; ++mi)
#pragma unroll
      for (int ni = 0; ni < 4; ++ni) {
        int row = rw + mi * 16 + r0, col = cw + ni * 8 + c0;
        uint32_t o1 = row * 512 + ((col * 4) ^ ((row & 7) << 4));
        *(float2*)(smem + TILE_BYTES + o1) =
            make_float2(acc[mi][ni][0], acc[mi][ni][1]);
        uint32_t o2 = (row + 8) * 512 + ((col * 4) ^ (((row + 8) & 7) << 4));
        *(float2*)(smem + TILE_BYTES + o2) =
            make_float2(acc[mi][ni][2], acc[mi][ni][3]);
      }
  }
  __syncthreads();

  // epilogue: read at PHYSICAL lane*16; logical col = (lane*16 ^ ((r&7)<<4))/4
#pragma unroll 2
  for (int i = 0; i < 16; ++i) {
    int r = wid * 16 + i;
    float4 y = *(float4*)(smem + TILE_BYTES + r * 512 + lane * 16);
    float s = wsum(y.x + y.y + y.z + y.w);
    float q = wsum(y.x * y.x + y.y * y.y + y.z * y.z + y.w * y.w);
    float mu = s * (1.0f / 128.0f);
    float rs = rsqrtf(q * (1.0f / 128.0f) - mu * mu + 1e-5f);
    int colb = ((lane * 16) ^ ((r & 7) << 4)) >> 2;
    float4 g2 = *(const float4*)(G2v + colb);
    float4 b2 = *(const float4*)(B2v + colb);
    size_t goff = (size_t)(rowBase + r) * C + colb;
    float4 id = *(const float4*)(Id + goff);
    float4 o;
    o.x = fmaxf((y.x - mu) * rs * g2.x + b2.x + id.x, 0.0f);
    o.y = fmaxf((y.y - mu) * rs * g2.y + b2.y + id.y, 0.0f);
    o.z = fmaxf((y.z - mu) * rs * g2.z + b2.z + id.z, 0.0f);
    o.w = fmaxf((y.w - mu) * rs * g2.w + b2.w + id.w, 0.0f);
    *(float4*)(OutF + goff) = o;
    if (Aout) {
      __half2 h0 = __floats2half2_rn(o.x, o.y);
      __half2 h1 = __floats2half2_rn(o.z, o.w);
      *(uint2*)(Aout + goff) = make_uint2(*(uint32_t*)&h0, *(uint32_t*)&h1);
    }
    if (TPz) *(float4*)(TPz + goff) = make_float4(0.f, 0.f, 0.f, 0.f);
  }
}

// ---------------------------------------------------------------------------
// fused per-block kernel:
//  it=0: ctr GEMM, own-row red.add into zeroed TP
//  it=1..12: pre/suc edge-GEMMs, sorted-edge smem scatter
//  it=13,14: left/right GATHER mode — only NCHUNK CTAs active; gather A[v]
//            rows for chunk (cp.async during previous scatter), GEMM, scatter
//            row r -> u[r]. Inactive CTAs exit after it=12.
// ---------------------------------------------------------------------------
constexpr int YPITCH_H = 136;
constexpr int W_OFF   = TILE_BYTES;       // 32768
constexpr int Y_OFF   = 2 * TILE_BYTES;   // 65536
constexpr int IDX_OFF = Y_OFF + 128 * YPITCH_H * 2;      // 100352
constexpr int CMP_OFF = IDX_OFF + 2 * IDX_CAP * 4;       // 104448
constexpr int SMEM_FUSED = CMP_OFF + 4 * 128 * 4;        // 106496

__global__ void __launch_bounds__(256, 2) fused_block_kernel(
    const __half* __restrict__ A, int ib, float* __restrict__ TP,
    const int* __restrict__ left_u, const int* __restrict__ left_v,
    const int* __restrict__ right_u, const int* __restrict__ right_v) {
  extern __shared__ __align__(16) char smem[];
  const uint32_t sbase = smem_u32(smem);
  __half* Ybuf = (__half*)(smem + Y_OFF);
  const int tid = threadIdx.x, lane = tid & 31, wid = tid >> 5;
  const int rowBase = blockIdx.x * 128;
  const bool activeCmp = blockIdx.x < NCHUNK;
  const int itMax = activeCmp ? 15 : 13;

  const int rw = (wid & 1) * 64, cw = (wid >> 1) * 32;
  const int r0 = lane >> 2, c0 = (lane & 3) * 2;

  auto slot_of = [&](int it) {
    return (it == 0)   ? 2 + ib
           : (it < 7)  ? 6 + ib * 6 + (it - 1)
           : (it < 13) ? 30 + ib * 6 + (it - 7)
           : (it == 13) ? 54 + ib : 58 + ib;
  };
  auto ebase_of = [&](int it) { return (it - 1) * E; };
  auto stage_idx = [&](int it) {
    int l = it - 1;
    int o0 = g_off[l * (NT + 1) + blockIdx.x];
    int o1 = g_off[l * (NT + 1) + blockIdx.x + 1];
    int cnt = min(o1 - o0, IDX_CAP);
    const int* src = g_epk + ebase_of(it) + o0;
    uint32_t dst = sbase + IDX_OFF + (it & 1) * (IDX_CAP * 4);
    for (int j = tid; j < cnt; j += 256) cp_async4(dst + j * 4, src + j);
  };
  // gather 128 rows A[v[r]] into the A-tile region (dead after it=12 MMA)
  auto stage_gather = [&](int voff) {
    const int* vs = (const int*)(smem + CMP_OFF + voff);
#pragma unroll
    for (int t2 = 0; t2 < 8; ++t2) {
      int idx = tid + t2 * 256;
      int row = idx >> 4, c16 = idx & 15;
      int vrow = vs[row];
      uint32_t off = row * 256 + ((c16 * 16) ^ ((row & 7) << 4));
      cp_async16(sbase + off, A + (size_t)vrow * C + c16 * 8);
    }
  };

  // initial staging: own A tile, W(0), idx(1), compact u/v segments
  stage_async(sbase, A + (size_t)rowBase * C, tid);
  stage_async(sbase + W_OFF, g_Wh + (size_t)slot_of(0) * CC, tid);
  stage_idx(1);
  if (activeCmp) {
    int cb = blockIdx.x * 128;
    for (int j = tid; j < 128; j += 256) {
      cp_async4(sbase + CMP_OFF + j * 4, left_u + cb + j);
      cp_async4(sbase + CMP_OFF + 512 + j * 4, left_v + cb + j);
      cp_async4(sbase + CMP_OFF + 1024 + j * 4, right_u + cb + j);
      cp_async4(sbase + CMP_OFF + 1536 + j * 4, right_v + cb + j);
    }
  }
  CP_COMMIT();
  CP_WAIT(0);
  __syncthreads();

  FragIdx f = frag_idx(lane, wid);

#pragma unroll 1
  for (int it = 0; it < itMax; ++it) {
    float acc[4][4][4];
    zero_acc(acc);
    mma_pass(sbase, sbase + W_OFF, f, acc);

#pragma unroll
    for (int mi = 0; mi < 4; ++mi)
#pragma unroll
      for (int ni = 0; ni < 4; ++ni) {
        int row = rw + mi * 16 + r0, col = cw + ni * 8 + c0;
        __half2 h0 = __floats2half2_rn(acc[mi][ni][0], acc[mi][ni][1]);
        __half2 h1 = __floats2half2_rn(acc[mi][ni][2], acc[mi][ni][3]);
        *(__half2*)(Ybuf + row * YPITCH_H + col) = h0;
        *(__half2*)(Ybuf + (row + 8) * YPITCH_H + col) = h1;
      }
    __syncthreads();  // Ybuf ready; W(it) + A region fully consumed

    if (it + 1 < itMax) {
      stage_async(sbase + W_OFF, g_Wh + (size_t)slot_of(it + 1) * CC, tid);
      if (it + 1 <= 12) stage_idx(it + 1);
      else stage_gather(it + 1 == 13 ? 512 : 1536);
      CP_COMMIT();
    }

    if (it == 0) {
      // ctr: add own 128 rows into (pre-zeroed) TP
      for (int r = wid; r < 128; r += 8) {
        uint2 hv = *(uint2*)(Ybuf + r * YPITCH_H + lane * 4);
        float2 f0 = __half22float2(*(__half2*)&hv.x);
        float2 f1 = __half22float2(*(__half2*)&hv.y);
        float* p = TP + (size_t)(rowBase + r) * C + lane * 4;
        asm volatile("red.global.add.v4.f32 [%0], {%1,%2,%3,%4};"
                     :: "l"(p), "f"(f0.x), "f"(f0.y), "f"(f1.x), "f"(f1.y)
                     : "memory");
      }
    } else if (it <= 12) {
      int l = it - 1;
      int o0 = g_off[l * (NT + 1) + blockIdx.x];
      int o1 = g_off[l * (NT + 1) + blockIdx.x + 1];
      int cnt = o1 - o0;
      const int* sidx = (const int*)(smem + IDX_OFF + (it & 1) * (IDX_CAP * 4));
      const int* gidx = g_epk + ebase_of(it) + o0;
#pragma unroll 2
      for (int j = wid; j < cnt; j += 8) {
        int pk = (j < IDX_CAP) ? sidx[j] : __ldg(&gidx[j]);
        int vl = pk & 127;
        int uu = pk >> 7;
        uint2 hv = *(uint2*)(Ybuf + vl * YPITCH_H + lane * 4);
        float2 f0 = __half22float2(*(__half2*)&hv.x);
        float2 f1 = __half22float2(*(__half2*)&hv.y);
        float* p = TP + (size_t)uu * C + lane * 4;
        asm volatile("red.global.add.v4.f32 [%0], {%1,%2,%3,%4};"
                     :: "l"(p), "f"(f0.x), "f"(f0.y), "f"(f1.x), "f"(f1.y)
                     : "memory");
      }
    } else {
      // compact left/right: row r of Ybuf -> TP[u[r]]
      const int* uarr =
          (const int*)(smem + CMP_OFF + (it == 13 ? 0 : 1024));
      for (int r = wid; r < 128; r += 8) {
        int uu = uarr[r];
        uint2 hv = *(uint2*)(Ybuf + r * YPITCH_H + lane * 4);
        float2 f0 = __half22float2(*(__half2*)&hv.x);
        float2 f1 = __half22float2(*(__half2*)&hv.y);
        float* p = TP + (size_t)uu * C + lane * 4;
        asm volatile("red.global.add.v4.f32 [%0], {%1,%2,%3,%4};"
                     :: "l"(p), "f"(f0.x), "f"(f0.y), "f"(f1.x), "f"(f1.y)
                     : "memory");
      }
    }

    if (it + 1 < itMax) CP_WAIT(0);
    __syncthreads();
  }
}

// ---------------------------------------------------------------------------
// edge sort (counting sort by v>>7) for the 12 pre/suc lists
// ---------------------------------------------------------------------------
__global__ void zero_cnt_kernel() {
  int i = blockIdx.x * 256 + threadIdx.x;
  if (i < NLS * NT) g_cnt[i] = 0;
}
__global__ void hist_all_kernel(const int* __restrict__ pre_v,
                                const int* __restrict__ suc_v) {
  int e = blockIdx.x * 256 + threadIdx.x;
  if (e >= 12 * E) return;
  int l = e / E;
  const int* vp = (l < 6) ? pre_v : suc_v;
  int off = (l < 6) ? e : e - 6 * E;
  atomicAdd(&g_cnt[l * NT + (__ldg(&vp[off]) >> 7)], 1);
}
__global__ void prefix_kernel() {  // one block per list, 1024 threads
  __shared__ int sh[NT];
  int l = blockIdx.x, t = threadIdx.x;
  sh[t] = g_cnt[l * NT + t];
  __syncthreads();
#pragma unroll
  for (int d = 1; d < NT; d <<= 1) {
    int x = (t >= d) ? sh[t - d] : 0;
    __syncthreads();
    sh[t] += x;
    __syncthreads();
  }
  g_off[l * (NT + 1) + t + 1] = sh[t];
  if (t == 0) g_off[l * (NT + 1)] = 0;
}
__global__ void fill_all_kernel(const int* __restrict__ pre_u,
                                const int* __restrict__ pre_v,
                                const int* __restrict__ suc_u,
                                const int* __restrict__ suc_v) {
  int e = blockIdx.x * 256 + threadIdx.x;
  if (e >= 12 * E) return;
  int l = e / E;
  const int* vp = (l < 6) ? pre_v : suc_v;
  const int* up = (l < 6) ? pre_u : suc_u;
  int off = (l < 6) ? e : e - 6 * E;
  int vv = __ldg(&vp[off]);
  int t = vv >> 7;
  int pos = l * E + g_off[l * (NT + 1) + t] + atomicAdd(&g_cnt[l * NT + t], 1);
  g_epk[pos] = (__ldg(&up[off]) << 7) | (vv & 127);
}

// ---------------------------------------------------------------------------
// setup: weight split + transpose, all 66 slots in one kernel
// ---------------------------------------------------------------------------
__global__ void wsplit_all_kernel(const float* __restrict__ ic_w1,
                                  const float* __restrict__ if_w1,
                                  const float* __restrict__ ctr_w,
                                  const float* __restrict__ pre_w,
                                  const float* __restrict__ suc_w,
                                  const float* __restrict__ left_w,
                                  const float* __restrict__ right_w,
                                  const float* __restrict__ ctr2_w) {
  int idx = blockIdx.x * 256 + threadIdx.x;  // NSLOT * 16384
  int slot = idx >> 14, r = idx & 16383;
  int c = r >> 7, k = r & 127;
  const float* src; int m;
  if (slot < 1)       { src = ic_w1;  m = 0; }
  else if (slot < 2)  { src = if_w1;  m = 0; }
  else if (slot < 6)  { src = ctr_w;  m = slot - 2; }
  else if (slot < 30) { src = pre_w;  m = slot - 6; }
  else if (slot < 54) { src = suc_w;  m = slot - 30; }
  else if (slot < 58) { src = left_w; m = slot - 54; }
  else if (slot < 62) { src = right_w; m = slot - 58; }
  else                { src = ctr2_w; m = slot - 62; }
  float w = src[(size_t)m * CC + k * 128 + c];
  __half hi = __float2half_rn(w);
  __half lo = __float2half_rn(w - __half2float(hi));
  size_t o = (size_t)slot * CC + r;
  g_Wh[o] = hi;
  g_Wl[o] = lo;
}

// ---------------------------------------------------------------------------
// elementwise kernels (input stage)
// ---------------------------------------------------------------------------
DEV_INLINE void h4_store(__half* H, size_t idx4, float4 o) {
  __half2 a = __floats2half2_rn(o.x, o.y);
  __half2 b = __floats2half2_rn(o.z, o.w);
  *(uint2*)(H + idx4) = make_uint2(*(uint32_t*)&a, *(uint32_t*)&b);
}

__global__ void mlp0_kernel(const float* __restrict__ X2,
                            const float* __restrict__ W0,
                            const float* __restrict__ B0,
                            __half* __restrict__ H) {
  int idx = blockIdx.x * 256 + threadIdx.x;  // N*64
  int n = idx >> 6, c = (idx & 63) << 1;
  float x0 = X2[2 * n], x1 = X2[2 * n + 1];
  float ha = fmaxf(fmaf(x0, W0[c], fmaf(x1, W0[C + c], B0[c])), 0.0f);
  float hb = fmaxf(fmaf(x0, W0[c + 1], fmaf(x1, W0[C + c + 1], B0[c + 1])), 0.0f);
  *(__half2*)(H + (size_t)n * C + c) = __floats2half2_rn(ha, hb);
}

// feat = relu(GN(Y1)+GN(Y2)); writes fp32 FT + fp16 split + zeroes TP
__global__ void combine_kernel(const float* __restrict__ Y1,
                               const float* __restrict__ Y2,
                               const float* __restrict__ G1,
                               const float* __restrict__ B1,
                               const float* __restrict__ G2,
                               const float* __restrict__ B2,
                               float* __restrict__ Of,
                               __half* __restrict__ H,
                               float* __restrict__ TPz) {
  int w = (blockIdx.x * blockDim.x + threadIdx.x) >> 5;
  int lane = threadIdx.x & 31;
  size_t idx = (size_t)w * 32 + lane;
  float4 x1 = ((const float4*)Y1)[idx];
  float4 x2 = ((const float4*)Y2)[idx];
  float s1 = wsum(x1.x + x1.y + x1.z + x1.w);
  float q1 = wsum(x1.x * x1.x + x1.y * x1.y + x1.z * x1.z + x1.w * x1.w);
  float s2 = wsum(x2.x + x2.y + x2.z + x2.w);
  float q2 = wsum(x2.x * x2.x + x2.y * x2.y + x2.z * x2.z + x2.w * x2.w);
  float mu1 = s1 * (1.0f / 128.0f);
  float rs1 = rsqrtf(q1 * (1.0f / 128.0f) - mu1 * mu1 + 1e-5f);
  float mu2 = s2 * (1.0f / 128.0f);
  float rs2 = rsqrtf(q2 * (1.0f / 128.0f) - mu2 * mu2 + 1e-5f);
  float4 g1 = ((const float4*)G1)[lane];
  float4 b1 = ((const float4*)B1)[lane];
  float4 g2 = ((const float4*)G2)[lane];
  float4 b2 = ((const float4*)B2)[lane];
  float4 o;
  o.x = fmaxf((x1.x - mu1) * rs1 * g1.x + b1.x + (x2.x - mu2) * rs2 * g2.x + b2.x, 0.0f);
  o.y = fmaxf((x1.y - mu1) * rs1 * g1.y + b1.y + (x2.y - mu2) * rs2 * g2.y + b2.y, 0.0f);
  o.z = fmaxf((x1.z - mu1) * rs1 * g1.z + b1.z + (x2.z - mu2) * rs2 * g2.z + b2.z, 0.0f);
  o.w = fmaxf((x1.w - mu1) * rs1 * g1.w + b1.w + (x2.w - mu2) * rs2 * g2.w + b2.w, 0.0f);
  ((float4*)Of)[idx] = o;
  h4_store(H, idx * 4, o);
  ((float4*)TPz)[idx] = make_float4(0.f, 0.f, 0.f, 0.f);
}

// ---------------------------------------------------------------------------
extern "C" void kernel_launch(void* const* d_in, const int* in_sizes, int n_in,
                              void* d_out, int out_size) {
  const float* ctrs   = (const float*)d_in[0];
  const float* feats  = (const float*)d_in[1];
  const int*   pre_u  = (const int*)d_in[2];
  const int*   pre_v  = (const int*)d_in[3];
  const int*   suc_u  = (const int*)d_in[4];
  const int*   suc_v  = (const int*)d_in[5];
  const int*   left_u = (const int*)d_in[6];
  const int*   left_v = (const int*)d_in[7];
  const int*   right_u= (const int*)d_in[8];
  const int*   right_v= (const int*)d_in[9];
  const float* ic_w0  = (const float*)d_in[10];
  const float* ic_b0  = (const float*)d_in[11];
  const float* ic_w1  = (const float*)d_in[12];
  const float* ic_g   = (const float*)d_in[13];
  const float* ic_bt  = (const float*)d_in[14];
  const float* if_w0  = (const float*)d_in[15];
  const float* if_b0  = (const float*)d_in[16];
  const float* if_w1  = (const float*)d_in[17];
  const float* if_g   = (const float*)d_in[18];
  const float* if_bt  = (const float*)d_in[19];
  const float* ctr_w  = (const float*)d_in[20];
  const float* pre_w  = (const float*)d_in[21];
  const float* suc_w  = (const float*)d_in[22];
  const float* left_w = (const float*)d_in[23];
  const float* right_w= (const float*)d_in[24];
  const float* norm_g = (const float*)d_in[25];
  const float* norm_b = (const float*)d_in[26];
  const float* ctr2_w = (const float*)d_in[27];
  const float* ctr2_g = (const float*)d_in[28];
  const float* ctr2_b = (const float*)d_in[29];
  float* out = (float*)d_out;

  float *FT, *TP, *YB;
  __half *AA, *WH, *WL;
  cudaGetSymbolAddress((void**)&FT, g_feat);
  cudaGetSymbolAddress((void**)&TP, g_temp);
  cudaGetSymbolAddress((void**)&YB, g_Y);
  cudaGetSymbolAddress((void**)&AA, g_A);
  cudaGetSymbolAddress((void**)&WH, g_Wh);
  cudaGetSymbolAddress((void**)&WL, g_Wl);

  cudaFuncSetAttribute(gemm_mma, cudaFuncAttributeMaxDynamicSharedMemorySize,
                       SMEM_MMA_BYTES);
  cudaFuncSetAttribute(gn_gemm_gn_kernel,
                       cudaFuncAttributeMaxDynamicSharedMemorySize,
                       SMEM_MMA_BYTES);
  cudaFuncSetAttribute(fused_block_kernel,
                       cudaFuncAttributeMaxDynamicSharedMemorySize, SMEM_FUSED);

  const int GEMM_GRID = N / 128;
  const int ROW_GRID  = N / 8;
  const int MLP_GRID  = (N * 64) / 256;
  const int ZG = (NLS * NT + 255) / 256;
  const int EG = (12 * E + 255) / 256;

  // ---- setup: weight split (1 launch) + edge sort (4 launches) ----
  wsplit_all_kernel<<<NSLOT * 64, 256>>>(ic_w1, if_w1, ctr_w, pre_w, suc_w,
                                         left_w, right_w, ctr2_w);
  zero_cnt_kernel<<<ZG, 256>>>();
  hist_all_kernel<<<EG, 256>>>(pre_v, suc_v);
  prefix_kernel<<<NLS, NT>>>();
  zero_cnt_kernel<<<ZG, 256>>>();
  fill_all_kernel<<<EG, 256>>>(pre_u, pre_v, suc_u, suc_v);

#define GEMM2(slot, OutPtr)                                                  \
  gemm_mma<<<GEMM_GRID, 256, SMEM_MMA_BYTES>>>(                              \
      AA, WH + (size_t)(slot) * CC, WL + (size_t)(slot) * CC, OutPtr)

  // ---- Input stage ----
  mlp0_kernel<<<MLP_GRID, 256>>>(ctrs, ic_w0, ic_b0, AA);
  GEMM2(0, FT);
  mlp0_kernel<<<MLP_GRID, 256>>>(feats, if_w0, if_b0, AA);
  GEMM2(1, YB);
  combine_kernel<<<ROW_GRID, 256>>>(FT, YB, ic_g, ic_bt, if_g, if_bt, FT, AA,
                                    TP);

  // ---- 4 fusion blocks: 2 kernels each ----
  for (int i = 0; i < NB; ++i) {
    fused_block_kernel<<<GEMM_GRID, 256, SMEM_FUSED>>>(AA, i, TP, left_u,
                                                       left_v, right_u,
                                                       right_v);

    if (i == NB - 1) {
      gn_gemm_gn_kernel<<<GEMM_GRID, 256, SMEM_MMA_BYTES>>>(
          TP, norm_g + (size_t)i * C, norm_b + (size_t)i * C,
          WH + (size_t)(62 + i) * CC, ctr2_g + (size_t)i * C,
          ctr2_b + (size_t)i * C, FT, out, nullptr, nullptr);
    } else {
      gn_gemm_gn_kernel<<<GEMM_GRID, 256, SMEM_MMA_BYTES>>>(
          TP, norm_g + (size_t)i * C, norm_b + (size_t)i * C,
          WH + (size_t)(62 + i) * CC, ctr2_g + (size_t)i * C,
          ctr2_b + (size_t)i * C, FT, FT, AA, TP);
    }
  }
#undef GEMM2
}

// round 14
// speedup vs baseline: 3.6053x; 1.0884x over previous
#include <cuda_runtime.h>
#include <cuda_fp16.h>
#include <cstdint>

#define DEV_INLINE __device__ __forceinline__

constexpr int N  = 131072;
constexpr int C  = 128;
constexpr int S  = 6;
constexpr int E  = 131072;
constexpr int EL = 32768;
constexpr int NB = 4;
constexpr int CC = C * C;
constexpr int NSLOT = 66;
constexpr int NT = 1024;   // source row tiles (N/128)
constexpr int NLS = 12;    // sorted edge lists: 0-5 pre, 6-11 suc
constexpr int ESTORE = 12 * E;
constexpr int IDX_CAP = 512;   // smem-resident edges per (tile, list)
constexpr int NCHUNK = EL / 128;  // 256 compact chunks for left/right

// Scratch (allocation-free rule: static __device__ arrays)
__device__ float  g_feat[N * C];
__device__ float  g_temp[N * C];
__device__ float  g_Y[N * C];
__device__ __half g_A[N * C];           // fp16 activations
__device__ __half g_Wh[NSLOT * CC];     // fp16 weight hi, [slot][c][k] (transposed)
__device__ __half g_Wl[NSLOT * CC];     // fp16 weight lo (unused now; kept for layout)
// edge sort scratch
__device__ int g_cnt[NLS * NT];
__device__ int g_off[NLS * (NT + 1)];
__device__ int g_epk[ESTORE];  // packed edge: (u << 7) | (v & 127)

DEV_INLINE uint32_t smem_u32(const void* p) {
  uint32_t a;
  asm("{ .reg .u64 t; cvta.to.shared.u64 t, %1; cvt.u32.u64 %0, t; }"
      : "=r"(a) : "l"(p));
  return a;
}

// ---------------------------------------------------------------------------
// MMA building blocks. smem tile: 128 rows x 256B, XOR-16B swizzle on (row&7)
// ---------------------------------------------------------------------------
constexpr int TILE_BYTES = 128 * 256;  // 32 KB (128x128 fp16)

DEV_INLINE void ldsm4(uint32_t& r0, uint32_t& r1, uint32_t& r2, uint32_t& r3,
                      uint32_t addr) {
  asm volatile("ldmatrix.sync.aligned.m8n8.x4.shared.b16 {%0,%1,%2,%3}, [%4];"
               : "=r"(r0), "=r"(r1), "=r"(r2), "=r"(r3) : "r"(addr));
}
DEV_INLINE void mma_f16(float* c, uint32_t a0, uint32_t a1, uint32_t a2,
                        uint32_t a3, uint32_t b0, uint32_t b1) {
  asm volatile(
      "mma.sync.aligned.m16n8k16.row.col.f32.f16.f16.f32 "
      "{%0,%1,%2,%3}, {%4,%5,%6,%7}, {%8,%9}, {%0,%1,%2,%3};"
      : "+f"(c[0]), "+f"(c[1]), "+f"(c[2]), "+f"(c[3])
      : "r"(a0), "r"(a1), "r"(a2), "r"(a3), "r"(b0), "r"(b1));
}

DEV_INLINE void cp_async16(uint32_t dst, const void* src) {
  asm volatile("cp.async.cg.shared.global [%0], [%1], 16;" :: "r"(dst),
               "l"(src));
}
DEV_INLINE void cp_async4(uint32_t dst, const void* src) {
  asm volatile("cp.async.ca.shared.global [%0], [%1], 4;" :: "r"(dst),
               "l"(src));
}
#define CP_COMMIT() asm volatile("cp.async.commit_group;" ::: "memory")
#define CP_WAIT(n)  asm volatile("cp.async.wait_group %0;" :: "n"(n) : "memory")

// stage one 128x128 fp16 tile (32 KB) with swizzle via cp.async; 256 threads
DEV_INLINE void stage_async(uint32_t dstBase, const __half* src, int tid) {
  const char* s = (const char*)src;
#pragma unroll
  for (int t = 0; t < 8; ++t) {
    int idx = tid + t * 256;
    int r = idx >> 4, c16 = idx & 15;
    uint32_t off = r * 256 + ((c16 * 16) ^ ((r & 7) << 4));
    cp_async16(dstBase + off, s + idx * 16);
  }
}

// fragment address precompute
struct FragIdx {
  uint32_t aRow[4], aColK, bRow[2], bColK;
  int rw, cw;
};
DEV_INLINE FragIdx frag_idx(int lane, int wid) {
  FragIdx f;
  f.rw = (wid & 1) * 64;
  f.cw = (wid >> 1) * 32;
  f.aColK = (lane >> 4) * 16;
#pragma unroll
  for (int mi = 0; mi < 4; ++mi) f.aRow[mi] = f.rw + mi * 16 + (lane & 15);
  f.bColK = ((lane >> 3) & 1) * 16;
#pragma unroll
  for (int bi = 0; bi < 2; ++bi)
    f.bRow[bi] = f.cw + bi * 16 + ((lane >> 4) * 8) + (lane & 7);
  return f;
}

DEV_INLINE void zero_acc(float (&acc)[4][4][4]) {
#pragma unroll
  for (int mi = 0; mi < 4; ++mi)
#pragma unroll
    for (int ni = 0; ni < 4; ++ni)
#pragma unroll
      for (int j = 0; j < 4; ++j) acc[mi][ni][j] = 0.0f;
}

// one K-sweep (8 chunks) of A@B accumulated
DEV_INLINE void mma_pass(uint32_t aBase, uint32_t bBase, const FragIdx& f,
                         float (&acc)[4][4][4]) {
#pragma unroll
  for (int kk = 0; kk < 8; ++kk) {
    const uint32_t kb = kk * 32;
    uint32_t a[4][4];
#pragma unroll
    for (int mi = 0; mi < 4; ++mi) {
      uint32_t r = f.aRow[mi];
      uint32_t addr = aBase + r * 256 + ((kb | f.aColK) ^ ((r & 7) << 4));
      ldsm4(a[mi][0], a[mi][1], a[mi][2], a[mi][3], addr);
    }
    uint32_t b[4][2];
#pragma unroll
    for (int bi = 0; bi < 2; ++bi) {
      uint32_t r = f.bRow[bi];
      uint32_t addr = bBase + r * 256 + ((kb | f.bColK) ^ ((r & 7) << 4));
      ldsm4(b[bi * 2][0], b[bi * 2][1], b[bi * 2 + 1][0], b[bi * 2 + 1][1],
            addr);
    }
#pragma unroll
    for (int mi = 0; mi < 4; ++mi)
#pragma unroll
      for (int ni = 0; ni < 4; ++ni)
        mma_f16(acc[mi][ni], a[mi][0], a[mi][1], a[mi][2], a[mi][3],
                b[ni][0], b[ni][1]);
  }
}

DEV_INLINE void store_acc_global(float* Out, int rowBase, int lane, int wid,
                                 float (&acc)[4][4][4]) {
  const int rw = (wid & 1) * 64, cw = (wid >> 1) * 32;
  const int r0 = lane >> 2, c0 = (lane & 3) * 2;
#pragma unroll
  for (int mi = 0; mi < 4; ++mi)
#pragma unroll
    for (int ni = 0; ni < 4; ++ni) {
      int grow = rowBase + rw + mi * 16 + r0;
      int gcol = cw + ni * 8 + c0;
      *(float2*)(Out + (size_t)grow * C + gcol) =
          make_float2(acc[mi][ni][0], acc[mi][ni][1]);
      *(float2*)(Out + (size_t)(grow + 8) * C + gcol) =
          make_float2(acc[mi][ni][2], acc[mi][ni][3]);
    }
}

// stage accumulators as fp32 into smem base 0: 128 rows x 512B, XOR swizzle
DEV_INLINE void stage_acc_smem(char* smem, int lane, int wid,
                               float (&acc)[4][4][4]) {
  const int rw = (wid & 1) * 64, cw = (wid >> 1) * 32;
  const int r0 = lane >> 2, c0 = (lane & 3) * 2;
#pragma unroll
  for (int mi = 0; mi < 4; ++mi)
#pragma unroll
    for (int ni = 0; ni < 4; ++ni) {
      int row = rw + mi * 16 + r0, col = cw + ni * 8 + c0;
      uint32_t o1 = row * 512 + ((col * 4) ^ ((row & 7) << 4));
      *(float2*)(smem + o1) = make_float2(acc[mi][ni][0], acc[mi][ni][1]);
      uint32_t o2 = (row + 8) * 512 + ((col * 4) ^ (((row + 8) & 7) << 4));
      *(float2*)(smem + o2) = make_float2(acc[mi][ni][2], acc[mi][ni][3]);
    }
}

DEV_INLINE float wsum(float v) {
#pragma unroll
  for (int o = 16; o > 0; o >>= 1) v += __shfl_xor_sync(0xffffffffu, v, o);
  return v;
}

// mlp layer-0 prologue: relu(x@W0 + b0) for this CTA's 128 rows -> fp16 A tile
DEV_INLINE void mlp0_prologue(char* smem, const float* X2, const float* W0,
                              const float* B0, int rowBase, int lane, int wid) {
  float4 wa = *(const float4*)(W0 + lane * 4);
  float4 wb = *(const float4*)(W0 + C + lane * 4);
  float4 b0 = *(const float4*)(B0 + lane * 4);
#pragma unroll 4
  for (int i = 0; i < 16; ++i) {
    int r = wid * 16 + i;
    float2 x = *(const float2*)(X2 + 2 * (size_t)(rowBase + r));
    float ox = fmaxf(fmaf(x.x, wa.x, fmaf(x.y, wb.x, b0.x)), 0.0f);
    float oy = fmaxf(fmaf(x.x, wa.y, fmaf(x.y, wb.y, b0.y)), 0.0f);
    float oz = fmaxf(fmaf(x.x, wa.z, fmaf(x.y, wb.z, b0.z)), 0.0f);
    float ow = fmaxf(fmaf(x.x, wa.w, fmaf(x.y, wb.w, b0.w)), 0.0f);
    __half2 h0 = __floats2half2_rn(ox, oy);
    __half2 h1 = __floats2half2_rn(oz, ow);
    uint32_t off = r * 256 + ((lane * 8) ^ ((r & 7) << 4));
    *(uint2*)(smem + off) = make_uint2(*(uint32_t*)&h0, *(uint32_t*)&h1);
  }
}

// ---------------------------------------------------------------------------
// input stage kernel 1: Y1 = relu(ctrs@w0+b0) @ Wh   (64 KB smem, 2 CTA/SM)
// ---------------------------------------------------------------------------
constexpr int SMEM_IN_BYTES = 2 * TILE_BYTES;  // 64 KB

__global__ void __launch_bounds__(256, 2) mlp_gemm_kernel(
    const float* __restrict__ X2, const float* __restrict__ W0,
    const float* __restrict__ B0, const __half* __restrict__ Bh,
    float* __restrict__ Out) {
  extern __shared__ __align__(16) char smem[];
  const uint32_t sbase = smem_u32(smem);
  const int tid = threadIdx.x, lane = tid & 31, wid = tid >> 5;
  const int rowBase = blockIdx.x * 128;

  stage_async(sbase + TILE_BYTES, Bh, tid);
  CP_COMMIT();
  mlp0_prologue(smem, X2, W0, B0, rowBase, lane, wid);
  CP_WAIT(0);
  __syncthreads();

  FragIdx f = frag_idx(lane, wid);
  float acc[4][4][4];
  zero_acc(acc);
  mma_pass(sbase, sbase + TILE_BYTES, f, acc);
  store_acc_global(Out, rowBase, lane, wid, acc);
}

// ---------------------------------------------------------------------------
// input stage kernel 2: Y2 = relu(feats@w0+b0) @ Wh, then
// feat = relu(GN1(Y1) + GN2(Y2)); writes feat fp32 + fp16 split + zeroes TP
// ---------------------------------------------------------------------------
__global__ void __launch_bounds__(256, 2) mlp_gemm_combine_kernel(
    const float* __restrict__ X2, const float* __restrict__ W0,
    const float* __restrict__ B0, const __half* __restrict__ Bh,
    const float* __restrict__ Y1,
    const float* __restrict__ G1v, const float* __restrict__ B1v,
    const float* __restrict__ G2v, const float* __restrict__ B2v,
    float* __restrict__ OutF, __half* __restrict__ Aout,
    float* __restrict__ TPz) {
  extern __shared__ __align__(16) char smem[];
  const uint32_t sbase = smem_u32(smem);
  const int tid = threadIdx.x, lane = tid & 31, wid = tid >> 5;
  const int rowBase = blockIdx.x * 128;

  stage_async(sbase + TILE_BYTES, Bh, tid);
  CP_COMMIT();
  mlp0_prologue(smem, X2, W0, B0, rowBase, lane, wid);
  CP_WAIT(0);
  __syncthreads();

  FragIdx f = frag_idx(lane, wid);
  float acc[4][4][4];
  zero_acc(acc);
  mma_pass(sbase, sbase + TILE_BYTES, f, acc);
  __syncthreads();  // A + W fully consumed

  stage_acc_smem(smem, lane, wid, acc);  // Y2 fp32 at base 0 (64 KB)
  __syncthreads();

#pragma unroll 2
  for (int i = 0; i < 16; ++i) {
    int r = wid * 16 + i;
    float4 y2 = *(float4*)(smem + r * 512 + lane * 16);
    int colb = ((lane * 16) ^ ((r & 7) << 4)) >> 2;  // logical column
    size_t goff = (size_t)(rowBase + r) * C + colb;
    float4 y1 = *(const float4*)(Y1 + goff);
    float s1 = wsum(y1.x + y1.y + y1.z + y1.w);
    float q1 = wsum(y1.x * y1.x + y1.y * y1.y + y1.z * y1.z + y1.w * y1.w);
    float s2 = wsum(y2.x + y2.y + y2.z + y2.w);
    float q2 = wsum(y2.x * y2.x + y2.y * y2.y + y2.z * y2.z + y2.w * y2.w);
    float mu1 = s1 * (1.0f / 128.0f);
    float rs1 = rsqrtf(q1 * (1.0f / 128.0f) - mu1 * mu1 + 1e-5f);
    float mu2 = s2 * (1.0f / 128.0f);
    float rs2 = rsqrtf(q2 * (1.0f / 128.0f) - mu2 * mu2 + 1e-5f);
    float4 g1 = *(const float4*)(G1v + colb);
    float4 b1 = *(const float4*)(B1v + colb);
    float4 g2 = *(const float4*)(G2v + colb);
    float4 b2 = *(const float4*)(B2v + colb);
    float4 o;
    o.x = fmaxf((y1.x - mu1) * rs1 * g1.x + b1.x + (y2.x - mu2) * rs2 * g2.x + b2.x, 0.0f);
    o.y = fmaxf((y1.y - mu1) * rs1 * g1.y + b1.y + (y2.y - mu2) * rs2 * g2.y + b2.y, 0.0f);
    o.z = fmaxf((y1.z - mu1) * rs1 * g1.z + b1.z + (y2.z - mu2) * rs2 * g2.z + b2.z, 0.0f);
    o.w = fmaxf((y1.w - mu1) * rs1 * g1.w + b1.w + (y2.w - mu2) * rs2 * g2.w + b2.w, 0.0f);
    *(float4*)(OutF + goff) = o;
    __half2 h0 = __floats2half2_rn(o.x, o.y);
    __half2 h1 = __floats2half2_rn(o.z, o.w);
    *(uint2*)(Aout + goff) = make_uint2(*(uint32_t*)&h0, *(uint32_t*)&h1);
    *(float4*)(TPz + goff) = make_float4(0.f, 0.f, 0.f, 0.f);
  }
}

// ---------------------------------------------------------------------------
// fused block tail: prologue GN(temp)+relu -> fp16 A tile, single-pass ctr2
// MMA, epilogue rowwise GN + identity + relu. Y2 fp32 staged at base 0.
// 64 KB smem.
// ---------------------------------------------------------------------------
__global__ void __launch_bounds__(256, 2) gn_gemm_gn_kernel(
    const float* __restrict__ Xin,                        // temp (post-atomics)
    const float* __restrict__ G1v, const float* __restrict__ B1v,
    const __half* __restrict__ Bh,
    const float* __restrict__ G2v, const float* __restrict__ B2v,
    const float* __restrict__ Id, float* __restrict__ OutF,
    __half* __restrict__ Aout, float* __restrict__ TPz) {
  extern __shared__ __align__(16) char smem[];
  const uint32_t sbase = smem_u32(smem);
  const int tid = threadIdx.x, lane = tid & 31, wid = tid >> 5;
  const int rowBase = blockIdx.x * 128;

  stage_async(sbase + TILE_BYTES, Bh, tid);
  CP_COMMIT();

  // prologue: rowwise GN+relu of Xin -> swizzled fp16 A tile
  {
    float4 g1 = ((const float4*)G1v)[lane];
    float4 b1 = ((const float4*)B1v)[lane];
#pragma unroll 4
    for (int i = 0; i < 16; ++i) {
      int r = wid * 16 + i;
      float4 x = *(const float4*)(Xin + (size_t)(rowBase + r) * C + lane * 4);
      float s = wsum(x.x + x.y + x.z + x.w);
      float q = wsum(x.x * x.x + x.y * x.y + x.z * x.z + x.w * x.w);
      float mu = s * (1.0f / 128.0f);
      float rs = rsqrtf(q * (1.0f / 128.0f) - mu * mu + 1e-5f);
      float ox = fmaxf((x.x - mu) * rs * g1.x + b1.x, 0.0f);
      float oy = fmaxf((x.y - mu) * rs * g1.y + b1.y, 0.0f);
      float oz = fmaxf((x.z - mu) * rs * g1.z + b1.z, 0.0f);
      float ow = fmaxf((x.w - mu) * rs * g1.w + b1.w, 0.0f);
      __half2 h0 = __floats2half2_rn(ox, oy);
      __half2 h1 = __floats2half2_rn(oz, ow);
      uint32_t off = r * 256 + ((lane * 8) ^ ((r & 7) << 4));
      *(uint2*)(smem + off) = make_uint2(*(uint32_t*)&h0, *(uint32_t*)&h1);
    }
  }
  CP_WAIT(0);
  __syncthreads();

  FragIdx f = frag_idx(lane, wid);
  float acc[4][4][4];
  zero_acc(acc);
  mma_pass(sbase, sbase + TILE_BYTES, f, acc);
  __syncthreads();  // A + W fully consumed

  stage_acc_smem(smem, lane, wid, acc);  // Y2 fp32 at base 0
  __syncthreads();

#pragma unroll 2
  for (int i = 0; i < 16; ++i) {
    int r = wid * 16 + i;
    float4 y = *(float4*)(smem + r * 512 + lane * 16);
    float s = wsum(y.x + y.y + y.z + y.w);
    float q = wsum(y.x * y.x + y.y * y.y + y.z * y.z + y.w * y.w);
    float mu = s * (1.0f / 128.0f);
    float rs = rsqrtf(q * (1.0f / 128.0f) - mu * mu + 1e-5f);
    int colb = ((lane * 16) ^ ((r & 7) << 4)) >> 2;
    float4 g2 = *(const float4*)(G2v + colb);
    float4 b2 = *(const float4*)(B2v + colb);
    size_t goff = (size_t)(rowBase + r) * C + colb;
    float4 id = *(const float4*)(Id + goff);
    float4 o;
    o.x = fmaxf((y.x - mu) * rs * g2.x + b2.x + id.x, 0.0f);
    o.y = fmaxf((y.y - mu) * rs * g2.y + b2.y + id.y, 0.0f);
    o.z = fmaxf((y.z - mu) * rs * g2.z + b2.z + id.z, 0.0f);
    o.w = fmaxf((y.w - mu) * rs * g2.w + b2.w + id.w, 0.0f);
    *(float4*)(OutF + goff) = o;
    if (Aout) {
      __half2 h0 = __floats2half2_rn(o.x, o.y);
      __half2 h1 = __floats2half2_rn(o.z, o.w);
      *(uint2*)(Aout + goff) = make_uint2(*(uint32_t*)&h0, *(uint32_t*)&h1);
    }
    if (TPz) *(float4*)(TPz + goff) = make_float4(0.f, 0.f, 0.f, 0.f);
  }
}

// ---------------------------------------------------------------------------
// fused per-block kernel:
//  it=0: ctr GEMM, own-row red.add into zeroed TP
//  it=1..12: pre/suc edge-GEMMs, sorted-edge smem scatter
//  it=13,14: left/right GATHER mode — only NCHUNK CTAs active; gather A[v]
//            rows for chunk, GEMM, scatter row r -> u[r].
// ---------------------------------------------------------------------------
constexpr int YPITCH_H = 136;
constexpr int W_OFF   = TILE_BYTES;       // 32768
constexpr int Y_OFF   = 2 * TILE_BYTES;   // 65536
constexpr int IDX_OFF = Y_OFF + 128 * YPITCH_H * 2;      // 100352
constexpr int CMP_OFF = IDX_OFF + 2 * IDX_CAP * 4;       // 104448
constexpr int SMEM_FUSED = CMP_OFF + 4 * 128 * 4;        // 106496

__global__ void __launch_bounds__(256, 2) fused_block_kernel(
    const __half* __restrict__ A, int ib, float* __restrict__ TP,
    const int* __restrict__ left_u, const int* __restrict__ left_v,
    const int* __restrict__ right_u, const int* __restrict__ right_v) {
  extern __shared__ __align__(16) char smem[];
  const uint32_t sbase = smem_u32(smem);
  __half* Ybuf = (__half*)(smem + Y_OFF);
  const int tid = threadIdx.x, lane = tid & 31, wid = tid >> 5;
  const int rowBase = blockIdx.x * 128;
  const bool activeCmp = blockIdx.x < NCHUNK;
  const int itMax = activeCmp ? 15 : 13;

  const int rw = (wid & 1) * 64, cw = (wid >> 1) * 32;
  const int r0 = lane >> 2, c0 = (lane & 3) * 2;

  auto slot_of = [&](int it) {
    return (it == 0)   ? 2 + ib
           : (it < 7)  ? 6 + ib * 6 + (it - 1)
           : (it < 13) ? 30 + ib * 6 + (it - 7)
           : (it == 13) ? 54 + ib : 58 + ib;
  };
  auto ebase_of = [&](int it) { return (it - 1) * E; };
  auto stage_idx = [&](int it) {
    int l = it - 1;
    int o0 = g_off[l * (NT + 1) + blockIdx.x];
    int o1 = g_off[l * (NT + 1) + blockIdx.x + 1];
    int cnt = min(o1 - o0, IDX_CAP);
    const int* src = g_epk + ebase_of(it) + o0;
    uint32_t dst = sbase + IDX_OFF + (it & 1) * (IDX_CAP * 4);
    for (int j = tid; j < cnt; j += 256) cp_async4(dst + j * 4, src + j);
  };
  auto stage_gather = [&](int voff) {
    const int* vs = (const int*)(smem + CMP_OFF + voff);
#pragma unroll
    for (int t2 = 0; t2 < 8; ++t2) {
      int idx = tid + t2 * 256;
      int row = idx >> 4, c16 = idx & 15;
      int vrow = vs[row];
      uint32_t off = row * 256 + ((c16 * 16) ^ ((row & 7) << 4));
      cp_async16(sbase + off, A + (size_t)vrow * C + c16 * 8);
    }
  };

  stage_async(sbase, A + (size_t)rowBase * C, tid);
  stage_async(sbase + W_OFF, g_Wh + (size_t)slot_of(0) * CC, tid);
  stage_idx(1);
  if (activeCmp) {
    int cb = blockIdx.x * 128;
    for (int j = tid; j < 128; j += 256) {
      cp_async4(sbase + CMP_OFF + j * 4, left_u + cb + j);
      cp_async4(sbase + CMP_OFF + 512 + j * 4, left_v + cb + j);
      cp_async4(sbase + CMP_OFF + 1024 + j * 4, right_u + cb + j);
      cp_async4(sbase + CMP_OFF + 1536 + j * 4, right_v + cb + j);
    }
  }
  CP_COMMIT();
  CP_WAIT(0);
  __syncthreads();

  FragIdx f = frag_idx(lane, wid);

#pragma unroll 1
  for (int it = 0; it < itMax; ++it) {
    float acc[4][4][4];
    zero_acc(acc);
    mma_pass(sbase, sbase + W_OFF, f, acc);

#pragma unroll
    for (int mi = 0; mi < 4; ++mi)
#pragma unroll
      for (int ni = 0; ni < 4; ++ni) {
        int row = rw + mi * 16 + r0, col = cw + ni * 8 + c0;
        __half2 h0 = __floats2half2_rn(acc[mi][ni][0], acc[mi][ni][1]);
        __half2 h1 = __floats2half2_rn(acc[mi][ni][2], acc[mi][ni][3]);
        *(__half2*)(Ybuf + row * YPITCH_H + col) = h0;
        *(__half2*)(Ybuf + (row + 8) * YPITCH_H + col) = h1;
      }
    __syncthreads();  // Ybuf ready; W(it) + A region fully consumed

    if (it + 1 < itMax) {
      stage_async(sbase + W_OFF, g_Wh + (size_t)slot_of(it + 1) * CC, tid);
      if (it + 1 <= 12) stage_idx(it + 1);
      else stage_gather(it + 1 == 13 ? 512 : 1536);
      CP_COMMIT();
    }

    if (it == 0) {
      for (int r = wid; r < 128; r += 8) {
        uint2 hv = *(uint2*)(Ybuf + r * YPITCH_H + lane * 4);
        float2 f0 = __half22float2(*(__half2*)&hv.x);
        float2 f1 = __half22float2(*(__half2*)&hv.y);
        float* p = TP + (size_t)(rowBase + r) * C + lane * 4;
        asm volatile("red.global.add.v4.f32 [%0], {%1,%2,%3,%4};"
                     :: "l"(p), "f"(f0.x), "f"(f0.y), "f"(f1.x), "f"(f1.y)
                     : "memory");
      }
    } else if (it <= 12) {
      int l = it - 1;
      int o0 = g_off[l * (NT + 1) + blockIdx.x];
      int o1 = g_off[l * (NT + 1) + blockIdx.x + 1];
      int cnt = o1 - o0;
      const int* sidx = (const int*)(smem + IDX_OFF + (it & 1) * (IDX_CAP * 4));
      const int* gidx = g_epk + ebase_of(it) + o0;
#pragma unroll 2
      for (int j = wid; j < cnt; j += 8) {
        int pk = (j < IDX_CAP) ? sidx[j] : __ldg(&gidx[j]);
        int vl = pk & 127;
        int uu = pk >> 7;
        uint2 hv = *(uint2*)(Ybuf + vl * YPITCH_H + lane * 4);
        float2 f0 = __half22float2(*(__half2*)&hv.x);
        float2 f1 = __half22float2(*(__half2*)&hv.y);
        float* p = TP + (size_t)uu * C + lane * 4;
        asm volatile("red.global.add.v4.f32 [%0], {%1,%2,%3,%4};"
                     :: "l"(p), "f"(f0.x), "f"(f0.y), "f"(f1.x), "f"(f1.y)
                     : "memory");
      }
    } else {
      const int* uarr = (const int*)(smem + CMP_OFF + (it == 13 ? 0 : 1024));
      for (int r = wid; r < 128; r += 8) {
        int uu = uarr[r];
        uint2 hv = *(uint2*)(Ybuf + r * YPITCH_H + lane * 4);
        float2 f0 = __half22float2(*(__half2*)&hv.x);
        float2 f1 = __half22float2(*(__half2*)&hv.y);
        float* p = TP + (size_t)uu * C + lane * 4;
        asm volatile("red.global.add.v4.f32 [%0], {%1,%2,%3,%4};"
                     :: "l"(p), "f"(f0.x), "f"(f0.y), "f"(f1.x), "f"(f1.y)
                     : "memory");
      }
    }

    if (it + 1 < itMax) CP_WAIT(0);
    __syncthreads();
  }
}

// ---------------------------------------------------------------------------
// edge sort (counting sort by v>>7) for the 12 pre/suc lists
// ---------------------------------------------------------------------------
__global__ void zero_cnt_kernel() {
  int i = blockIdx.x * 256 + threadIdx.x;
  if (i < NLS * NT) g_cnt[i] = 0;
}
__global__ void hist_all_kernel(const int* __restrict__ pre_v,
                                const int* __restrict__ suc_v) {
  int e = blockIdx.x * 256 + threadIdx.x;
  if (e >= 12 * E) return;
  int l = e / E;
  const int* vp = (l < 6) ? pre_v : suc_v;
  int off = (l < 6) ? e : e - 6 * E;
  atomicAdd(&g_cnt[l * NT + (__ldg(&vp[off]) >> 7)], 1);
}
__global__ void prefix_kernel() {  // one block per list, 1024 threads
  __shared__ int sh[NT];
  int l = blockIdx.x, t = threadIdx.x;
  sh[t] = g_cnt[l * NT + t];
  __syncthreads();
#pragma unroll
  for (int d = 1; d < NT; d <<= 1) {
    int x = (t >= d) ? sh[t - d] : 0;
    __syncthreads();
    sh[t] += x;
    __syncthreads();
  }
  g_off[l * (NT + 1) + t + 1] = sh[t];
  if (t == 0) g_off[l * (NT + 1)] = 0;
}
__global__ void fill_all_kernel(const int* __restrict__ pre_u,
                                const int* __restrict__ pre_v,
                                const int* __restrict__ suc_u,
                                const int* __restrict__ suc_v) {
  int e = blockIdx.x * 256 + threadIdx.x;
  if (e >= 12 * E) return;
  int l = e / E;
  const int* vp = (l < 6) ? pre_v : suc_v;
  const int* up = (l < 6) ? pre_u : suc_u;
  int off = (l < 6) ? e : e - 6 * E;
  int vv = __ldg(&vp[off]);
  int t = vv >> 7;
  int pos = l * E + g_off[l * (NT + 1) + t] + atomicAdd(&g_cnt[l * NT + t], 1);
  g_epk[pos] = (__ldg(&up[off]) << 7) | (vv & 127);
}

// ---------------------------------------------------------------------------
// setup: weight split + transpose, all 66 slots in one kernel
// ---------------------------------------------------------------------------
__global__ void wsplit_all_kernel(const float* __restrict__ ic_w1,
                                  const float* __restrict__ if_w1,
                                  const float* __restrict__ ctr_w,
                                  const float* __restrict__ pre_w,
                                  const float* __restrict__ suc_w,
                                  const float* __restrict__ left_w,
                                  const float* __restrict__ right_w,
                                  const float* __restrict__ ctr2_w) {
  int idx = blockIdx.x * 256 + threadIdx.x;  // NSLOT * 16384
  int slot = idx >> 14, r = idx & 16383;
  int c = r >> 7, k = r & 127;
  const float* src; int m;
  if (slot < 1)       { src = ic_w1;  m = 0; }
  else if (slot < 2)  { src = if_w1;  m = 0; }
  else if (slot < 6)  { src = ctr_w;  m = slot - 2; }
  else if (slot < 30) { src = pre_w;  m = slot - 6; }
  else if (slot < 54) { src = suc_w;  m = slot - 30; }
  else if (slot < 58) { src = left_w; m = slot - 54; }
  else if (slot < 62) { src = right_w; m = slot - 58; }
  else                { src = ctr2_w; m = slot - 62; }
  float w = src[(size_t)m * CC + k * 128 + c];
  g_Wh[(size_t)slot * CC + r] = __float2half_rn(w);
}

// ---------------------------------------------------------------------------
extern "C" void kernel_launch(void* const* d_in, const int* in_sizes, int n_in,
                              void* d_out, int out_size) {
  const float* ctrs   = (const float*)d_in[0];
  const float* feats  = (const float*)d_in[1];
  const int*   pre_u  = (const int*)d_in[2];
  const int*   pre_v  = (const int*)d_in[3];
  const int*   suc_u  = (const int*)d_in[4];
  const int*   suc_v  = (const int*)d_in[5];
  const int*   left_u = (const int*)d_in[6];
  const int*   left_v = (const int*)d_in[7];
  const int*   right_u= (const int*)d_in[8];
  const int*   right_v= (const int*)d_in[9];
  const float* ic_w0  = (const float*)d_in[10];
  const float* ic_b0  = (const float*)d_in[11];
  const float* ic_w1  = (const float*)d_in[12];
  const float* ic_g   = (const float*)d_in[13];
  const float* ic_bt  = (const float*)d_in[14];
  const float* if_w0  = (const float*)d_in[15];
  const float* if_b0  = (const float*)d_in[16];
  const float* if_w1  = (const float*)d_in[17];
  const float* if_g   = (const float*)d_in[18];
  const float* if_bt  = (const float*)d_in[19];
  const float* ctr_w  = (const float*)d_in[20];
  const float* pre_w  = (const float*)d_in[21];
  const float* suc_w  = (const float*)d_in[22];
  const float* left_w = (const float*)d_in[23];
  const float* right_w= (const float*)d_in[24];
  const float* norm_g = (const float*)d_in[25];
  const float* norm_b = (const float*)d_in[26];
  const float* ctr2_w = (const float*)d_in[27];
  const float* ctr2_g = (const float*)d_in[28];
  const float* ctr2_b = (const float*)d_in[29];
  float* out = (float*)d_out;

  float *FT, *TP, *YB;
  __half *AA, *WH;
  cudaGetSymbolAddress((void**)&FT, g_feat);
  cudaGetSymbolAddress((void**)&TP, g_temp);
  cudaGetSymbolAddress((void**)&YB, g_Y);
  cudaGetSymbolAddress((void**)&AA, g_A);
  cudaGetSymbolAddress((void**)&WH, g_Wh);

  cudaFuncSetAttribute(mlp_gemm_kernel,
                       cudaFuncAttributeMaxDynamicSharedMemorySize,
                       SMEM_IN_BYTES);
  cudaFuncSetAttribute(mlp_gemm_combine_kernel,
                       cudaFuncAttributeMaxDynamicSharedMemorySize,
                       SMEM_IN_BYTES);
  cudaFuncSetAttribute(gn_gemm_gn_kernel,
                       cudaFuncAttributeMaxDynamicSharedMemorySize,
                       SMEM_IN_BYTES);
  cudaFuncSetAttribute(fused_block_kernel,
                       cudaFuncAttributeMaxDynamicSharedMemorySize, SMEM_FUSED);

  const int GEMM_GRID = N / 128;
  const int ZG = (NLS * NT + 255) / 256;
  const int EG = (12 * E + 255) / 256;

  // ---- setup: weight split (1 launch) + edge sort (4 launches) ----
  wsplit_all_kernel<<<NSLOT * 64, 256>>>(ic_w1, if_w1, ctr_w, pre_w, suc_w,
                                         left_w, right_w, ctr2_w);
  zero_cnt_kernel<<<ZG, 256>>>();
  hist_all_kernel<<<EG, 256>>>(pre_v, suc_v);
  prefix_kernel<<<NLS, NT>>>();
  zero_cnt_kernel<<<ZG, 256>>>();
  fill_all_kernel<<<EG, 256>>>(pre_u, pre_v, suc_u, suc_v);

  // ---- Input stage: 2 fused kernels ----
  mlp_gemm_kernel<<<GEMM_GRID, 256, SMEM_IN_BYTES>>>(ctrs, ic_w0, ic_b0, WH,
                                                     YB);
  mlp_gemm_combine_kernel<<<GEMM_GRID, 256, SMEM_IN_BYTES>>>(
      feats, if_w0, if_b0, WH + (size_t)1 * CC, YB, ic_g, ic_bt, if_g, if_bt,
      FT, AA, TP);

  // ---- 4 fusion blocks: 2 kernels each ----
  for (int i = 0; i < NB; ++i) {
    fused_block_kernel<<<GEMM_GRID, 256, SMEM_FUSED>>>(AA, i, TP, left_u,
                                                       left_v, right_u,
                                                       right_v);

    if (i == NB - 1) {
      gn_gemm_gn_kernel<<<GEMM_GRID, 256, SMEM_IN_BYTES>>>(
          TP, norm_g + (size_t)i * C, norm_b + (size_t)i * C,
          WH + (size_t)(62 + i) * CC, ctr2_g + (size_t)i * C,
          ctr2_b + (size_t)i * C, FT, out, nullptr, nullptr);
    } else {
      gn_gemm_gn_kernel<<<GEMM_GRID, 256, SMEM_IN_BYTES>>>(
          TP, norm_g + (size_t)i * C, norm_b + (size_t)i * C,
          WH + (size_t)(62 + i) * CC, ctr2_g + (size_t)i * C,
          ctr2_b + (size_t)i * C, FT, FT, AA, TP);
    }
  }
}